// round 1
// baseline (speedup 1.0000x reference)
#include <cuda_runtime.h>
#include <math.h>
#include <stdint.h>

// ---------------------------------------------------------------------------
// Problem constants (shapes are fixed by the reference)
// ---------------------------------------------------------------------------
#define BSZ   8
#define HDIM  128
#define WDIM  128
#define CCH   192      // C
#define LTOK  16384    // H*W
#define C8    24       // C/8
#define MTOT  (BSZ * LTOK)   // 131072

static __device__ __forceinline__ float gelu_erf(float x) {
    return 0.5f * x * (1.0f + erff(x * 0.70710678118654752f));
}
static __device__ __forceinline__ float sigmoidf_(float x) {
    return 1.0f / (1.0f + expf(-x));
}

// ---------------------------------------------------------------------------
// Device scratch (allocation-free rule: use __device__ globals)
// ---------------------------------------------------------------------------
__device__ float g_qkv [MTOT * 3 * CCH];   // (B,L,3C)    302 MB
__device__ float g_fu  [MTOT * CCH];       // (B,L,C)     100 MB
__device__ float g_conv1[MTOT * CCH];      // (B,C,H,W)   100 MB
__device__ float g_fuimg[MTOT * CCH];      // (B,C,H,W)   100 MB
__device__ float g_conv2[MTOT * CCH];      // (B,C,H,W)   100 MB
__device__ float g_sgate[MTOT];            // 1+sigmoid(spatial)  per (b,l)
__device__ float g_pool [BSZ * CCH];       // channel means
__device__ float g_cgate[BSZ * CCH];       // 1+sigmoid(channel)  per (b,c)

// ---------------------------------------------------------------------------
// SGEMM: C[M,N] = A[M,K] @ B[K,N] + bias[N]
// BM=64, BN=64, BK=16, 256 threads, 4x4 register tile per thread.
// MODE 0: A = param (row-major (M,K)), writes g_qkv.
// MODE 1: A = g_conv2 viewed as NCHW with channel gate g_cgate
//         (A[m,k] = g_conv2[b*K*L + k*L + l] * g_cgate[b*K+k]), writes Cout.
// M = 131072 (mult of 64), K mult of 16, N mult of 64. No bounds checks.
// ---------------------------------------------------------------------------
template<int MODE, int N, int K>
__global__ __launch_bounds__(256) void sgemm_kernel(
    const float* __restrict__ A,
    const float* __restrict__ Bw,
    const float* __restrict__ bias,
    float* __restrict__ Cout)
{
    __shared__ float As[16][64];
    __shared__ float Bs[16][64];

    const int tid = threadIdx.x;
    const int n0 = blockIdx.x * 64;
    const int m0 = blockIdx.y * 64;

    float* outp = (MODE == 0) ? g_qkv : Cout;

    // decompositions used by MODE 1 loader (tile never crosses a batch: 64|L)
    const int bb    = m0 / LTOK;
    const int lbase = m0 % LTOK;

    float acc[4][4];
#pragma unroll
    for (int i = 0; i < 4; i++)
#pragma unroll
        for (int j = 0; j < 4; j++) acc[i][j] = 0.0f;

    const int mt = (tid >> 4) * 4;   // 0..60
    const int nt = (tid & 15) * 4;   // 0..60

    for (int kt = 0; kt < K; kt += 16) {
        // ---- load A tile ----
        if (MODE == 0) {
            const int row = tid >> 2;          // 0..63
            const int kq  = (tid & 3) * 4;     // 0,4,8,12
            const float4 av = *(const float4*)(A + (size_t)(m0 + row) * K + kt + kq);
            As[kq + 0][row] = av.x;
            As[kq + 1][row] = av.y;
            As[kq + 2][row] = av.z;
            As[kq + 3][row] = av.w;
        } else {
            const int m  = tid & 63;
            const int k4 = (tid >> 6) * 4;     // 0,4,8,12
#pragma unroll
            for (int j = 0; j < 4; j++) {
                const int k = kt + k4 + j;
                float v = g_conv2[(size_t)bb * K * LTOK + (size_t)k * LTOK + lbase + m];
                As[k4 + j][m] = v * g_cgate[bb * K + k];
            }
        }
        // ---- load B tile ----
        {
            const int kb = tid >> 4;           // 0..15
            const int nq = (tid & 15) * 4;
            const float4 bv = *(const float4*)(Bw + (size_t)(kt + kb) * N + n0 + nq);
            *(float4*)&Bs[kb][nq] = bv;
        }
        __syncthreads();

#pragma unroll
        for (int kk = 0; kk < 16; kk++) {
            const float4 a = *(const float4*)&As[kk][mt];
            const float4 b = *(const float4*)&Bs[kk][nt];
            const float ar[4] = {a.x, a.y, a.z, a.w};
            const float br[4] = {b.x, b.y, b.z, b.w};
#pragma unroll
            for (int i = 0; i < 4; i++)
#pragma unroll
                for (int j = 0; j < 4; j++) acc[i][j] = fmaf(ar[i], br[j], acc[i][j]);
        }
        __syncthreads();
    }

    const float4 bv = *(const float4*)(bias + n0 + nt);
    const float br[4] = {bv.x, bv.y, bv.z, bv.w};
#pragma unroll
    for (int i = 0; i < 4; i++) {
        float4 o;
        o.x = acc[i][0] + br[0];
        o.y = acc[i][1] + br[1];
        o.z = acc[i][2] + br[2];
        o.w = acc[i][3] + br[3];
        *(float4*)(outp + (size_t)(m0 + mt + i) * N + n0 + nt) = o;
    }
}

// ---------------------------------------------------------------------------
// Windowed attention, flash-style. One block = (window, head). T=128, hd=32.
// q,k,v are slices of g_qkv (B,L,3C): q cols [0,C), k [C,2C), v [2C,3C).
// Scores scaled by 3/sqrt(32) (attn1+attn2+attn3 identity), output *3.
// Writes g_fu (B,L,C) channels [COFF + head*32 .. +32).
// ---------------------------------------------------------------------------
template<int HS, int WS, int COFF>
__global__ __launch_bounds__(128) void attn_kernel()
{
    constexpr int WH = HDIM / HS;
    constexpr int WWn = WDIM / WS;
    constexpr float SCALE3 = 3.0f * 0.17677669529663688f;   // 3/sqrt(32)

    int bid = blockIdx.x;
    const int head = bid % 3; bid /= 3;
    const int ww = bid % WWn; bid /= WWn;
    const int wh = bid % WH;  bid /= WH;
    const int b  = bid;

    const int t  = threadIdx.x;
    const int hs = t / WS, ws = t % WS;
    const int l  = (wh * HS + hs) * WDIM + ww * WS + ws;
    const int co = COFF + head * 32;

    const float* qrow = g_qkv + ((size_t)b * LTOK + l) * (3 * CCH) + co;
    float q[32];
#pragma unroll
    for (int d4 = 0; d4 < 32; d4 += 4) {
        const float4 v = *(const float4*)(qrow + d4);
        q[d4] = v.x; q[d4+1] = v.y; q[d4+2] = v.z; q[d4+3] = v.w;
    }

    __shared__ float ksm[32][32];
    __shared__ float vsm[32][32];

    float m = -INFINITY, ssum = 0.0f;
    float acc[32];
#pragma unroll
    for (int d = 0; d < 32; d++) acc[d] = 0.0f;

    for (int chunk = 0; chunk < 4; chunk++) {
        __syncthreads();
        {
            const int s  = t >> 2;
            const int d0 = (t & 3) * 8;
            const int ts = chunk * 32 + s;
            const int hs2 = ts / WS, ws2 = ts % WS;
            const int l2  = (wh * HS + hs2) * WDIM + ww * WS + ws2;
            const float* kb = g_qkv + ((size_t)b * LTOK + l2) * (3 * CCH) + CCH + co;
            const float* vb = kb + CCH;
            *(float4*)&ksm[s][d0]     = *(const float4*)(kb + d0);
            *(float4*)&ksm[s][d0 + 4] = *(const float4*)(kb + d0 + 4);
            *(float4*)&vsm[s][d0]     = *(const float4*)(vb + d0);
            *(float4*)&vsm[s][d0 + 4] = *(const float4*)(vb + d0 + 4);
        }
        __syncthreads();

        float p[32];
        float cmax = -INFINITY;
#pragma unroll
        for (int s = 0; s < 32; s++) {
            float dot = 0.0f;
#pragma unroll
            for (int d = 0; d < 32; d++) dot = fmaf(q[d], ksm[s][d], dot);
            p[s] = dot * SCALE3;
            cmax = fmaxf(cmax, p[s]);
        }
        const float nm = fmaxf(m, cmax);
        const float corr = __expf(m - nm);
        ssum *= corr;
#pragma unroll
        for (int d = 0; d < 32; d++) acc[d] *= corr;
#pragma unroll
        for (int s = 0; s < 32; s++) {
            const float w = __expf(p[s] - nm);
            ssum += w;
#pragma unroll
            for (int d = 0; d < 32; d++) acc[d] = fmaf(w, vsm[s][d], acc[d]);
        }
        m = nm;
    }

    const float sc = 3.0f / ssum;
    float* orow = g_fu + ((size_t)b * LTOK + l) * CCH + co;
#pragma unroll
    for (int d4 = 0; d4 < 32; d4 += 4) {
        float4 o;
        o.x = acc[d4]   * sc;
        o.y = acc[d4+1] * sc;
        o.z = acc[d4+2] * sc;
        o.w = acc[d4+3] * sc;
        *(float4*)(orow + d4) = o;
    }
}

// ---------------------------------------------------------------------------
// Depthwise 3x3 conv (SAME, zero pad) + bias + eval BN + exact GELU.
// WHICH 0: input = param (x viewed NCHW via raw reshape), output g_conv1.
// WHICH 1: input = g_fuimg, output g_conv2.
// ---------------------------------------------------------------------------
template<int WHICH>
__global__ __launch_bounds__(256) void dwconv_bn_gelu_kernel(
    const float* __restrict__ xin,
    const float* __restrict__ wdw,   // (C,1,3,3)
    const float* __restrict__ bdw,
    const float* __restrict__ gbn,
    const float* __restrict__ bebn)
{
    const int idx = blockIdx.x * blockDim.x + threadIdx.x;  // B*C*H*W
    const int w = idx & (WDIM - 1);
    const int h = (idx >> 7) & (HDIM - 1);
    const int c = (idx >> 14) % CCH;
    const int b = idx / (CCH * LTOK);

    const float* in  = (WHICH == 0) ? xin : g_fuimg;
    float*       out = (WHICH == 0) ? g_conv1 : g_conv2;

    const float* p = in + ((size_t)b * CCH + c) * LTOK;
    const float* wk = wdw + c * 9;

    float s = 0.0f;
#pragma unroll
    for (int ky = -1; ky <= 1; ky++) {
        const int hh = h + ky;
        if (hh < 0 || hh >= HDIM) continue;
#pragma unroll
        for (int kx = -1; kx <= 1; kx++) {
            const int wwp = w + kx;
            if (wwp < 0 || wwp >= WDIM) continue;
            s = fmaf(p[hh * WDIM + wwp], wk[(ky + 1) * 3 + (kx + 1)], s);
        }
    }
    s += bdw[c];
    const float bni = rsqrtf(1.0f + 1e-5f);
    s = s * (gbn[c] * bni) + bebn[c];
    out[idx] = gelu_erf(s);
}

// ---------------------------------------------------------------------------
// Mean over H*W per (b,c): g_conv1 -> g_pool
// ---------------------------------------------------------------------------
__global__ __launch_bounds__(256) void mean_kernel()
{
    const int bc = blockIdx.x;
    const float* p = g_conv1 + (size_t)bc * LTOK;
    float s = 0.0f;
    for (int i = threadIdx.x; i < LTOK; i += 256) s += p[i];
#pragma unroll
    for (int o = 16; o > 0; o >>= 1) s += __shfl_xor_sync(0xffffffffu, s, o);
    __shared__ float red[8];
    if ((threadIdx.x & 31) == 0) red[threadIdx.x >> 5] = s;
    __syncthreads();
    if (threadIdx.x == 0) {
        float tot = 0.0f;
#pragma unroll
        for (int i = 0; i < 8; i++) tot += red[i];
        g_pool[bc] = tot * (1.0f / LTOK);
    }
}

// ---------------------------------------------------------------------------
// Spatial interaction: per pixel (b,hw):
//   t[o]  = gelu(bn_si( sum_c w_si1[o,c]*conv1[b,c,hw] + b_si1[o] ))
//   s     = sum_o w_si2[o]*t[o] + b_si2
//   g_sgate = 1 + sigmoid(s)
// One thread per pixel, 128 threads/block, w_si1 staged in smem as [c][o].
// ---------------------------------------------------------------------------
__global__ __launch_bounds__(128) void spatial_kernel(
    const float* __restrict__ w_si1, const float* __restrict__ b_si1,
    const float* __restrict__ g_si,  const float* __restrict__ be_si,
    const float* __restrict__ w_si2, const float* __restrict__ b_si2)
{
    __shared__ float wsm[CCH * C8];   // [c][o]
    for (int i = threadIdx.x; i < CCH * C8; i += 128)
        wsm[i] = w_si1[(i % C8) * CCH + (i / C8)];
    __syncthreads();

    const int pid = blockIdx.x * 128 + threadIdx.x;   // b*L + hw
    const int b  = pid / LTOK;
    const int hw = pid % LTOK;

    float t[C8];
#pragma unroll
    for (int o = 0; o < C8; o++) t[o] = 0.0f;

    const float* base = g_conv1 + (size_t)b * CCH * LTOK + hw;
    for (int c = 0; c < CCH; c++) {
        const float v = base[(size_t)c * LTOK];
        const float* wr = &wsm[c * C8];
#pragma unroll
        for (int o = 0; o < C8; o++) t[o] = fmaf(wr[o], v, t[o]);
    }

    const float bni = rsqrtf(1.0f + 1e-5f);
    float s = b_si2[0];
#pragma unroll
    for (int o = 0; o < C8; o++) {
        float u = (t[o] + b_si1[o]) * (g_si[o] * bni) + be_si[o];
        s = fmaf(w_si2[o], gelu_erf(u), s);
    }
    g_sgate[pid] = 1.0f + sigmoidf_(s);
}

// ---------------------------------------------------------------------------
// Channel interaction: per batch, from g_pool -> g_cgate
// ---------------------------------------------------------------------------
__global__ __launch_bounds__(192) void channel_kernel(
    const float* __restrict__ w_ci1, const float* __restrict__ b_ci1,
    const float* __restrict__ g_ci,  const float* __restrict__ be_ci,
    const float* __restrict__ w_ci2, const float* __restrict__ b_ci2)
{
    const int b = blockIdx.x;
    __shared__ float t[C8];
    const float bni = rsqrtf(1.0f + 1e-5f);
    if (threadIdx.x < C8) {
        const int o = threadIdx.x;
        float s = b_ci1[o];
        for (int c = 0; c < CCH; c++)
            s = fmaf(w_ci1[o * CCH + c], g_pool[b * CCH + c], s);
        s = s * (g_ci[o] * bni) + be_ci[o];
        t[o] = gelu_erf(s);
    }
    __syncthreads();
    const int c = threadIdx.x;
    float s = b_ci2[c];
#pragma unroll
    for (int o = 0; o < C8; o++) s = fmaf(w_ci2[c * C8 + o], t[o], s);
    g_cgate[b * CCH + c] = 1.0f + sigmoidf_(s);
}

// ---------------------------------------------------------------------------
// Gate-1 + transpose: g_fuimg[b,c,l] = g_fu[b,l,c] * g_sgate[b,l]
// 32x32 smem tile transpose, block (32,8).
// ---------------------------------------------------------------------------
__global__ __launch_bounds__(256) void gate1_transpose_kernel()
{
    __shared__ float tile[32][33];
    const int l0 = blockIdx.x * 32;
    const int c0 = blockIdx.y * 32;
    const int b  = blockIdx.z;

#pragma unroll
    for (int i = 0; i < 4; i++) {
        const int ly = threadIdx.y + i * 8;
        const int l = l0 + ly;
        tile[ly][threadIdx.x] =
            g_fu[((size_t)b * LTOK + l) * CCH + c0 + threadIdx.x] * g_sgate[b * LTOK + l];
    }
    __syncthreads();
#pragma unroll
    for (int i = 0; i < 4; i++) {
        const int cy = threadIdx.y + i * 8;
        g_fuimg[((size_t)b * CCH + c0 + cy) * LTOK + l0 + threadIdx.x] =
            tile[threadIdx.x][cy];
    }
}

// ---------------------------------------------------------------------------
// kernel_launch: pure kernel launches on stream 0 (graph-capturable).
// ---------------------------------------------------------------------------
extern "C" void kernel_launch(void* const* d_in, const int* in_sizes, int n_in,
                              void* d_out, int out_size)
{
    const float* x      = (const float*)d_in[0];
    const float* w_qkv  = (const float*)d_in[1];
    const float* b_qkv  = (const float*)d_in[2];
    const float* w_dw1  = (const float*)d_in[3];
    const float* b_dw1  = (const float*)d_in[4];
    const float* gbn1   = (const float*)d_in[5];
    const float* bebn1  = (const float*)d_in[6];
    const float* w_si1  = (const float*)d_in[7];
    const float* b_si1  = (const float*)d_in[8];
    const float* g_si   = (const float*)d_in[9];
    const float* be_si  = (const float*)d_in[10];
    const float* w_si2  = (const float*)d_in[11];
    const float* b_si2  = (const float*)d_in[12];
    const float* w_ci1  = (const float*)d_in[13];
    const float* b_ci1  = (const float*)d_in[14];
    const float* g_ci   = (const float*)d_in[15];
    const float* be_ci  = (const float*)d_in[16];
    const float* w_ci2  = (const float*)d_in[17];
    const float* b_ci2  = (const float*)d_in[18];
    const float* w_dw2  = (const float*)d_in[19];
    const float* b_dw2  = (const float*)d_in[20];
    const float* gbn2   = (const float*)d_in[21];
    const float* bebn2  = (const float*)d_in[22];
    const float* w_proj = (const float*)d_in[23];
    const float* b_proj = (const float*)d_in[24];
    float* out = (float*)d_out;

    // 1) qkv = x @ w_qkv + b_qkv         -> g_qkv
    sgemm_kernel<0, 3 * CCH, CCH><<<dim3((3 * CCH) / 64, MTOT / 64), 256>>>(
        x, w_qkv, b_qkv, nullptr);

    // 2) windowed attention (both branches) -> g_fu
    attn_kernel<8, 16, 0 ><<<BSZ * (HDIM / 8) * (WDIM / 16) * 3, 128>>>();
    attn_kernel<16, 8, 96><<<BSZ * (HDIM / 16) * (WDIM / 8) * 3, 128>>>();

    // 3) conv_x1 = gelu(bn(dwconv(x)))   -> g_conv1
    dwconv_bn_gelu_kernel<0><<<(MTOT * CCH) / 256, 256>>>(x, w_dw1, b_dw1, gbn1, bebn1);

    // 4) channel pool + spatial/channel interaction maps
    mean_kernel<<<BSZ * CCH, 256>>>();
    spatial_kernel<<<MTOT / 128, 128>>>(w_si1, b_si1, g_si, be_si, w_si2, b_si2);
    channel_kernel<<<BSZ, CCH>>>(w_ci1, b_ci1, g_ci, be_ci, w_ci2, b_ci2);

    // 5) fu*(1+sig(spatial)), transpose to NCHW -> g_fuimg
    gate1_transpose_kernel<<<dim3(LTOK / 32, CCH / 32, BSZ), dim3(32, 8)>>>();

    // 6) conv2 = gelu(bn(dwconv(fu_img))) -> g_conv2
    dwconv_bn_gelu_kernel<1><<<(MTOT * CCH) / 256, 256>>>(nullptr, w_dw2, b_dw2, gbn2, bebn2);

    // 7) out = (gate2-transposed conv2) @ w_proj + b_proj   (gate+transpose fused in A load)
    sgemm_kernel<1, CCH, CCH><<<dim3(CCH / 64, MTOT / 64), 256>>>(
        nullptr, w_proj, b_proj, out);
}

// round 4
// speedup vs baseline: 1.5245x; 1.5245x over previous
#include <cuda_runtime.h>
#include <math.h>
#include <stdint.h>

// ---------------------------------------------------------------------------
// Problem constants
// ---------------------------------------------------------------------------
#define BSZ   8
#define HDIM  128
#define WDIM  128
#define CCH   192
#define LTOK  16384
#define C8    24
#define MTOT  (BSZ * LTOK)   // 131072

static __device__ __forceinline__ float gelu_erf(float x) {
    return 0.5f * x * (1.0f + erff(x * 0.70710678118654752f));
}
static __device__ __forceinline__ float sigmoidf_(float x) {
    return 1.0f / (1.0f + expf(-x));
}
static __device__ __forceinline__ uint32_t f2tf32(float x) {
    uint32_t r;
    asm("cvt.rna.tf32.f32 %0, %1;" : "=r"(r) : "f"(x));
    return r;
}

// m16n8k8 tf32 tensor-core MMA (Ampere-compatible path, no tcgen05)
static __device__ __forceinline__ void mma_tf32(
    float* c, const uint32_t* a, const uint32_t* b)
{
    asm volatile(
        "mma.sync.aligned.m16n8k8.row.col.f32.tf32.tf32.f32 "
        "{%0,%1,%2,%3}, {%4,%5,%6,%7}, {%8,%9}, {%0,%1,%2,%3};\n"
        : "+f"(c[0]), "+f"(c[1]), "+f"(c[2]), "+f"(c[3])
        : "r"(a[0]), "r"(a[1]), "r"(a[2]), "r"(a[3]),
          "r"(b[0]), "r"(b[1]));
}

// ---------------------------------------------------------------------------
// Device scratch
// ---------------------------------------------------------------------------
__device__ float g_qkv [MTOT * 3 * CCH];   // (B,L,3C)
__device__ float g_fu  [MTOT * CCH];       // (B,L,C)
__device__ float g_conv1[MTOT * CCH];      // (B,C,H,W)
__device__ float g_fuimg[MTOT * CCH];      // (B,C,H,W)
__device__ float g_conv2[MTOT * CCH];      // (B,C,H,W)
__device__ float g_xT  [CCH * MTOT];       // xT[k][m]  (k-major A for qkv GEMM)
__device__ float g_sgate[MTOT];
__device__ float g_pool [BSZ * CCH];
__device__ float g_cgate[BSZ * CCH];

// ---------------------------------------------------------------------------
// Tensor-core GEMM via mma.sync tf32.
// C[M,NFULL] = A[M,192] @ B[192,NFULL] + bias.
// Block tile 128(M) x 96(N), BK=16, 6 warps (2 M x 3 N), warp tile 64x32.
// A is consumed K-MAJOR:
//   MODE 0: Ak = g_xT          (xT[k][m]),             out = g_qkv
//   MODE 1: Ak = g_conv2[b,k,l] * g_cgate[b,k],        out = Cout
// B = weight in native [K][NFULL] row-major layout.
// ---------------------------------------------------------------------------
#define APAD 136   // 136 mod 32 == 8  -> conflict-free frag loads
#define BPAD 104   // 104 mod 32 == 8

template<int MODE, int NFULL>
__global__ __launch_bounds__(192) void mma_gemm_kernel(
    const float* __restrict__ Bw,
    const float* __restrict__ bias,
    float* __restrict__ Cout)
{
    __shared__ uint32_t As[16][APAD];   // [k][m]  128 cols used
    __shared__ uint32_t Bs[16][BPAD];   // [k][n]   96 cols used

    const int tid  = threadIdx.x;
    const int wid  = tid >> 5;
    const int lane = tid & 31;
    const int gid  = lane >> 2;    // 0..7
    const int tig  = lane & 3;     // 0..3
    const int warp_m = wid & 1;    // 0..1
    const int warp_n = wid >> 1;   // 0..2

    const int n0 = blockIdx.x * 96;
    const int m0 = blockIdx.y * 128;
    const int bb = m0 / LTOK;      // MODE 1
    const int lb = m0 % LTOK;

    float* __restrict__ outp = (MODE == 0) ? g_qkv : Cout;

    float acc[4][4][4];
#pragma unroll
    for (int mt = 0; mt < 4; mt++)
#pragma unroll
        for (int nt = 0; nt < 4; nt++)
#pragma unroll
            for (int v = 0; v < 4; v++) acc[mt][nt][v] = 0.0f;

    for (int kt = 0; kt < CCH; kt += 16) {
        __syncthreads();
        // ---- A tile: 16 k-rows x 128 m (512 float4) ----
#pragma unroll
        for (int it = 0; it < 3; it++) {
            const int lin = tid + it * 192;
            if (lin < 512) {
                const int k  = lin >> 5;
                const int mq = (lin & 31) << 2;
                float4 v;
                if (MODE == 0) {
                    v = *(const float4*)(g_xT + (size_t)(kt + k) * MTOT + m0 + mq);
                } else {
                    v = *(const float4*)(g_conv2 + (size_t)bb * CCH * LTOK
                                         + (size_t)(kt + k) * LTOK + lb + mq);
                    const float g = g_cgate[bb * CCH + kt + k];
                    v.x *= g; v.y *= g; v.z *= g; v.w *= g;
                }
                uint4 t;
                t.x = f2tf32(v.x); t.y = f2tf32(v.y);
                t.z = f2tf32(v.z); t.w = f2tf32(v.w);
                *(uint4*)&As[k][mq] = t;
            }
        }
        // ---- B tile: 16 k-rows x 96 n (384 float4) ----
#pragma unroll
        for (int it = 0; it < 2; it++) {
            const int lin = tid + it * 192;
            const int k   = lin / 24;
            const int nq  = (lin % 24) << 2;
            float4 v = *(const float4*)(Bw + (size_t)(kt + k) * NFULL + n0 + nq);
            uint4 t;
            t.x = f2tf32(v.x); t.y = f2tf32(v.y);
            t.z = f2tf32(v.z); t.w = f2tf32(v.w);
            *(uint4*)&Bs[k][nq] = t;
        }
        __syncthreads();

        // ---- compute: 2 k8 steps ----
#pragma unroll
        for (int ks = 0; ks < 2; ks++) {
            const int kr = ks * 8;
            uint32_t af[4][4];
#pragma unroll
            for (int mt = 0; mt < 4; mt++) {
                const int mr = warp_m * 64 + mt * 16;
                af[mt][0] = As[kr + tig    ][mr + gid];
                af[mt][1] = As[kr + tig    ][mr + gid + 8];
                af[mt][2] = As[kr + tig + 4][mr + gid];
                af[mt][3] = As[kr + tig + 4][mr + gid + 8];
            }
            uint32_t bf[4][2];
#pragma unroll
            for (int nt = 0; nt < 4; nt++) {
                const int nb = warp_n * 32 + nt * 8;
                bf[nt][0] = Bs[kr + tig    ][nb + gid];
                bf[nt][1] = Bs[kr + tig + 4][nb + gid];
            }
#pragma unroll
            for (int mt = 0; mt < 4; mt++)
#pragma unroll
                for (int nt = 0; nt < 4; nt++)
                    mma_tf32(acc[mt][nt], af[mt], bf[nt]);
        }
    }

    // ---- epilogue: direct gmem stores (32B-sector friendly) ----
#pragma unroll
    for (int mt = 0; mt < 4; mt++) {
        const int r0 = m0 + warp_m * 64 + mt * 16 + gid;
#pragma unroll
        for (int nt = 0; nt < 4; nt++) {
            const int col = n0 + warp_n * 32 + nt * 8 + tig * 2;
            const float bx = bias[col], by = bias[col + 1];
            float2 v0 = { acc[mt][nt][0] + bx, acc[mt][nt][1] + by };
            float2 v1 = { acc[mt][nt][2] + bx, acc[mt][nt][3] + by };
            *(float2*)(outp + (size_t)r0 * NFULL + col) = v0;
            *(float2*)(outp + (size_t)(r0 + 8) * NFULL + col) = v1;
        }
    }
}

// ---------------------------------------------------------------------------
// x (M x 192 row-major) -> g_xT (192 x M), 32x32 smem tile transpose
// ---------------------------------------------------------------------------
__global__ __launch_bounds__(256) void xpose_kernel(const float* __restrict__ x)
{
    __shared__ float tile[32][33];
    const int m0 = blockIdx.x * 32;
    const int c0 = blockIdx.y * 32;
#pragma unroll
    for (int i = 0; i < 4; i++) {
        const int my = threadIdx.y + i * 8;
        tile[my][threadIdx.x] = x[(size_t)(m0 + my) * CCH + c0 + threadIdx.x];
    }
    __syncthreads();
#pragma unroll
    for (int i = 0; i < 4; i++) {
        const int cy = threadIdx.y + i * 8;
        g_xT[(size_t)(c0 + cy) * MTOT + m0 + threadIdx.x] = tile[threadIdx.x][cy];
    }
}

// ---------------------------------------------------------------------------
// Windowed attention, flash-style (proven in R1)
// ---------------------------------------------------------------------------
template<int HS, int WS, int COFF>
__global__ __launch_bounds__(128) void attn_kernel()
{
    constexpr int WWn = WDIM / WS;
    constexpr int WH = HDIM / HS;
    constexpr float SCALE3 = 3.0f * 0.17677669529663688f;   // 3/sqrt(32)

    int bid = blockIdx.x;
    const int head = bid % 3; bid /= 3;
    const int ww = bid % WWn; bid /= WWn;
    const int wh = bid % WH;  bid /= WH;
    const int b  = bid;

    const int t  = threadIdx.x;
    const int hs = t / WS, ws = t % WS;
    const int l  = (wh * HS + hs) * WDIM + ww * WS + ws;
    const int co = COFF + head * 32;

    const float* qrow = g_qkv + ((size_t)b * LTOK + l) * (3 * CCH) + co;
    float q[32];
#pragma unroll
    for (int d4 = 0; d4 < 32; d4 += 4) {
        const float4 v = *(const float4*)(qrow + d4);
        q[d4] = v.x; q[d4+1] = v.y; q[d4+2] = v.z; q[d4+3] = v.w;
    }

    __shared__ float ksm[32][32];
    __shared__ float vsm[32][32];

    float m = -INFINITY, ssum = 0.0f;
    float acc[32];
#pragma unroll
    for (int d = 0; d < 32; d++) acc[d] = 0.0f;

    for (int chunk = 0; chunk < 4; chunk++) {
        __syncthreads();
        {
            const int s  = t >> 2;
            const int d0 = (t & 3) * 8;
            const int ts = chunk * 32 + s;
            const int hs2 = ts / WS, ws2 = ts % WS;
            const int l2  = (wh * HS + hs2) * WDIM + ww * WS + ws2;
            const float* kb = g_qkv + ((size_t)b * LTOK + l2) * (3 * CCH) + CCH + co;
            const float* vb = kb + CCH;
            *(float4*)&ksm[s][d0]     = *(const float4*)(kb + d0);
            *(float4*)&ksm[s][d0 + 4] = *(const float4*)(kb + d0 + 4);
            *(float4*)&vsm[s][d0]     = *(const float4*)(vb + d0);
            *(float4*)&vsm[s][d0 + 4] = *(const float4*)(vb + d0 + 4);
        }
        __syncthreads();

        float p[32];
        float cmax = -INFINITY;
#pragma unroll
        for (int s = 0; s < 32; s++) {
            float dot = 0.0f;
#pragma unroll
            for (int d = 0; d < 32; d++) dot = fmaf(q[d], ksm[s][d], dot);
            p[s] = dot * SCALE3;
            cmax = fmaxf(cmax, p[s]);
        }
        const float nm = fmaxf(m, cmax);
        const float corr = __expf(m - nm);
        ssum *= corr;
#pragma unroll
        for (int d = 0; d < 32; d++) acc[d] *= corr;
#pragma unroll
        for (int s = 0; s < 32; s++) {
            const float w = __expf(p[s] - nm);
            ssum += w;
#pragma unroll
            for (int d = 0; d < 32; d++) acc[d] = fmaf(w, vsm[s][d], acc[d]);
        }
        m = nm;
    }

    const float sc = 3.0f / ssum;
    float* orow = g_fu + ((size_t)b * LTOK + l) * CCH + co;
#pragma unroll
    for (int d4 = 0; d4 < 32; d4 += 4) {
        float4 o;
        o.x = acc[d4]   * sc;
        o.y = acc[d4+1] * sc;
        o.z = acc[d4+2] * sc;
        o.w = acc[d4+3] * sc;
        *(float4*)(orow + d4) = o;
    }
}

// ---------------------------------------------------------------------------
// Depthwise 3x3 + bias + BN + GELU, 4 pixels per thread (float4 in/out).
// ---------------------------------------------------------------------------
template<int WHICH>
__global__ __launch_bounds__(256) void dwconv_bn_gelu_kernel(
    const float* __restrict__ xin,
    const float* __restrict__ wdw,
    const float* __restrict__ bdw,
    const float* __restrict__ gbn,
    const float* __restrict__ bebn)
{
    const int idx = blockIdx.x * 256 + threadIdx.x;   // over MTOT*CCH/4
    const int w0 = (idx & 31) * 4;
    const int h  = (idx >> 5) & 127;
    const int bc = idx >> 12;                          // b*C + c
    const int c  = bc % CCH;

    const float* in  = (WHICH == 0) ? xin : g_fuimg;
    float*       out = (WHICH == 0) ? g_conv1 : g_conv2;

    const float* p = in + (size_t)bc * LTOK;
    float wk[9];
#pragma unroll
    for (int i = 0; i < 9; i++) wk[i] = wdw[c * 9 + i];

    float o0 = 0.f, o1 = 0.f, o2 = 0.f, o3 = 0.f;
#pragma unroll
    for (int r = 0; r < 3; r++) {
        const int hh = h - 1 + r;
        if (hh < 0 || hh >= HDIM) continue;
        const float* row = p + hh * WDIM;
        const float4 cc = *(const float4*)(row + w0);
        const float lf = (w0 > 0)   ? row[w0 - 1] : 0.0f;
        const float rt = (w0 < 124) ? row[w0 + 4] : 0.0f;
        const float k0 = wk[r*3+0], k1 = wk[r*3+1], k2 = wk[r*3+2];
        o0 = fmaf(k0, lf,   fmaf(k1, cc.x, fmaf(k2, cc.y, o0)));
        o1 = fmaf(k0, cc.x, fmaf(k1, cc.y, fmaf(k2, cc.z, o1)));
        o2 = fmaf(k0, cc.y, fmaf(k1, cc.z, fmaf(k2, cc.w, o2)));
        o3 = fmaf(k0, cc.z, fmaf(k1, cc.w, fmaf(k2, rt,   o3)));
    }
    const float bni = rsqrtf(1.0f + 1e-5f);
    const float sc = gbn[c] * bni, bb = bebn[c], bs = bdw[c];
    float4 o;
    o.x = gelu_erf((o0 + bs) * sc + bb);
    o.y = gelu_erf((o1 + bs) * sc + bb);
    o.z = gelu_erf((o2 + bs) * sc + bb);
    o.w = gelu_erf((o3 + bs) * sc + bb);
    *(float4*)(out + (size_t)idx * 4) = o;
}

// ---------------------------------------------------------------------------
// Mean over H*W per (b,c)
// ---------------------------------------------------------------------------
__global__ __launch_bounds__(256) void mean_kernel()
{
    const int bc = blockIdx.x;
    const float* p = g_conv1 + (size_t)bc * LTOK;
    float s = 0.0f;
    for (int i = threadIdx.x; i < LTOK; i += 256) s += p[i];
#pragma unroll
    for (int o = 16; o > 0; o >>= 1) s += __shfl_xor_sync(0xffffffffu, s, o);
    __shared__ float red[8];
    if ((threadIdx.x & 31) == 0) red[threadIdx.x >> 5] = s;
    __syncthreads();
    if (threadIdx.x == 0) {
        float tot = 0.0f;
#pragma unroll
        for (int i = 0; i < 8; i++) tot += red[i];
        g_pool[bc] = tot * (1.0f / LTOK);
    }
}

// ---------------------------------------------------------------------------
// Spatial interaction map -> g_sgate
// ---------------------------------------------------------------------------
__global__ __launch_bounds__(128) void spatial_kernel(
    const float* __restrict__ w_si1, const float* __restrict__ b_si1,
    const float* __restrict__ g_si,  const float* __restrict__ be_si,
    const float* __restrict__ w_si2, const float* __restrict__ b_si2)
{
    __shared__ float wsm[CCH * C8];   // [c][o]
    for (int i = threadIdx.x; i < CCH * C8; i += 128)
        wsm[i] = w_si1[(i % C8) * CCH + (i / C8)];
    __syncthreads();

    const int pid = blockIdx.x * 128 + threadIdx.x;
    const int b  = pid / LTOK;
    const int hw = pid % LTOK;

    float t[C8];
#pragma unroll
    for (int o = 0; o < C8; o++) t[o] = 0.0f;

    const float* base = g_conv1 + (size_t)b * CCH * LTOK + hw;
    for (int c = 0; c < CCH; c++) {
        const float v = base[(size_t)c * LTOK];
        const float* wr = &wsm[c * C8];
#pragma unroll
        for (int o = 0; o < C8; o++) t[o] = fmaf(wr[o], v, t[o]);
    }

    const float bni = rsqrtf(1.0f + 1e-5f);
    float s = b_si2[0];
#pragma unroll
    for (int o = 0; o < C8; o++) {
        float u = (t[o] + b_si1[o]) * (g_si[o] * bni) + be_si[o];
        s = fmaf(w_si2[o], gelu_erf(u), s);
    }
    g_sgate[pid] = 1.0f + sigmoidf_(s);
}

// ---------------------------------------------------------------------------
// Channel interaction -> g_cgate
// ---------------------------------------------------------------------------
__global__ __launch_bounds__(192) void channel_kernel(
    const float* __restrict__ w_ci1, const float* __restrict__ b_ci1,
    const float* __restrict__ g_ci,  const float* __restrict__ be_ci,
    const float* __restrict__ w_ci2, const float* __restrict__ b_ci2)
{
    const int b = blockIdx.x;
    __shared__ float t[C8];
    const float bni = rsqrtf(1.0f + 1e-5f);
    if (threadIdx.x < C8) {
        const int o = threadIdx.x;
        float s = b_ci1[o];
        for (int c = 0; c < CCH; c++)
            s = fmaf(w_ci1[o * CCH + c], g_pool[b * CCH + c], s);
        s = s * (g_ci[o] * bni) + be_ci[o];
        t[o] = gelu_erf(s);
    }
    __syncthreads();
    const int c = threadIdx.x;
    float s = b_ci2[c];
#pragma unroll
    for (int o = 0; o < C8; o++) s = fmaf(w_ci2[c * C8 + o], t[o], s);
    g_cgate[b * CCH + c] = 1.0f + sigmoidf_(s);
}

// ---------------------------------------------------------------------------
// Gate-1 + transpose: g_fuimg[b,c,l] = g_fu[b,l,c] * g_sgate[b,l]
// ---------------------------------------------------------------------------
__global__ __launch_bounds__(256) void gate1_transpose_kernel()
{
    __shared__ float tile[32][33];
    const int l0 = blockIdx.x * 32;
    const int c0 = blockIdx.y * 32;
    const int b  = blockIdx.z;

#pragma unroll
    for (int i = 0; i < 4; i++) {
        const int ly = threadIdx.y + i * 8;
        const int l = l0 + ly;
        tile[ly][threadIdx.x] =
            g_fu[((size_t)b * LTOK + l) * CCH + c0 + threadIdx.x] * g_sgate[b * LTOK + l];
    }
    __syncthreads();
#pragma unroll
    for (int i = 0; i < 4; i++) {
        const int cy = threadIdx.y + i * 8;
        g_fuimg[((size_t)b * CCH + c0 + cy) * LTOK + l0 + threadIdx.x] =
            tile[threadIdx.x][cy];
    }
}

// ---------------------------------------------------------------------------
// kernel_launch
// ---------------------------------------------------------------------------
extern "C" void kernel_launch(void* const* d_in, const int* in_sizes, int n_in,
                              void* d_out, int out_size)
{
    const float* x      = (const float*)d_in[0];
    const float* w_qkv  = (const float*)d_in[1];
    const float* b_qkv  = (const float*)d_in[2];
    const float* w_dw1  = (const float*)d_in[3];
    const float* b_dw1  = (const float*)d_in[4];
    const float* gbn1   = (const float*)d_in[5];
    const float* bebn1  = (const float*)d_in[6];
    const float* w_si1  = (const float*)d_in[7];
    const float* b_si1  = (const float*)d_in[8];
    const float* g_si   = (const float*)d_in[9];
    const float* be_si  = (const float*)d_in[10];
    const float* w_si2  = (const float*)d_in[11];
    const float* b_si2  = (const float*)d_in[12];
    const float* w_ci1  = (const float*)d_in[13];
    const float* b_ci1  = (const float*)d_in[14];
    const float* g_ci   = (const float*)d_in[15];
    const float* be_ci  = (const float*)d_in[16];
    const float* w_ci2  = (const float*)d_in[17];
    const float* b_ci2  = (const float*)d_in[18];
    const float* w_dw2  = (const float*)d_in[19];
    const float* b_dw2  = (const float*)d_in[20];
    const float* gbn2   = (const float*)d_in[21];
    const float* bebn2  = (const float*)d_in[22];
    const float* w_proj = (const float*)d_in[23];
    const float* b_proj = (const float*)d_in[24];
    float* out = (float*)d_out;

    // 0) x -> xT (k-major A for the qkv GEMM)
    xpose_kernel<<<dim3(MTOT / 32, CCH / 32), dim3(32, 8)>>>(x);

    // 1) qkv = x @ w_qkv + b_qkv  (mma.sync tf32) -> g_qkv
    mma_gemm_kernel<0, 3 * CCH><<<dim3((3 * CCH) / 96, MTOT / 128), 192>>>(
        w_qkv, b_qkv, nullptr);

    // 2) windowed attention -> g_fu
    attn_kernel<8, 16, 0 ><<<BSZ * (HDIM / 8) * (WDIM / 16) * 3, 128>>>();
    attn_kernel<16, 8, 96><<<BSZ * (HDIM / 16) * (WDIM / 8) * 3, 128>>>();

    // 3) conv_x1 -> g_conv1
    dwconv_bn_gelu_kernel<0><<<(MTOT * CCH) / 1024, 256>>>(x, w_dw1, b_dw1, gbn1, bebn1);

    // 4) pooling + interaction maps
    mean_kernel<<<BSZ * CCH, 256>>>();
    spatial_kernel<<<MTOT / 128, 128>>>(w_si1, b_si1, g_si, be_si, w_si2, b_si2);
    channel_kernel<<<BSZ, CCH>>>(w_ci1, b_ci1, g_ci, be_ci, w_ci2, b_ci2);

    // 5) gate-1 + transpose -> g_fuimg
    gate1_transpose_kernel<<<dim3(LTOK / 32, CCH / 32, BSZ), dim3(32, 8)>>>();

    // 6) conv2 -> g_conv2
    dwconv_bn_gelu_kernel<1><<<(MTOT * CCH) / 1024, 256>>>(nullptr, w_dw2, b_dw2, gbn2, bebn2);

    // 7) out = (channel-gated conv2) @ w_proj + b_proj  (mma.sync tf32)
    mma_gemm_kernel<1, CCH><<<dim3(CCH / 96, MTOT / 128), 192>>>(
        w_proj, b_proj, out);
}

// round 5
// speedup vs baseline: 1.6053x; 1.0530x over previous
#include <cuda_runtime.h>
#include <math.h>
#include <stdint.h>

// ---------------------------------------------------------------------------
// Problem constants
// ---------------------------------------------------------------------------
#define BSZ   8
#define HDIM  128
#define WDIM  128
#define CCH   192
#define LTOK  16384
#define C8    24
#define MTOT  (BSZ * LTOK)   // 131072

static __device__ __forceinline__ float gelu_erf(float x) {
    return 0.5f * x * (1.0f + erff(x * 0.70710678118654752f));
}
static __device__ __forceinline__ float sigmoidf_(float x) {
    return 1.0f / (1.0f + expf(-x));
}
static __device__ __forceinline__ uint32_t f2tf32(float x) {
    uint32_t r;
    asm("cvt.rna.tf32.f32 %0, %1;" : "=r"(r) : "f"(x));
    return r;
}

// m16n8k8 tf32 tensor-core MMA (proven layout from R4)
static __device__ __forceinline__ void mma_tf32(
    float* c, const uint32_t* a, const uint32_t* b)
{
    asm volatile(
        "mma.sync.aligned.m16n8k8.row.col.f32.tf32.tf32.f32 "
        "{%0,%1,%2,%3}, {%4,%5,%6,%7}, {%8,%9}, {%0,%1,%2,%3};\n"
        : "+f"(c[0]), "+f"(c[1]), "+f"(c[2]), "+f"(c[3])
        : "r"(a[0]), "r"(a[1]), "r"(a[2]), "r"(a[3]),
          "r"(b[0]), "r"(b[1]));
}

// ---------------------------------------------------------------------------
// Device scratch
// ---------------------------------------------------------------------------
__device__ float g_qkv [MTOT * 3 * CCH];   // (B,L,3C)
__device__ float g_fu  [MTOT * CCH];       // (B,L,C)
__device__ float g_conv1[MTOT * CCH];      // (B,C,H,W)
__device__ float g_fuimg[MTOT * CCH];      // (B,C,H,W)
__device__ float g_conv2[MTOT * CCH];      // (B,C,H,W)
__device__ float g_xT  [CCH * MTOT];       // xT[k][m]
__device__ float g_sgate[MTOT];
__device__ float g_pool [BSZ * CCH];
__device__ float g_cgate[BSZ * CCH];

// ---------------------------------------------------------------------------
// GEMM via mma.sync tf32 (unchanged from R4 — proven)
// ---------------------------------------------------------------------------
#define APAD 136
#define BPAD 104

template<int MODE, int NFULL>
__global__ __launch_bounds__(192) void mma_gemm_kernel(
    const float* __restrict__ Bw,
    const float* __restrict__ bias,
    float* __restrict__ Cout)
{
    __shared__ uint32_t As[16][APAD];
    __shared__ uint32_t Bs[16][BPAD];

    const int tid  = threadIdx.x;
    const int wid  = tid >> 5;
    const int lane = tid & 31;
    const int gid  = lane >> 2;
    const int tig  = lane & 3;
    const int warp_m = wid & 1;
    const int warp_n = wid >> 1;

    const int n0 = blockIdx.x * 96;
    const int m0 = blockIdx.y * 128;
    const int bb = m0 / LTOK;
    const int lb = m0 % LTOK;

    float* __restrict__ outp = (MODE == 0) ? g_qkv : Cout;

    float acc[4][4][4];
#pragma unroll
    for (int mt = 0; mt < 4; mt++)
#pragma unroll
        for (int nt = 0; nt < 4; nt++)
#pragma unroll
            for (int v = 0; v < 4; v++) acc[mt][nt][v] = 0.0f;

    for (int kt = 0; kt < CCH; kt += 16) {
        __syncthreads();
#pragma unroll
        for (int it = 0; it < 3; it++) {
            const int lin = tid + it * 192;
            if (lin < 512) {
                const int k  = lin >> 5;
                const int mq = (lin & 31) << 2;
                float4 v;
                if (MODE == 0) {
                    v = *(const float4*)(g_xT + (size_t)(kt + k) * MTOT + m0 + mq);
                } else {
                    v = *(const float4*)(g_conv2 + (size_t)bb * CCH * LTOK
                                         + (size_t)(kt + k) * LTOK + lb + mq);
                    const float g = g_cgate[bb * CCH + kt + k];
                    v.x *= g; v.y *= g; v.z *= g; v.w *= g;
                }
                uint4 t;
                t.x = f2tf32(v.x); t.y = f2tf32(v.y);
                t.z = f2tf32(v.z); t.w = f2tf32(v.w);
                *(uint4*)&As[k][mq] = t;
            }
        }
#pragma unroll
        for (int it = 0; it < 2; it++) {
            const int lin = tid + it * 192;
            const int k   = lin / 24;
            const int nq  = (lin % 24) << 2;
            float4 v = *(const float4*)(Bw + (size_t)(kt + k) * NFULL + n0 + nq);
            uint4 t;
            t.x = f2tf32(v.x); t.y = f2tf32(v.y);
            t.z = f2tf32(v.z); t.w = f2tf32(v.w);
            *(uint4*)&Bs[k][nq] = t;
        }
        __syncthreads();

#pragma unroll
        for (int ks = 0; ks < 2; ks++) {
            const int kr = ks * 8;
            uint32_t af[4][4];
#pragma unroll
            for (int mt = 0; mt < 4; mt++) {
                const int mr = warp_m * 64 + mt * 16;
                af[mt][0] = As[kr + tig    ][mr + gid];
                af[mt][1] = As[kr + tig    ][mr + gid + 8];
                af[mt][2] = As[kr + tig + 4][mr + gid];
                af[mt][3] = As[kr + tig + 4][mr + gid + 8];
            }
            uint32_t bf[4][2];
#pragma unroll
            for (int nt = 0; nt < 4; nt++) {
                const int nb = warp_n * 32 + nt * 8;
                bf[nt][0] = Bs[kr + tig    ][nb + gid];
                bf[nt][1] = Bs[kr + tig + 4][nb + gid];
            }
#pragma unroll
            for (int mt = 0; mt < 4; mt++)
#pragma unroll
                for (int nt = 0; nt < 4; nt++)
                    mma_tf32(acc[mt][nt], af[mt], bf[nt]);
        }
    }

#pragma unroll
    for (int mt = 0; mt < 4; mt++) {
        const int r0 = m0 + warp_m * 64 + mt * 16 + gid;
#pragma unroll
        for (int nt = 0; nt < 4; nt++) {
            const int col = n0 + warp_n * 32 + nt * 8 + tig * 2;
            const float bx = bias[col], by = bias[col + 1];
            float2 v0 = { acc[mt][nt][0] + bx, acc[mt][nt][1] + by };
            float2 v1 = { acc[mt][nt][2] + bx, acc[mt][nt][3] + by };
            *(float2*)(outp + (size_t)r0 * NFULL + col) = v0;
            *(float2*)(outp + (size_t)(r0 + 8) * NFULL + col) = v1;
        }
    }
}

// ---------------------------------------------------------------------------
// x -> g_xT transpose
// ---------------------------------------------------------------------------
__global__ __launch_bounds__(256) void xpose_kernel(const float* __restrict__ x)
{
    __shared__ float tile[32][33];
    const int m0 = blockIdx.x * 32;
    const int c0 = blockIdx.y * 32;
#pragma unroll
    for (int i = 0; i < 4; i++) {
        const int my = threadIdx.y + i * 8;
        tile[my][threadIdx.x] = x[(size_t)(m0 + my) * CCH + c0 + threadIdx.x];
    }
    __syncthreads();
#pragma unroll
    for (int i = 0; i < 4; i++) {
        const int cy = threadIdx.y + i * 8;
        g_xT[(size_t)(c0 + cy) * MTOT + m0 + threadIdx.x] = tile[threadIdx.x][cy];
    }
}

// ---------------------------------------------------------------------------
// Windowed attention via mma.sync tf32.
// Block = (window, head), 128 threads / 4 warps. T=128 tokens, hd=32.
//   Phase 1: S = Q K^T * (3/sqrt(32))  -> smem (fp32)
//   Phase 2: per-row softmax (warp-per-row, shfl reduce); write exp back as tf32
//   Phase 3: O^T = V^T P^T  (A = V natural [tok][dim], B = S natural [row][col])
//   Phase 4: scale 3/rowsum, stage in smem, coalesced store
// Smem layout (dynamic, 102912 B):
//   [0)      Ssm  f32/u32 [128][132]   67584
//   [67584)  rsum f32 [128]              512
//   [68096)  X region 34816:
//            phase0/1: Qs u32[32][136], Ks u32[32][136]
//            phase2/3: Vs u32[128][40]
//            phase4:   Os f32[128][33]
// ---------------------------------------------------------------------------
#define ATT_SMEM 102912

template<int HS, int WS, int COFF>
__global__ __launch_bounds__(128) void attn_mma_kernel()
{
    extern __shared__ char sm[];
    float*    Ssm  = (float*)sm;                    // [128][132]
    uint32_t* Su   = (uint32_t*)sm;
    float*    rsum = (float*)(sm + 67584);
    uint32_t* Qs   = (uint32_t*)(sm + 68096);       // [32][136]
    uint32_t* Ks   = Qs + 32 * 136;
    uint32_t* Vs   = (uint32_t*)(sm + 68096);       // [128][40]
    float*    Os   = (float*)(sm + 68096);          // [128][33]

    constexpr int WWn = WDIM / WS;
    constexpr int WH  = HDIM / HS;
    constexpr float SCALE3 = 3.0f * 0.17677669529663688f;   // 3/sqrt(32)

    int bid = blockIdx.x;
    const int head = bid % 3; bid /= 3;
    const int ww = bid % WWn; bid /= WWn;
    const int wh = bid % WH;  bid /= WH;
    const int b  = bid;
    const int co = COFF + head * 32;

    const int t    = threadIdx.x;
    const int wid  = t >> 5;
    const int lane = t & 31;
    const int gid  = lane >> 2;
    const int tig  = lane & 3;

    const int sL = t >> 2;          // token sub-index 0..31
    const int d0 = (t & 3) * 8;     // dim group

    // ---- Phase 0: Q,K -> smem [dim][token], tf32 ----
#pragma unroll
    for (int p = 0; p < 4; p++) {
        const int ts = p * 32 + sL;
        const int l  = (wh * HS + ts / WS) * WDIM + ww * WS + ts % WS;
        const float* qb = g_qkv + ((size_t)b * LTOK + l) * (3 * CCH) + co;
        const float* kb = qb + CCH;
        const float4 q0 = *(const float4*)(qb + d0);
        const float4 q1 = *(const float4*)(qb + d0 + 4);
        const float4 k0 = *(const float4*)(kb + d0);
        const float4 k1 = *(const float4*)(kb + d0 + 4);
        const float qa[8] = {q0.x,q0.y,q0.z,q0.w,q1.x,q1.y,q1.z,q1.w};
        const float ka[8] = {k0.x,k0.y,k0.z,k0.w,k1.x,k1.y,k1.z,k1.w};
#pragma unroll
        for (int j = 0; j < 8; j++) {
            Qs[(d0 + j) * 136 + ts] = f2tf32(qa[j]);
            Ks[(d0 + j) * 136 + ts] = f2tf32(ka[j]);
        }
    }
    __syncthreads();

    // ---- Phase 1: S = Q K^T, scaled ----
    {
        const int mrb = wid * 32;
#pragma unroll
        for (int nc = 0; nc < 4; nc++) {
            float acc[2][4][4] = {};
#pragma unroll
            for (int ks = 0; ks < 4; ks++) {
                const int kr = ks * 8;
                uint32_t af[2][4];
#pragma unroll
                for (int mt = 0; mt < 2; mt++) {
                    const int mr = mrb + mt * 16;
                    af[mt][0] = Qs[(kr + tig    ) * 136 + mr + gid];
                    af[mt][1] = Qs[(kr + tig    ) * 136 + mr + gid + 8];
                    af[mt][2] = Qs[(kr + tig + 4) * 136 + mr + gid];
                    af[mt][3] = Qs[(kr + tig + 4) * 136 + mr + gid + 8];
                }
                uint32_t bf[4][2];
#pragma unroll
                for (int nt = 0; nt < 4; nt++) {
                    const int nb = nc * 32 + nt * 8;
                    bf[nt][0] = Ks[(kr + tig    ) * 136 + nb + gid];
                    bf[nt][1] = Ks[(kr + tig + 4) * 136 + nb + gid];
                }
#pragma unroll
                for (int mt = 0; mt < 2; mt++)
#pragma unroll
                    for (int nt = 0; nt < 4; nt++)
                        mma_tf32(acc[mt][nt], af[mt], bf[nt]);
            }
#pragma unroll
            for (int mt = 0; mt < 2; mt++) {
                const int r0 = mrb + mt * 16 + gid;
#pragma unroll
                for (int nt = 0; nt < 4; nt++) {
                    const int col = nc * 32 + nt * 8 + tig * 2;
                    Ssm[r0 * 132 + col]           = acc[mt][nt][0] * SCALE3;
                    Ssm[r0 * 132 + col + 1]       = acc[mt][nt][1] * SCALE3;
                    Ssm[(r0 + 8) * 132 + col]     = acc[mt][nt][2] * SCALE3;
                    Ssm[(r0 + 8) * 132 + col + 1] = acc[mt][nt][3] * SCALE3;
                }
            }
        }
    }
    __syncthreads();   // S complete; Qs/Ks dead

    // ---- Phase 2a: load V into X region (overwrites Qs/Ks) ----
#pragma unroll
    for (int p = 0; p < 4; p++) {
        const int ts = p * 32 + sL;
        const int l  = (wh * HS + ts / WS) * WDIM + ww * WS + ts % WS;
        const float* vb = g_qkv + ((size_t)b * LTOK + l) * (3 * CCH) + 2 * CCH + co;
        const float4 v0 = *(const float4*)(vb + d0);
        const float4 v1 = *(const float4*)(vb + d0 + 4);
        uint4 t0, t1;
        t0.x = f2tf32(v0.x); t0.y = f2tf32(v0.y); t0.z = f2tf32(v0.z); t0.w = f2tf32(v0.w);
        t1.x = f2tf32(v1.x); t1.y = f2tf32(v1.y); t1.z = f2tf32(v1.z); t1.w = f2tf32(v1.w);
        *(uint4*)(Vs + ts * 40 + d0)     = t0;
        *(uint4*)(Vs + ts * 40 + d0 + 4) = t1;
    }

    // ---- Phase 2b: softmax per row; write exp back in place as tf32 ----
    for (int i = 0; i < 32; i++) {
        const int r = wid * 32 + i;
        float v[4];
#pragma unroll
        for (int j = 0; j < 4; j++) v[j] = Ssm[r * 132 + lane + 32 * j];
        float mx = fmaxf(fmaxf(v[0], v[1]), fmaxf(v[2], v[3]));
#pragma unroll
        for (int o = 16; o > 0; o >>= 1) mx = fmaxf(mx, __shfl_xor_sync(~0u, mx, o));
        float s = 0.0f;
#pragma unroll
        for (int j = 0; j < 4; j++) {
            const float e = __expf(v[j] - mx);
            s += e;
            Su[r * 132 + lane + 32 * j] = f2tf32(e);
        }
#pragma unroll
        for (int o = 16; o > 0; o >>= 1) s += __shfl_xor_sync(~0u, s, o);
        if (lane == 0) rsum[r] = 3.0f / s;
    }
    __syncthreads();

    // ---- Phase 3: O^T = V^T P^T  (M=32 dims, N=128 rows, K=128 tokens) ----
    {
        const int nbb = wid * 32;
        float acc[2][4][4] = {};
        for (int ks = 0; ks < 16; ks++) {
            const int kr = ks * 8;
            uint32_t af[2][4];
#pragma unroll
            for (int mt = 0; mt < 2; mt++) {
                const int mr = mt * 16;
                af[mt][0] = Vs[(kr + tig    ) * 40 + mr + gid];
                af[mt][1] = Vs[(kr + tig    ) * 40 + mr + gid + 8];
                af[mt][2] = Vs[(kr + tig + 4) * 40 + mr + gid];
                af[mt][3] = Vs[(kr + tig + 4) * 40 + mr + gid + 8];
            }
            uint32_t bf[4][2];
#pragma unroll
            for (int nt = 0; nt < 4; nt++) {
                const int nb = nbb + nt * 8;
                bf[nt][0] = Su[(nb + gid) * 132 + kr + tig];
                bf[nt][1] = Su[(nb + gid) * 132 + kr + tig + 4];
            }
#pragma unroll
            for (int mt = 0; mt < 2; mt++)
#pragma unroll
                for (int nt = 0; nt < 4; nt++)
                    mma_tf32(acc[mt][nt], af[mt], bf[nt]);
        }
        __syncthreads();   // Vs dead everywhere before Os overwrite

#pragma unroll
        for (int mt = 0; mt < 2; mt++) {
            const int dim0 = mt * 16 + gid;
#pragma unroll
            for (int nt = 0; nt < 4; nt++) {
                const int r = nbb + nt * 8 + tig * 2;
                const float s0 = rsum[r], s1 = rsum[r + 1];
                Os[r * 33 + dim0]           = acc[mt][nt][0] * s0;
                Os[(r + 1) * 33 + dim0]     = acc[mt][nt][1] * s1;
                Os[r * 33 + dim0 + 8]       = acc[mt][nt][2] * s0;
                Os[(r + 1) * 33 + dim0 + 8] = acc[mt][nt][3] * s1;
            }
        }
    }
    __syncthreads();

    // ---- Phase 4: coalesced writeout ----
#pragma unroll
    for (int p = 0; p < 4; p++) {
        const int ts = p * 32 + sL;
        const int l  = (wh * HS + ts / WS) * WDIM + ww * WS + ts % WS;
        float* orow = g_fu + ((size_t)b * LTOK + l) * CCH + co + d0;
        float4 o0, o1;
        o0.x = Os[ts * 33 + d0];     o0.y = Os[ts * 33 + d0 + 1];
        o0.z = Os[ts * 33 + d0 + 2]; o0.w = Os[ts * 33 + d0 + 3];
        o1.x = Os[ts * 33 + d0 + 4]; o1.y = Os[ts * 33 + d0 + 5];
        o1.z = Os[ts * 33 + d0 + 6]; o1.w = Os[ts * 33 + d0 + 7];
        *(float4*)orow       = o0;
        *(float4*)(orow + 4) = o1;
    }
}

// ---------------------------------------------------------------------------
// Depthwise 3x3 + bias + BN + GELU, 4 pixels per thread
// ---------------------------------------------------------------------------
template<int WHICH>
__global__ __launch_bounds__(256) void dwconv_bn_gelu_kernel(
    const float* __restrict__ xin,
    const float* __restrict__ wdw,
    const float* __restrict__ bdw,
    const float* __restrict__ gbn,
    const float* __restrict__ bebn)
{
    const int idx = blockIdx.x * 256 + threadIdx.x;
    const int w0 = (idx & 31) * 4;
    const int h  = (idx >> 5) & 127;
    const int bc = idx >> 12;
    const int c  = bc % CCH;

    const float* in  = (WHICH == 0) ? xin : g_fuimg;
    float*       out = (WHICH == 0) ? g_conv1 : g_conv2;

    const float* p = in + (size_t)bc * LTOK;
    float wk[9];
#pragma unroll
    for (int i = 0; i < 9; i++) wk[i] = wdw[c * 9 + i];

    float o0 = 0.f, o1 = 0.f, o2 = 0.f, o3 = 0.f;
#pragma unroll
    for (int r = 0; r < 3; r++) {
        const int hh = h - 1 + r;
        if (hh < 0 || hh >= HDIM) continue;
        const float* row = p + hh * WDIM;
        const float4 cc = *(const float4*)(row + w0);
        const float lf = (w0 > 0)   ? row[w0 - 1] : 0.0f;
        const float rt = (w0 < 124) ? row[w0 + 4] : 0.0f;
        const float k0 = wk[r*3+0], k1 = wk[r*3+1], k2 = wk[r*3+2];
        o0 = fmaf(k0, lf,   fmaf(k1, cc.x, fmaf(k2, cc.y, o0)));
        o1 = fmaf(k0, cc.x, fmaf(k1, cc.y, fmaf(k2, cc.z, o1)));
        o2 = fmaf(k0, cc.y, fmaf(k1, cc.z, fmaf(k2, cc.w, o2)));
        o3 = fmaf(k0, cc.z, fmaf(k1, cc.w, fmaf(k2, rt,   o3)));
    }
    const float bni = rsqrtf(1.0f + 1e-5f);
    const float sc = gbn[c] * bni, bb = bebn[c], bs = bdw[c];
    float4 o;
    o.x = gelu_erf((o0 + bs) * sc + bb);
    o.y = gelu_erf((o1 + bs) * sc + bb);
    o.z = gelu_erf((o2 + bs) * sc + bb);
    o.w = gelu_erf((o3 + bs) * sc + bb);
    *(float4*)(out + (size_t)idx * 4) = o;
}

// ---------------------------------------------------------------------------
// Mean over H*W per (b,c)
// ---------------------------------------------------------------------------
__global__ __launch_bounds__(256) void mean_kernel()
{
    const int bc = blockIdx.x;
    const float* p = g_conv1 + (size_t)bc * LTOK;
    float s = 0.0f;
    for (int i = threadIdx.x; i < LTOK; i += 256) s += p[i];
#pragma unroll
    for (int o = 16; o > 0; o >>= 1) s += __shfl_xor_sync(0xffffffffu, s, o);
    __shared__ float red[8];
    if ((threadIdx.x & 31) == 0) red[threadIdx.x >> 5] = s;
    __syncthreads();
    if (threadIdx.x == 0) {
        float tot = 0.0f;
#pragma unroll
        for (int i = 0; i < 8; i++) tot += red[i];
        g_pool[bc] = tot * (1.0f / LTOK);
    }
}

// ---------------------------------------------------------------------------
// Spatial interaction map -> g_sgate
// ---------------------------------------------------------------------------
__global__ __launch_bounds__(128) void spatial_kernel(
    const float* __restrict__ w_si1, const float* __restrict__ b_si1,
    const float* __restrict__ g_si,  const float* __restrict__ be_si,
    const float* __restrict__ w_si2, const float* __restrict__ b_si2)
{
    __shared__ float wsm[CCH * C8];   // [c][o]
    for (int i = threadIdx.x; i < CCH * C8; i += 128)
        wsm[i] = w_si1[(i % C8) * CCH + (i / C8)];
    __syncthreads();

    const int pid = blockIdx.x * 128 + threadIdx.x;
    const int b  = pid / LTOK;
    const int hw = pid % LTOK;

    float t[C8];
#pragma unroll
    for (int o = 0; o < C8; o++) t[o] = 0.0f;

    const float* base = g_conv1 + (size_t)b * CCH * LTOK + hw;
    for (int c = 0; c < CCH; c++) {
        const float v = base[(size_t)c * LTOK];
        const float* wr = &wsm[c * C8];
#pragma unroll
        for (int o = 0; o < C8; o++) t[o] = fmaf(wr[o], v, t[o]);
    }

    const float bni = rsqrtf(1.0f + 1e-5f);
    float s = b_si2[0];
#pragma unroll
    for (int o = 0; o < C8; o++) {
        float u = (t[o] + b_si1[o]) * (g_si[o] * bni) + be_si[o];
        s = fmaf(w_si2[o], gelu_erf(u), s);
    }
    g_sgate[pid] = 1.0f + sigmoidf_(s);
}

// ---------------------------------------------------------------------------
// Channel interaction -> g_cgate
// ---------------------------------------------------------------------------
__global__ __launch_bounds__(192) void channel_kernel(
    const float* __restrict__ w_ci1, const float* __restrict__ b_ci1,
    const float* __restrict__ g_ci,  const float* __restrict__ be_ci,
    const float* __restrict__ w_ci2, const float* __restrict__ b_ci2)
{
    const int b = blockIdx.x;
    __shared__ float t[C8];
    const float bni = rsqrtf(1.0f + 1e-5f);
    if (threadIdx.x < C8) {
        const int o = threadIdx.x;
        float s = b_ci1[o];
        for (int c = 0; c < CCH; c++)
            s = fmaf(w_ci1[o * CCH + c], g_pool[b * CCH + c], s);
        s = s * (g_ci[o] * bni) + be_ci[o];
        t[o] = gelu_erf(s);
    }
    __syncthreads();
    const int c = threadIdx.x;
    float s = b_ci2[c];
#pragma unroll
    for (int o = 0; o < C8; o++) s = fmaf(w_ci2[c * C8 + o], t[o], s);
    g_cgate[b * CCH + c] = 1.0f + sigmoidf_(s);
}

// ---------------------------------------------------------------------------
// Gate-1 + transpose: g_fuimg[b,c,l] = g_fu[b,l,c] * g_sgate[b,l]
// ---------------------------------------------------------------------------
__global__ __launch_bounds__(256) void gate1_transpose_kernel()
{
    __shared__ float tile[32][33];
    const int l0 = blockIdx.x * 32;
    const int c0 = blockIdx.y * 32;
    const int b  = blockIdx.z;

#pragma unroll
    for (int i = 0; i < 4; i++) {
        const int ly = threadIdx.y + i * 8;
        const int l = l0 + ly;
        tile[ly][threadIdx.x] =
            g_fu[((size_t)b * LTOK + l) * CCH + c0 + threadIdx.x] * g_sgate[b * LTOK + l];
    }
    __syncthreads();
#pragma unroll
    for (int i = 0; i < 4; i++) {
        const int cy = threadIdx.y + i * 8;
        g_fuimg[((size_t)b * CCH + c0 + cy) * LTOK + l0 + threadIdx.x] =
            tile[threadIdx.x][cy];
    }
}

// ---------------------------------------------------------------------------
// kernel_launch
// ---------------------------------------------------------------------------
extern "C" void kernel_launch(void* const* d_in, const int* in_sizes, int n_in,
                              void* d_out, int out_size)
{
    const float* x      = (const float*)d_in[0];
    const float* w_qkv  = (const float*)d_in[1];
    const float* b_qkv  = (const float*)d_in[2];
    const float* w_dw1  = (const float*)d_in[3];
    const float* b_dw1  = (const float*)d_in[4];
    const float* gbn1   = (const float*)d_in[5];
    const float* bebn1  = (const float*)d_in[6];
    const float* w_si1  = (const float*)d_in[7];
    const float* b_si1  = (const float*)d_in[8];
    const float* g_si   = (const float*)d_in[9];
    const float* be_si  = (const float*)d_in[10];
    const float* w_si2  = (const float*)d_in[11];
    const float* b_si2  = (const float*)d_in[12];
    const float* w_ci1  = (const float*)d_in[13];
    const float* b_ci1  = (const float*)d_in[14];
    const float* g_ci   = (const float*)d_in[15];
    const float* be_ci  = (const float*)d_in[16];
    const float* w_ci2  = (const float*)d_in[17];
    const float* b_ci2  = (const float*)d_in[18];
    const float* w_dw2  = (const float*)d_in[19];
    const float* b_dw2  = (const float*)d_in[20];
    const float* gbn2   = (const float*)d_in[21];
    const float* bebn2  = (const float*)d_in[22];
    const float* w_proj = (const float*)d_in[23];
    const float* b_proj = (const float*)d_in[24];
    float* out = (float*)d_out;

    cudaFuncSetAttribute(attn_mma_kernel<8, 16, 0>,
                         cudaFuncAttributeMaxDynamicSharedMemorySize, ATT_SMEM);
    cudaFuncSetAttribute(attn_mma_kernel<16, 8, 96>,
                         cudaFuncAttributeMaxDynamicSharedMemorySize, ATT_SMEM);

    // 0) x -> xT
    xpose_kernel<<<dim3(MTOT / 32, CCH / 32), dim3(32, 8)>>>(x);

    // 1) qkv = x @ w_qkv + b_qkv
    mma_gemm_kernel<0, 3 * CCH><<<dim3((3 * CCH) / 96, MTOT / 128), 192>>>(
        w_qkv, b_qkv, nullptr);

    // 2) windowed attention (tensor-core) -> g_fu
    attn_mma_kernel<8, 16, 0 ><<<BSZ * (HDIM / 8) * (WDIM / 16) * 3, 128, ATT_SMEM>>>();
    attn_mma_kernel<16, 8, 96><<<BSZ * (HDIM / 16) * (WDIM / 8) * 3, 128, ATT_SMEM>>>();

    // 3) conv_x1 -> g_conv1
    dwconv_bn_gelu_kernel<0><<<(MTOT * CCH) / 1024, 256>>>(x, w_dw1, b_dw1, gbn1, bebn1);

    // 4) pooling + interaction maps
    mean_kernel<<<BSZ * CCH, 256>>>();
    spatial_kernel<<<MTOT / 128, 128>>>(w_si1, b_si1, g_si, be_si, w_si2, b_si2);
    channel_kernel<<<BSZ, CCH>>>(w_ci1, b_ci1, g_ci, be_ci, w_ci2, b_ci2);

    // 5) gate-1 + transpose -> g_fuimg
    gate1_transpose_kernel<<<dim3(LTOK / 32, CCH / 32, BSZ), dim3(32, 8)>>>();

    // 6) conv2 -> g_conv2
    dwconv_bn_gelu_kernel<1><<<(MTOT * CCH) / 1024, 256>>>(nullptr, w_dw2, b_dw2, gbn2, bebn2);

    // 7) out = (channel-gated conv2) @ w_proj + b_proj
    mma_gemm_kernel<1, CCH><<<dim3(CCH / 96, MTOT / 128), 192>>>(
        w_proj, b_proj, out);
}

// round 6
// speedup vs baseline: 1.8288x; 1.1392x over previous
#include <cuda_runtime.h>
#include <math.h>
#include <stdint.h>

// ---------------------------------------------------------------------------
// Problem constants
// ---------------------------------------------------------------------------
#define BSZ   8
#define HDIM  128
#define WDIM  128
#define CCH   192
#define LTOK  16384
#define C8    24
#define MTOT  (BSZ * LTOK)   // 131072

static __device__ __forceinline__ float gelu_erf(float x) {
    return 0.5f * x * (1.0f + erff(x * 0.70710678118654752f));
}
static __device__ __forceinline__ float sigmoidf_(float x) {
    return 1.0f / (1.0f + expf(-x));
}
static __device__ __forceinline__ uint32_t f2tf32(float x) {
    uint32_t r;
    asm("cvt.rna.tf32.f32 %0, %1;" : "=r"(r) : "f"(x));
    return r;
}

// m16n8k8 tf32 tensor-core MMA (proven layout)
static __device__ __forceinline__ void mma_tf32(
    float* c, const uint32_t* a, const uint32_t* b)
{
    asm volatile(
        "mma.sync.aligned.m16n8k8.row.col.f32.tf32.tf32.f32 "
        "{%0,%1,%2,%3}, {%4,%5,%6,%7}, {%8,%9}, {%0,%1,%2,%3};\n"
        : "+f"(c[0]), "+f"(c[1]), "+f"(c[2]), "+f"(c[3])
        : "r"(a[0]), "r"(a[1]), "r"(a[2]), "r"(a[3]),
          "r"(b[0]), "r"(b[1]));
}

// ---------------------------------------------------------------------------
// Device scratch
// ---------------------------------------------------------------------------
__device__ float g_qkv [MTOT * 3 * CCH];   // (B,L,3C)
__device__ float g_fu  [MTOT * CCH];       // (B,L,C)
__device__ float g_conv1[MTOT * CCH];      // (B,C,H,W)
__device__ float g_fuimg[MTOT * CCH];      // (B,C,H,W)
__device__ float g_conv2[MTOT * CCH];      // (B,C,H,W)
__device__ float g_xT  [CCH * MTOT];       // xT[k][m]
__device__ float g_sgate[MTOT];
__device__ float g_pool [BSZ * CCH];
__device__ float g_cgate[BSZ * CCH];

// ---------------------------------------------------------------------------
// GEMM via mma.sync tf32 (unchanged — proven)
// ---------------------------------------------------------------------------
#define APAD 136
#define BPAD 104

template<int MODE, int NFULL>
__global__ __launch_bounds__(192) void mma_gemm_kernel(
    const float* __restrict__ Bw,
    const float* __restrict__ bias,
    float* __restrict__ Cout)
{
    __shared__ uint32_t As[16][APAD];
    __shared__ uint32_t Bs[16][BPAD];

    const int tid  = threadIdx.x;
    const int wid  = tid >> 5;
    const int lane = tid & 31;
    const int gid  = lane >> 2;
    const int tig  = lane & 3;
    const int warp_m = wid & 1;
    const int warp_n = wid >> 1;

    const int n0 = blockIdx.x * 96;
    const int m0 = blockIdx.y * 128;
    const int bb = m0 / LTOK;
    const int lb = m0 % LTOK;

    float* __restrict__ outp = (MODE == 0) ? g_qkv : Cout;

    float acc[4][4][4];
#pragma unroll
    for (int mt = 0; mt < 4; mt++)
#pragma unroll
        for (int nt = 0; nt < 4; nt++)
#pragma unroll
            for (int v = 0; v < 4; v++) acc[mt][nt][v] = 0.0f;

    for (int kt = 0; kt < CCH; kt += 16) {
        __syncthreads();
#pragma unroll
        for (int it = 0; it < 3; it++) {
            const int lin = tid + it * 192;
            if (lin < 512) {
                const int k  = lin >> 5;
                const int mq = (lin & 31) << 2;
                float4 v;
                if (MODE == 0) {
                    v = *(const float4*)(g_xT + (size_t)(kt + k) * MTOT + m0 + mq);
                } else {
                    v = *(const float4*)(g_conv2 + (size_t)bb * CCH * LTOK
                                         + (size_t)(kt + k) * LTOK + lb + mq);
                    const float g = g_cgate[bb * CCH + kt + k];
                    v.x *= g; v.y *= g; v.z *= g; v.w *= g;
                }
                uint4 t;
                t.x = f2tf32(v.x); t.y = f2tf32(v.y);
                t.z = f2tf32(v.z); t.w = f2tf32(v.w);
                *(uint4*)&As[k][mq] = t;
            }
        }
#pragma unroll
        for (int it = 0; it < 2; it++) {
            const int lin = tid + it * 192;
            const int k   = lin / 24;
            const int nq  = (lin % 24) << 2;
            float4 v = *(const float4*)(Bw + (size_t)(kt + k) * NFULL + n0 + nq);
            uint4 t;
            t.x = f2tf32(v.x); t.y = f2tf32(v.y);
            t.z = f2tf32(v.z); t.w = f2tf32(v.w);
            *(uint4*)&Bs[k][nq] = t;
        }
        __syncthreads();

#pragma unroll
        for (int ks = 0; ks < 2; ks++) {
            const int kr = ks * 8;
            uint32_t af[4][4];
#pragma unroll
            for (int mt = 0; mt < 4; mt++) {
                const int mr = warp_m * 64 + mt * 16;
                af[mt][0] = As[kr + tig    ][mr + gid];
                af[mt][1] = As[kr + tig    ][mr + gid + 8];
                af[mt][2] = As[kr + tig + 4][mr + gid];
                af[mt][3] = As[kr + tig + 4][mr + gid + 8];
            }
            uint32_t bf[4][2];
#pragma unroll
            for (int nt = 0; nt < 4; nt++) {
                const int nb = warp_n * 32 + nt * 8;
                bf[nt][0] = Bs[kr + tig    ][nb + gid];
                bf[nt][1] = Bs[kr + tig + 4][nb + gid];
            }
#pragma unroll
            for (int mt = 0; mt < 4; mt++)
#pragma unroll
                for (int nt = 0; nt < 4; nt++)
                    mma_tf32(acc[mt][nt], af[mt], bf[nt]);
        }
    }

#pragma unroll
    for (int mt = 0; mt < 4; mt++) {
        const int r0 = m0 + warp_m * 64 + mt * 16 + gid;
#pragma unroll
        for (int nt = 0; nt < 4; nt++) {
            const int col = n0 + warp_n * 32 + nt * 8 + tig * 2;
            const float bx = bias[col], by = bias[col + 1];
            float2 v0 = { acc[mt][nt][0] + bx, acc[mt][nt][1] + by };
            float2 v1 = { acc[mt][nt][2] + bx, acc[mt][nt][3] + by };
            *(float2*)(outp + (size_t)r0 * NFULL + col) = v0;
            *(float2*)(outp + (size_t)(r0 + 8) * NFULL + col) = v1;
        }
    }
}

// ---------------------------------------------------------------------------
// x -> g_xT transpose
// ---------------------------------------------------------------------------
__global__ __launch_bounds__(256) void xpose_kernel(const float* __restrict__ x)
{
    __shared__ float tile[32][33];
    const int m0 = blockIdx.x * 32;
    const int c0 = blockIdx.y * 32;
#pragma unroll
    for (int i = 0; i < 4; i++) {
        const int my = threadIdx.y + i * 8;
        tile[my][threadIdx.x] = x[(size_t)(m0 + my) * CCH + c0 + threadIdx.x];
    }
    __syncthreads();
#pragma unroll
    for (int i = 0; i < 4; i++) {
        const int cy = threadIdx.y + i * 8;
        g_xT[(size_t)(c0 + cy) * MTOT + m0 + threadIdx.x] = tile[threadIdx.x][cy];
    }
}

// ---------------------------------------------------------------------------
// Windowed attention via mma.sync tf32 — 256 threads / 8 warps.
// Block = (window, head). T=128, hd=32.
//   Phase 1: S = QK^T * 3/sqrt(32), warp w -> rows w*16..+15 (fp32 smem)
//   Phase 2: quad-per-row softmax (2 iters of 8 rows/warp); exp back as tf32
//   Phase 3: O^T = V^T P^T, warp w -> N rows w*16..+15 (its own S rows)
//   Phase 4: scale 3/rowsum, smem stage, coalesced store
// Smem (102912 B): Ssm[128][132] | rsum[128] | X{Qs[32][136]+Ks | Vs[128][40] | Os[128][33]}
// ---------------------------------------------------------------------------
#define ATT_SMEM 102912

template<int HS, int WS, int COFF>
__global__ __launch_bounds__(256) void attn_mma_kernel()
{
    extern __shared__ char sm[];
    float*    Ssm  = (float*)sm;                    // [128][132]
    uint32_t* Su   = (uint32_t*)sm;
    float*    rsum = (float*)(sm + 67584);
    uint32_t* Qs   = (uint32_t*)(sm + 68096);       // [32][136]
    uint32_t* Ks   = Qs + 32 * 136;
    uint32_t* Vs   = (uint32_t*)(sm + 68096);       // [128][40]
    float*    Os   = (float*)(sm + 68096);          // [128][33]

    constexpr int WWn = WDIM / WS;
    constexpr int WH  = HDIM / HS;
    constexpr float SCALE3 = 3.0f * 0.17677669529663688f;   // 3/sqrt(32)

    int bid = blockIdx.x;
    const int head = bid % 3; bid /= 3;
    const int ww = bid % WWn; bid /= WWn;
    const int wh = bid % WH;  bid /= WH;
    const int b  = bid;
    const int co = COFF + head * 32;

    const int t    = threadIdx.x;
    const int wid  = t >> 5;        // 0..7
    const int lane = t & 31;
    const int gid  = lane >> 2;     // 0..7
    const int tig  = lane & 3;      // 0..3

    const int sL = t >> 2;          // 0..63
    const int d0 = (t & 3) * 8;

    // ---- Phase 0: Q,K -> smem [dim][token] tf32 ----
#pragma unroll
    for (int p = 0; p < 2; p++) {
        const int ts = p * 64 + sL;
        const int l  = (wh * HS + ts / WS) * WDIM + ww * WS + ts % WS;
        const float* qb = g_qkv + ((size_t)b * LTOK + l) * (3 * CCH) + co;
        const float* kb = qb + CCH;
        const float4 q0 = *(const float4*)(qb + d0);
        const float4 q1 = *(const float4*)(qb + d0 + 4);
        const float4 k0 = *(const float4*)(kb + d0);
        const float4 k1 = *(const float4*)(kb + d0 + 4);
        const float qa[8] = {q0.x,q0.y,q0.z,q0.w,q1.x,q1.y,q1.z,q1.w};
        const float ka[8] = {k0.x,k0.y,k0.z,k0.w,k1.x,k1.y,k1.z,k1.w};
#pragma unroll
        for (int j = 0; j < 8; j++) {
            Qs[(d0 + j) * 136 + ts] = f2tf32(qa[j]);
            Ks[(d0 + j) * 136 + ts] = f2tf32(ka[j]);
        }
    }
    __syncthreads();

    // ---- Phase 1: S rows wid*16..+15 ----
    {
        const int mrb = wid * 16;
#pragma unroll
        for (int nc = 0; nc < 4; nc++) {
            float acc[4][4] = {};
#pragma unroll
            for (int ks = 0; ks < 4; ks++) {
                const int kr = ks * 8;
                uint32_t af[4];
                af[0] = Qs[(kr + tig    ) * 136 + mrb + gid];
                af[1] = Qs[(kr + tig    ) * 136 + mrb + gid + 8];
                af[2] = Qs[(kr + tig + 4) * 136 + mrb + gid];
                af[3] = Qs[(kr + tig + 4) * 136 + mrb + gid + 8];
                uint32_t bf[4][2];
#pragma unroll
                for (int nt = 0; nt < 4; nt++) {
                    const int nb = nc * 32 + nt * 8;
                    bf[nt][0] = Ks[(kr + tig    ) * 136 + nb + gid];
                    bf[nt][1] = Ks[(kr + tig + 4) * 136 + nb + gid];
                }
#pragma unroll
                for (int nt = 0; nt < 4; nt++)
                    mma_tf32(acc[nt], af, bf[nt]);
            }
            const int r0 = mrb + gid;
#pragma unroll
            for (int nt = 0; nt < 4; nt++) {
                const int col = nc * 32 + nt * 8 + tig * 2;
                Ssm[r0 * 132 + col]           = acc[nt][0] * SCALE3;
                Ssm[r0 * 132 + col + 1]       = acc[nt][1] * SCALE3;
                Ssm[(r0 + 8) * 132 + col]     = acc[nt][2] * SCALE3;
                Ssm[(r0 + 8) * 132 + col + 1] = acc[nt][3] * SCALE3;
            }
        }
    }
    __syncthreads();   // S done; Qs/Ks dead

    // ---- Phase 2a: V -> X region ----
#pragma unroll
    for (int p = 0; p < 2; p++) {
        const int ts = p * 64 + sL;
        const int l  = (wh * HS + ts / WS) * WDIM + ww * WS + ts % WS;
        const float* vb = g_qkv + ((size_t)b * LTOK + l) * (3 * CCH) + 2 * CCH + co;
        const float4 v0 = *(const float4*)(vb + d0);
        const float4 v1 = *(const float4*)(vb + d0 + 4);
        uint4 t0, t1;
        t0.x = f2tf32(v0.x); t0.y = f2tf32(v0.y); t0.z = f2tf32(v0.z); t0.w = f2tf32(v0.w);
        t1.x = f2tf32(v1.x); t1.y = f2tf32(v1.y); t1.z = f2tf32(v1.z); t1.w = f2tf32(v1.w);
        *(uint4*)(Vs + ts * 40 + d0)     = t0;
        *(uint4*)(Vs + ts * 40 + d0 + 4) = t1;
    }

    // ---- Phase 2b: quad-per-row softmax on own 16 rows ----
#pragma unroll
    for (int i = 0; i < 2; i++) {
        const int r = wid * 16 + i * 8 + gid;
        float v[32];
#pragma unroll
        for (int jj = 0; jj < 32; jj++) v[jj] = Ssm[r * 132 + tig + 4 * jj];
        float mx = v[0];
#pragma unroll
        for (int jj = 1; jj < 32; jj++) mx = fmaxf(mx, v[jj]);
        mx = fmaxf(mx, __shfl_xor_sync(~0u, mx, 1));
        mx = fmaxf(mx, __shfl_xor_sync(~0u, mx, 2));
        float s = 0.0f;
#pragma unroll
        for (int jj = 0; jj < 32; jj++) {
            const float e = __expf(v[jj] - mx);
            s += e;
            Su[r * 132 + tig + 4 * jj] = f2tf32(e);
        }
        s += __shfl_xor_sync(~0u, s, 1);
        s += __shfl_xor_sync(~0u, s, 2);
        if (tig == 0) rsum[r] = 3.0f / s;
    }
    __syncthreads();

    // ---- Phase 3: O^T = V^T P^T ; warp w -> N rows w*16..+15 ----
    {
        const int nbb = wid * 16;
        float acc[2][2][4] = {};
#pragma unroll
        for (int ks = 0; ks < 16; ks++) {
            const int kr = ks * 8;
            uint32_t af[2][4];
#pragma unroll
            for (int mt = 0; mt < 2; mt++) {
                const int mr = mt * 16;
                af[mt][0] = Vs[(kr + tig    ) * 40 + mr + gid];
                af[mt][1] = Vs[(kr + tig    ) * 40 + mr + gid + 8];
                af[mt][2] = Vs[(kr + tig + 4) * 40 + mr + gid];
                af[mt][3] = Vs[(kr + tig + 4) * 40 + mr + gid + 8];
            }
            uint32_t bf[2][2];
#pragma unroll
            for (int nt = 0; nt < 2; nt++) {
                const int nb = nbb + nt * 8;
                bf[nt][0] = Su[(nb + gid) * 132 + kr + tig];
                bf[nt][1] = Su[(nb + gid) * 132 + kr + tig + 4];
            }
#pragma unroll
            for (int mt = 0; mt < 2; mt++)
#pragma unroll
                for (int nt = 0; nt < 2; nt++)
                    mma_tf32(acc[mt][nt], af[mt], bf[nt]);
        }
        __syncthreads();   // Vs dead before Os overwrite

#pragma unroll
        for (int mt = 0; mt < 2; mt++) {
            const int dim0 = mt * 16 + gid;
#pragma unroll
            for (int nt = 0; nt < 2; nt++) {
                const int r = nbb + nt * 8 + tig * 2;
                const float s0 = rsum[r], s1 = rsum[r + 1];
                Os[r * 33 + dim0]           = acc[mt][nt][0] * s0;
                Os[(r + 1) * 33 + dim0]     = acc[mt][nt][1] * s1;
                Os[r * 33 + dim0 + 8]       = acc[mt][nt][2] * s0;
                Os[(r + 1) * 33 + dim0 + 8] = acc[mt][nt][3] * s1;
            }
        }
    }
    __syncthreads();

    // ---- Phase 4: coalesced writeout ----
#pragma unroll
    for (int p = 0; p < 2; p++) {
        const int ts = p * 64 + sL;
        const int l  = (wh * HS + ts / WS) * WDIM + ww * WS + ts % WS;
        float* orow = g_fu + ((size_t)b * LTOK + l) * CCH + co + d0;
        float4 o0, o1;
        o0.x = Os[ts * 33 + d0];     o0.y = Os[ts * 33 + d0 + 1];
        o0.z = Os[ts * 33 + d0 + 2]; o0.w = Os[ts * 33 + d0 + 3];
        o1.x = Os[ts * 33 + d0 + 4]; o1.y = Os[ts * 33 + d0 + 5];
        o1.z = Os[ts * 33 + d0 + 6]; o1.w = Os[ts * 33 + d0 + 7];
        *(float4*)orow       = o0;
        *(float4*)(orow + 4) = o1;
    }
}

// ---------------------------------------------------------------------------
// Depthwise 3x3 + bias + BN + GELU, 4 pixels per thread
// ---------------------------------------------------------------------------
template<int WHICH>
__global__ __launch_bounds__(256) void dwconv_bn_gelu_kernel(
    const float* __restrict__ xin,
    const float* __restrict__ wdw,
    const float* __restrict__ bdw,
    const float* __restrict__ gbn,
    const float* __restrict__ bebn)
{
    const int idx = blockIdx.x * 256 + threadIdx.x;
    const int w0 = (idx & 31) * 4;
    const int h  = (idx >> 5) & 127;
    const int bc = idx >> 12;
    const int c  = bc % CCH;

    const float* in  = (WHICH == 0) ? xin : g_fuimg;
    float*       out = (WHICH == 0) ? g_conv1 : g_conv2;

    const float* p = in + (size_t)bc * LTOK;
    float wk[9];
#pragma unroll
    for (int i = 0; i < 9; i++) wk[i] = wdw[c * 9 + i];

    float o0 = 0.f, o1 = 0.f, o2 = 0.f, o3 = 0.f;
#pragma unroll
    for (int r = 0; r < 3; r++) {
        const int hh = h - 1 + r;
        if (hh < 0 || hh >= HDIM) continue;
        const float* row = p + hh * WDIM;
        const float4 cc = *(const float4*)(row + w0);
        const float lf = (w0 > 0)   ? row[w0 - 1] : 0.0f;
        const float rt = (w0 < 124) ? row[w0 + 4] : 0.0f;
        const float k0 = wk[r*3+0], k1 = wk[r*3+1], k2 = wk[r*3+2];
        o0 = fmaf(k0, lf,   fmaf(k1, cc.x, fmaf(k2, cc.y, o0)));
        o1 = fmaf(k0, cc.x, fmaf(k1, cc.y, fmaf(k2, cc.z, o1)));
        o2 = fmaf(k0, cc.y, fmaf(k1, cc.z, fmaf(k2, cc.w, o2)));
        o3 = fmaf(k0, cc.z, fmaf(k1, cc.w, fmaf(k2, rt,   o3)));
    }
    const float bni = rsqrtf(1.0f + 1e-5f);
    const float sc = gbn[c] * bni, bb = bebn[c], bs = bdw[c];
    float4 o;
    o.x = gelu_erf((o0 + bs) * sc + bb);
    o.y = gelu_erf((o1 + bs) * sc + bb);
    o.z = gelu_erf((o2 + bs) * sc + bb);
    o.w = gelu_erf((o3 + bs) * sc + bb);
    *(float4*)(out + (size_t)idx * 4) = o;
}

// ---------------------------------------------------------------------------
// Mean over H*W per (b,c)
// ---------------------------------------------------------------------------
__global__ __launch_bounds__(256) void mean_kernel()
{
    const int bc = blockIdx.x;
    const float* p = g_conv1 + (size_t)bc * LTOK;
    float s = 0.0f;
    for (int i = threadIdx.x; i < LTOK; i += 256) s += p[i];
#pragma unroll
    for (int o = 16; o > 0; o >>= 1) s += __shfl_xor_sync(0xffffffffu, s, o);
    __shared__ float red[8];
    if ((threadIdx.x & 31) == 0) red[threadIdx.x >> 5] = s;
    __syncthreads();
    if (threadIdx.x == 0) {
        float tot = 0.0f;
#pragma unroll
        for (int i = 0; i < 8; i++) tot += red[i];
        g_pool[bc] = tot * (1.0f / LTOK);
    }
}

// ---------------------------------------------------------------------------
// Spatial interaction map -> g_sgate
// ---------------------------------------------------------------------------
__global__ __launch_bounds__(128) void spatial_kernel(
    const float* __restrict__ w_si1, const float* __restrict__ b_si1,
    const float* __restrict__ g_si,  const float* __restrict__ be_si,
    const float* __restrict__ w_si2, const float* __restrict__ b_si2)
{
    __shared__ float wsm[CCH * C8];   // [c][o]
    for (int i = threadIdx.x; i < CCH * C8; i += 128)
        wsm[i] = w_si1[(i % C8) * CCH + (i / C8)];
    __syncthreads();

    const int pid = blockIdx.x * 128 + threadIdx.x;
    const int b  = pid / LTOK;
    const int hw = pid % LTOK;

    float t[C8];
#pragma unroll
    for (int o = 0; o < C8; o++) t[o] = 0.0f;

    const float* base = g_conv1 + (size_t)b * CCH * LTOK + hw;
    for (int c = 0; c < CCH; c++) {
        const float v = base[(size_t)c * LTOK];
        const float* wr = &wsm[c * C8];
#pragma unroll
        for (int o = 0; o < C8; o++) t[o] = fmaf(wr[o], v, t[o]);
    }

    const float bni = rsqrtf(1.0f + 1e-5f);
    float s = b_si2[0];
#pragma unroll
    for (int o = 0; o < C8; o++) {
        float u = (t[o] + b_si1[o]) * (g_si[o] * bni) + be_si[o];
        s = fmaf(w_si2[o], gelu_erf(u), s);
    }
    g_sgate[pid] = 1.0f + sigmoidf_(s);
}

// ---------------------------------------------------------------------------
// Channel interaction -> g_cgate
// ---------------------------------------------------------------------------
__global__ __launch_bounds__(192) void channel_kernel(
    const float* __restrict__ w_ci1, const float* __restrict__ b_ci1,
    const float* __restrict__ g_ci,  const float* __restrict__ be_ci,
    const float* __restrict__ w_ci2, const float* __restrict__ b_ci2)
{
    const int b = blockIdx.x;
    __shared__ float t[C8];
    const float bni = rsqrtf(1.0f + 1e-5f);
    if (threadIdx.x < C8) {
        const int o = threadIdx.x;
        float s = b_ci1[o];
        for (int c = 0; c < CCH; c++)
            s = fmaf(w_ci1[o * CCH + c], g_pool[b * CCH + c], s);
        s = s * (g_ci[o] * bni) + be_ci[o];
        t[o] = gelu_erf(s);
    }
    __syncthreads();
    const int c = threadIdx.x;
    float s = b_ci2[c];
#pragma unroll
    for (int o = 0; o < C8; o++) s = fmaf(w_ci2[c * C8 + o], t[o], s);
    g_cgate[b * CCH + c] = 1.0f + sigmoidf_(s);
}

// ---------------------------------------------------------------------------
// Gate-1 + transpose: g_fuimg[b,c,l] = g_fu[b,l,c] * g_sgate[b,l]
// ---------------------------------------------------------------------------
__global__ __launch_bounds__(256) void gate1_transpose_kernel()
{
    __shared__ float tile[32][33];
    const int l0 = blockIdx.x * 32;
    const int c0 = blockIdx.y * 32;
    const int b  = blockIdx.z;

#pragma unroll
    for (int i = 0; i < 4; i++) {
        const int ly = threadIdx.y + i * 8;
        const int l = l0 + ly;
        tile[ly][threadIdx.x] =
            g_fu[((size_t)b * LTOK + l) * CCH + c0 + threadIdx.x] * g_sgate[b * LTOK + l];
    }
    __syncthreads();
#pragma unroll
    for (int i = 0; i < 4; i++) {
        const int cy = threadIdx.y + i * 8;
        g_fuimg[((size_t)b * CCH + c0 + cy) * LTOK + l0 + threadIdx.x] =
            tile[threadIdx.x][cy];
    }
}

// ---------------------------------------------------------------------------
// kernel_launch
// ---------------------------------------------------------------------------
extern "C" void kernel_launch(void* const* d_in, const int* in_sizes, int n_in,
                              void* d_out, int out_size)
{
    const float* x      = (const float*)d_in[0];
    const float* w_qkv  = (const float*)d_in[1];
    const float* b_qkv  = (const float*)d_in[2];
    const float* w_dw1  = (const float*)d_in[3];
    const float* b_dw1  = (const float*)d_in[4];
    const float* gbn1   = (const float*)d_in[5];
    const float* bebn1  = (const float*)d_in[6];
    const float* w_si1  = (const float*)d_in[7];
    const float* b_si1  = (const float*)d_in[8];
    const float* g_si   = (const float*)d_in[9];
    const float* be_si  = (const float*)d_in[10];
    const float* w_si2  = (const float*)d_in[11];
    const float* b_si2  = (const float*)d_in[12];
    const float* w_ci1  = (const float*)d_in[13];
    const float* b_ci1  = (const float*)d_in[14];
    const float* g_ci   = (const float*)d_in[15];
    const float* be_ci  = (const float*)d_in[16];
    const float* w_ci2  = (const float*)d_in[17];
    const float* b_ci2  = (const float*)d_in[18];
    const float* w_dw2  = (const float*)d_in[19];
    const float* b_dw2  = (const float*)d_in[20];
    const float* gbn2   = (const float*)d_in[21];
    const float* bebn2  = (const float*)d_in[22];
    const float* w_proj = (const float*)d_in[23];
    const float* b_proj = (const float*)d_in[24];
    float* out = (float*)d_out;

    cudaFuncSetAttribute(attn_mma_kernel<8, 16, 0>,
                         cudaFuncAttributeMaxDynamicSharedMemorySize, ATT_SMEM);
    cudaFuncSetAttribute(attn_mma_kernel<16, 8, 96>,
                         cudaFuncAttributeMaxDynamicSharedMemorySize, ATT_SMEM);

    // 0) x -> xT
    xpose_kernel<<<dim3(MTOT / 32, CCH / 32), dim3(32, 8)>>>(x);

    // 1) qkv = x @ w_qkv + b_qkv
    mma_gemm_kernel<0, 3 * CCH><<<dim3((3 * CCH) / 96, MTOT / 128), 192>>>(
        w_qkv, b_qkv, nullptr);

    // 2) windowed attention (tensor-core, 256 thr) -> g_fu
    attn_mma_kernel<8, 16, 0 ><<<BSZ * (HDIM / 8) * (WDIM / 16) * 3, 256, ATT_SMEM>>>();
    attn_mma_kernel<16, 8, 96><<<BSZ * (HDIM / 16) * (WDIM / 8) * 3, 256, ATT_SMEM>>>();

    // 3) conv_x1 -> g_conv1
    dwconv_bn_gelu_kernel<0><<<(MTOT * CCH) / 1024, 256>>>(x, w_dw1, b_dw1, gbn1, bebn1);

    // 4) pooling + interaction maps
    mean_kernel<<<BSZ * CCH, 256>>>();
    spatial_kernel<<<MTOT / 128, 128>>>(w_si1, b_si1, g_si, be_si, w_si2, b_si2);
    channel_kernel<<<BSZ, CCH>>>(w_ci1, b_ci1, g_ci, be_ci, w_ci2, b_ci2);

    // 5) gate-1 + transpose -> g_fuimg
    gate1_transpose_kernel<<<dim3(LTOK / 32, CCH / 32, BSZ), dim3(32, 8)>>>();

    // 6) conv2 -> g_conv2
    dwconv_bn_gelu_kernel<1><<<(MTOT * CCH) / 1024, 256>>>(nullptr, w_dw2, b_dw2, gbn2, bebn2);

    // 7) out = (channel-gated conv2) @ w_proj + b_proj
    mma_gemm_kernel<1, CCH><<<dim3(CCH / 96, MTOT / 128), 192>>>(
        w_proj, b_proj, out);
}

// round 9
// speedup vs baseline: 1.8869x; 1.0318x over previous
#include <cuda_runtime.h>
#include <math.h>
#include <stdint.h>

// ---------------------------------------------------------------------------
// Problem constants
// ---------------------------------------------------------------------------
#define BSZ   8
#define HDIM  128
#define WDIM  128
#define CCH   192
#define LTOK  16384
#define C8    24
#define MTOT  (BSZ * LTOK)   // 131072

static __device__ __forceinline__ float gelu_erf(float x) {
    return 0.5f * x * (1.0f + erff(x * 0.70710678118654752f));
}
static __device__ __forceinline__ float sigmoidf_(float x) {
    return 1.0f / (1.0f + expf(-x));
}
static __device__ __forceinline__ uint32_t f2tf32(float x) {
    uint32_t r;
    asm("cvt.rna.tf32.f32 %0, %1;" : "=r"(r) : "f"(x));
    return r;
}

// m16n8k8 tf32 tensor-core MMA (proven layout)
static __device__ __forceinline__ void mma_tf32(
    float* c, const uint32_t* a, const uint32_t* b)
{
    asm volatile(
        "mma.sync.aligned.m16n8k8.row.col.f32.tf32.tf32.f32 "
        "{%0,%1,%2,%3}, {%4,%5,%6,%7}, {%8,%9}, {%0,%1,%2,%3};\n"
        : "+f"(c[0]), "+f"(c[1]), "+f"(c[2]), "+f"(c[3])
        : "r"(a[0]), "r"(a[1]), "r"(a[2]), "r"(a[3]),
          "r"(b[0]), "r"(b[1]));
}

// ---------------------------------------------------------------------------
// Device scratch
// ---------------------------------------------------------------------------
__device__ float g_qkv [MTOT * 3 * CCH];   // (B,L,3C)
__device__ float g_conv1[MTOT * CCH];      // (B,C,H,W)
__device__ float g_fuimg[MTOT * CCH];      // (B,C,H,W) gated attn out (NCHW)
__device__ float g_conv2[MTOT * CCH];      // (B,C,H,W)
__device__ float g_xT  [CCH * MTOT];       // xT[k][m]
__device__ float g_sgate[MTOT];
__device__ float g_pool [BSZ * CCH];
__device__ float g_cgate[BSZ * CCH];

// ---------------------------------------------------------------------------
// GEMM via mma.sync tf32 (unchanged — proven)
// ---------------------------------------------------------------------------
#define APAD 136
#define BPAD 104

template<int MODE, int NFULL>
__global__ __launch_bounds__(192) void mma_gemm_kernel(
    const float* __restrict__ Bw,
    const float* __restrict__ bias,
    float* __restrict__ Cout)
{
    __shared__ uint32_t As[16][APAD];
    __shared__ uint32_t Bs[16][BPAD];

    const int tid  = threadIdx.x;
    const int wid  = tid >> 5;
    const int lane = tid & 31;
    const int gid  = lane >> 2;
    const int tig  = lane & 3;
    const int warp_m = wid & 1;
    const int warp_n = wid >> 1;

    const int n0 = blockIdx.x * 96;
    const int m0 = blockIdx.y * 128;
    const int bb = m0 / LTOK;
    const int lb = m0 % LTOK;

    float* __restrict__ outp = (MODE == 0) ? g_qkv : Cout;

    float acc[4][4][4];
#pragma unroll
    for (int mt = 0; mt < 4; mt++)
#pragma unroll
        for (int nt = 0; nt < 4; nt++)
#pragma unroll
            for (int v = 0; v < 4; v++) acc[mt][nt][v] = 0.0f;

    for (int kt = 0; kt < CCH; kt += 16) {
        __syncthreads();
#pragma unroll
        for (int it = 0; it < 3; it++) {
            const int lin = tid + it * 192;
            if (lin < 512) {
                const int k  = lin >> 5;
                const int mq = (lin & 31) << 2;
                float4 v;
                if (MODE == 0) {
                    v = *(const float4*)(g_xT + (size_t)(kt + k) * MTOT + m0 + mq);
                } else {
                    v = *(const float4*)(g_conv2 + (size_t)bb * CCH * LTOK
                                         + (size_t)(kt + k) * LTOK + lb + mq);
                    const float g = g_cgate[bb * CCH + kt + k];
                    v.x *= g; v.y *= g; v.z *= g; v.w *= g;
                }
                uint4 t;
                t.x = f2tf32(v.x); t.y = f2tf32(v.y);
                t.z = f2tf32(v.z); t.w = f2tf32(v.w);
                *(uint4*)&As[k][mq] = t;
            }
        }
#pragma unroll
        for (int it = 0; it < 2; it++) {
            const int lin = tid + it * 192;
            const int k   = lin / 24;
            const int nq  = (lin % 24) << 2;
            float4 v = *(const float4*)(Bw + (size_t)(kt + k) * NFULL + n0 + nq);
            uint4 t;
            t.x = f2tf32(v.x); t.y = f2tf32(v.y);
            t.z = f2tf32(v.z); t.w = f2tf32(v.w);
            *(uint4*)&Bs[k][nq] = t;
        }
        __syncthreads();

#pragma unroll
        for (int ks = 0; ks < 2; ks++) {
            const int kr = ks * 8;
            uint32_t af[4][4];
#pragma unroll
            for (int mt = 0; mt < 4; mt++) {
                const int mr = warp_m * 64 + mt * 16;
                af[mt][0] = As[kr + tig    ][mr + gid];
                af[mt][1] = As[kr + tig    ][mr + gid + 8];
                af[mt][2] = As[kr + tig + 4][mr + gid];
                af[mt][3] = As[kr + tig + 4][mr + gid + 8];
            }
            uint32_t bf[4][2];
#pragma unroll
            for (int nt = 0; nt < 4; nt++) {
                const int nb = warp_n * 32 + nt * 8;
                bf[nt][0] = Bs[kr + tig    ][nb + gid];
                bf[nt][1] = Bs[kr + tig + 4][nb + gid];
            }
#pragma unroll
            for (int mt = 0; mt < 4; mt++)
#pragma unroll
                for (int nt = 0; nt < 4; nt++)
                    mma_tf32(acc[mt][nt], af[mt], bf[nt]);
        }
    }

#pragma unroll
    for (int mt = 0; mt < 4; mt++) {
        const int r0 = m0 + warp_m * 64 + mt * 16 + gid;
#pragma unroll
        for (int nt = 0; nt < 4; nt++) {
            const int col = n0 + warp_n * 32 + nt * 8 + tig * 2;
            const float bx = bias[col], by = bias[col + 1];
            float2 v0 = { acc[mt][nt][0] + bx, acc[mt][nt][1] + by };
            float2 v1 = { acc[mt][nt][2] + bx, acc[mt][nt][3] + by };
            *(float2*)(outp + (size_t)r0 * NFULL + col) = v0;
            *(float2*)(outp + (size_t)(r0 + 8) * NFULL + col) = v1;
        }
    }
}

// ---------------------------------------------------------------------------
// x -> g_xT transpose
// ---------------------------------------------------------------------------
__global__ __launch_bounds__(256) void xpose_kernel(const float* __restrict__ x)
{
    __shared__ float tile[32][33];
    const int m0 = blockIdx.x * 32;
    const int c0 = blockIdx.y * 32;
#pragma unroll
    for (int i = 0; i < 4; i++) {
        const int my = threadIdx.y + i * 8;
        tile[my][threadIdx.x] = x[(size_t)(m0 + my) * CCH + c0 + threadIdx.x];
    }
    __syncthreads();
#pragma unroll
    for (int i = 0; i < 4; i++) {
        const int cy = threadIdx.y + i * 8;
        g_xT[(size_t)(c0 + cy) * MTOT + m0 + threadIdx.x] = tile[threadIdx.x][cy];
    }
}

// ---------------------------------------------------------------------------
// Windowed attention — EXACT R6-proven body (smem softmax), with only:
//   * spatial gate folded into rsum
//   * phase-4 writes NCHW directly to g_fuimg
// 256 threads / 8 warps, smem 102912 B.
// ---------------------------------------------------------------------------
#define ATT_SMEM 102912

template<int HS, int WS, int COFF>
__global__ __launch_bounds__(256) void attn_mma_kernel()
{
    extern __shared__ char sm[];
    float*    Ssm  = (float*)sm;                    // [128][132]
    uint32_t* Su   = (uint32_t*)sm;
    float*    rsum = (float*)(sm + 67584);
    uint32_t* Qs   = (uint32_t*)(sm + 68096);       // [32][136]
    uint32_t* Ks   = Qs + 32 * 136;
    uint32_t* Vs   = (uint32_t*)(sm + 68096);       // [128][40]
    float*    Os   = (float*)(sm + 68096);          // [128][33]

    constexpr int WWn = WDIM / WS;
    constexpr int WH  = HDIM / HS;
    constexpr float SCALE3 = 3.0f * 0.17677669529663688f;   // 3/sqrt(32)

    int bid = blockIdx.x;
    const int head = bid % 3; bid /= 3;
    const int ww = bid % WWn; bid /= WWn;
    const int wh = bid % WH;  bid /= WH;
    const int b  = bid;
    const int co = COFF + head * 32;

    const int t    = threadIdx.x;
    const int wid  = t >> 5;        // 0..7
    const int lane = t & 31;
    const int gid  = lane >> 2;     // 0..7
    const int tig  = lane & 3;      // 0..3

    const int sL = t >> 2;          // 0..63
    const int d0 = (t & 3) * 8;

    // ---- Phase 0: Q,K -> smem [dim][token] tf32 ----
#pragma unroll
    for (int p = 0; p < 2; p++) {
        const int ts = p * 64 + sL;
        const int l  = (wh * HS + ts / WS) * WDIM + ww * WS + ts % WS;
        const float* qb = g_qkv + ((size_t)b * LTOK + l) * (3 * CCH) + co;
        const float* kb = qb + CCH;
        const float4 q0 = *(const float4*)(qb + d0);
        const float4 q1 = *(const float4*)(qb + d0 + 4);
        const float4 k0 = *(const float4*)(kb + d0);
        const float4 k1 = *(const float4*)(kb + d0 + 4);
        const float qa[8] = {q0.x,q0.y,q0.z,q0.w,q1.x,q1.y,q1.z,q1.w};
        const float ka[8] = {k0.x,k0.y,k0.z,k0.w,k1.x,k1.y,k1.z,k1.w};
#pragma unroll
        for (int j = 0; j < 8; j++) {
            Qs[(d0 + j) * 136 + ts] = f2tf32(qa[j]);
            Ks[(d0 + j) * 136 + ts] = f2tf32(ka[j]);
        }
    }
    __syncthreads();

    // ---- Phase 1: S rows wid*16..+15 ----
    {
        const int mrb = wid * 16;
#pragma unroll
        for (int nc = 0; nc < 4; nc++) {
            float acc[4][4] = {};
#pragma unroll
            for (int ks = 0; ks < 4; ks++) {
                const int kr = ks * 8;
                uint32_t af[4];
                af[0] = Qs[(kr + tig    ) * 136 + mrb + gid];
                af[1] = Qs[(kr + tig    ) * 136 + mrb + gid + 8];
                af[2] = Qs[(kr + tig + 4) * 136 + mrb + gid];
                af[3] = Qs[(kr + tig + 4) * 136 + mrb + gid + 8];
                uint32_t bf[4][2];
#pragma unroll
                for (int nt = 0; nt < 4; nt++) {
                    const int nb = nc * 32 + nt * 8;
                    bf[nt][0] = Ks[(kr + tig    ) * 136 + nb + gid];
                    bf[nt][1] = Ks[(kr + tig + 4) * 136 + nb + gid];
                }
#pragma unroll
                for (int nt = 0; nt < 4; nt++)
                    mma_tf32(acc[nt], af, bf[nt]);
            }
            const int r0 = mrb + gid;
#pragma unroll
            for (int nt = 0; nt < 4; nt++) {
                const int col = nc * 32 + nt * 8 + tig * 2;
                Ssm[r0 * 132 + col]           = acc[nt][0] * SCALE3;
                Ssm[r0 * 132 + col + 1]       = acc[nt][1] * SCALE3;
                Ssm[(r0 + 8) * 132 + col]     = acc[nt][2] * SCALE3;
                Ssm[(r0 + 8) * 132 + col + 1] = acc[nt][3] * SCALE3;
            }
        }
    }
    __syncthreads();   // S done; Qs/Ks dead

    // ---- Phase 2a: V -> X region ----
#pragma unroll
    for (int p = 0; p < 2; p++) {
        const int ts = p * 64 + sL;
        const int l  = (wh * HS + ts / WS) * WDIM + ww * WS + ts % WS;
        const float* vb = g_qkv + ((size_t)b * LTOK + l) * (3 * CCH) + 2 * CCH + co;
        const float4 v0 = *(const float4*)(vb + d0);
        const float4 v1 = *(const float4*)(vb + d0 + 4);
        uint4 t0, t1;
        t0.x = f2tf32(v0.x); t0.y = f2tf32(v0.y); t0.z = f2tf32(v0.z); t0.w = f2tf32(v0.w);
        t1.x = f2tf32(v1.x); t1.y = f2tf32(v1.y); t1.z = f2tf32(v1.z); t1.w = f2tf32(v1.w);
        *(uint4*)(Vs + ts * 40 + d0)     = t0;
        *(uint4*)(Vs + ts * 40 + d0 + 4) = t1;
    }

    // ---- Phase 2b: quad-per-row softmax on own 16 rows (gate folded) ----
#pragma unroll
    for (int i = 0; i < 2; i++) {
        const int r = wid * 16 + i * 8 + gid;
        float v[32];
#pragma unroll
        for (int jj = 0; jj < 32; jj++) v[jj] = Ssm[r * 132 + tig + 4 * jj];
        float mx = v[0];
#pragma unroll
        for (int jj = 1; jj < 32; jj++) mx = fmaxf(mx, v[jj]);
        mx = fmaxf(mx, __shfl_xor_sync(~0u, mx, 1));
        mx = fmaxf(mx, __shfl_xor_sync(~0u, mx, 2));
        float s = 0.0f;
#pragma unroll
        for (int jj = 0; jj < 32; jj++) {
            const float e = __expf(v[jj] - mx);
            s += e;
            Su[r * 132 + tig + 4 * jj] = f2tf32(e);
        }
        s += __shfl_xor_sync(~0u, s, 1);
        s += __shfl_xor_sync(~0u, s, 2);
        if (tig == 0) {
            const int lr = (wh * HS + r / WS) * WDIM + ww * WS + r % WS;
            rsum[r] = 3.0f * g_sgate[b * LTOK + lr] / s;
        }
    }
    __syncthreads();

    // ---- Phase 3: O^T = V^T P^T ; warp w -> N rows w*16..+15 ----
    {
        const int nbb = wid * 16;
        float acc[2][2][4] = {};
#pragma unroll
        for (int ks = 0; ks < 16; ks++) {
            const int kr = ks * 8;
            uint32_t af[2][4];
#pragma unroll
            for (int mt = 0; mt < 2; mt++) {
                const int mr = mt * 16;
                af[mt][0] = Vs[(kr + tig    ) * 40 + mr + gid];
                af[mt][1] = Vs[(kr + tig    ) * 40 + mr + gid + 8];
                af[mt][2] = Vs[(kr + tig + 4) * 40 + mr + gid];
                af[mt][3] = Vs[(kr + tig + 4) * 40 + mr + gid + 8];
            }
            uint32_t bf[2][2];
#pragma unroll
            for (int nt = 0; nt < 2; nt++) {
                const int nb = nbb + nt * 8;
                bf[nt][0] = Su[(nb + gid) * 132 + kr + tig];
                bf[nt][1] = Su[(nb + gid) * 132 + kr + tig + 4];
            }
#pragma unroll
            for (int mt = 0; mt < 2; mt++)
#pragma unroll
                for (int nt = 0; nt < 2; nt++)
                    mma_tf32(acc[mt][nt], af[mt], bf[nt]);
        }
        __syncthreads();   // Vs dead before Os overwrite

#pragma unroll
        for (int mt = 0; mt < 2; mt++) {
            const int dim0 = mt * 16 + gid;
#pragma unroll
            for (int nt = 0; nt < 2; nt++) {
                const int r = nbb + nt * 8 + tig * 2;
                const float s0 = rsum[r], s1 = rsum[r + 1];
                Os[r * 33 + dim0]           = acc[mt][nt][0] * s0;
                Os[(r + 1) * 33 + dim0]     = acc[mt][nt][1] * s1;
                Os[r * 33 + dim0 + 8]       = acc[mt][nt][2] * s0;
                Os[(r + 1) * 33 + dim0 + 8] = acc[mt][nt][3] * s1;
            }
        }
    }
    __syncthreads();

    // ---- Phase 4: transposed NCHW writeout (warp-per-channel-slice) ----
#pragma unroll
    for (int cc = 0; cc < 4; cc++) {
        const int c = wid * 4 + cc;
        float* cbase = g_fuimg + ((size_t)b * CCH + co + c) * LTOK;
#pragma unroll
        for (int rp = 0; rp < 4; rp++) {
            const int ts = rp * 32 + lane;
            const int l  = (wh * HS + ts / WS) * WDIM + ww * WS + ts % WS;
            cbase[l] = Os[ts * 33 + c];
        }
    }
}

// ---------------------------------------------------------------------------
// Depthwise 3x3 + bias + BN + GELU, 4 pixels per thread
// ---------------------------------------------------------------------------
template<int WHICH>
__global__ __launch_bounds__(256) void dwconv_bn_gelu_kernel(
    const float* __restrict__ xin,
    const float* __restrict__ wdw,
    const float* __restrict__ bdw,
    const float* __restrict__ gbn,
    const float* __restrict__ bebn)
{
    const int idx = blockIdx.x * 256 + threadIdx.x;
    const int w0 = (idx & 31) * 4;
    const int h  = (idx >> 5) & 127;
    const int bc = idx >> 12;
    const int c  = bc % CCH;

    const float* in  = (WHICH == 0) ? xin : g_fuimg;
    float*       out = (WHICH == 0) ? g_conv1 : g_conv2;

    const float* p = in + (size_t)bc * LTOK;
    float wk[9];
#pragma unroll
    for (int i = 0; i < 9; i++) wk[i] = wdw[c * 9 + i];

    float o0 = 0.f, o1 = 0.f, o2 = 0.f, o3 = 0.f;
#pragma unroll
    for (int r = 0; r < 3; r++) {
        const int hh = h - 1 + r;
        if (hh < 0 || hh >= HDIM) continue;
        const float* row = p + hh * WDIM;
        const float4 cc = *(const float4*)(row + w0);
        const float lf = (w0 > 0)   ? row[w0 - 1] : 0.0f;
        const float rt = (w0 < 124) ? row[w0 + 4] : 0.0f;
        const float k0 = wk[r*3+0], k1 = wk[r*3+1], k2 = wk[r*3+2];
        o0 = fmaf(k0, lf,   fmaf(k1, cc.x, fmaf(k2, cc.y, o0)));
        o1 = fmaf(k0, cc.x, fmaf(k1, cc.y, fmaf(k2, cc.z, o1)));
        o2 = fmaf(k0, cc.y, fmaf(k1, cc.z, fmaf(k2, cc.w, o2)));
        o3 = fmaf(k0, cc.z, fmaf(k1, cc.w, fmaf(k2, rt,   o3)));
    }
    const float bni = rsqrtf(1.0f + 1e-5f);
    const float sc = gbn[c] * bni, bb = bebn[c], bs = bdw[c];
    float4 o;
    o.x = gelu_erf((o0 + bs) * sc + bb);
    o.y = gelu_erf((o1 + bs) * sc + bb);
    o.z = gelu_erf((o2 + bs) * sc + bb);
    o.w = gelu_erf((o3 + bs) * sc + bb);
    *(float4*)(out + (size_t)idx * 4) = o;
}

// ---------------------------------------------------------------------------
// Mean over H*W per (b,c)
// ---------------------------------------------------------------------------
__global__ __launch_bounds__(256) void mean_kernel()
{
    const int bc = blockIdx.x;
    const float* p = g_conv1 + (size_t)bc * LTOK;
    float s = 0.0f;
    for (int i = threadIdx.x; i < LTOK; i += 256) s += p[i];
#pragma unroll
    for (int o = 16; o > 0; o >>= 1) s += __shfl_xor_sync(0xffffffffu, s, o);
    __shared__ float red[8];
    if ((threadIdx.x & 31) == 0) red[threadIdx.x >> 5] = s;
    __syncthreads();
    if (threadIdx.x == 0) {
        float tot = 0.0f;
#pragma unroll
        for (int i = 0; i < 8; i++) tot += red[i];
        g_pool[bc] = tot * (1.0f / LTOK);
    }
}

// ---------------------------------------------------------------------------
// Spatial interaction map -> g_sgate
// ---------------------------------------------------------------------------
__global__ __launch_bounds__(128) void spatial_kernel(
    const float* __restrict__ w_si1, const float* __restrict__ b_si1,
    const float* __restrict__ g_si,  const float* __restrict__ be_si,
    const float* __restrict__ w_si2, const float* __restrict__ b_si2)
{
    __shared__ float wsm[CCH * C8];   // [c][o]
    for (int i = threadIdx.x; i < CCH * C8; i += 128)
        wsm[i] = w_si1[(i % C8) * CCH + (i / C8)];
    __syncthreads();

    const int pid = blockIdx.x * 128 + threadIdx.x;
    const int b  = pid / LTOK;
    const int hw = pid % LTOK;

    float t[C8];
#pragma unroll
    for (int o = 0; o < C8; o++) t[o] = 0.0f;

    const float* base = g_conv1 + (size_t)b * CCH * LTOK + hw;
    for (int c = 0; c < CCH; c++) {
        const float v = base[(size_t)c * LTOK];
        const float* wr = &wsm[c * C8];
#pragma unroll
        for (int o = 0; o < C8; o++) t[o] = fmaf(wr[o], v, t[o]);
    }

    const float bni = rsqrtf(1.0f + 1e-5f);
    float s = b_si2[0];
#pragma unroll
    for (int o = 0; o < C8; o++) {
        float u = (t[o] + b_si1[o]) * (g_si[o] * bni) + be_si[o];
        s = fmaf(w_si2[o], gelu_erf(u), s);
    }
    g_sgate[pid] = 1.0f + sigmoidf_(s);
}

// ---------------------------------------------------------------------------
// Channel interaction -> g_cgate
// ---------------------------------------------------------------------------
__global__ __launch_bounds__(192) void channel_kernel(
    const float* __restrict__ w_ci1, const float* __restrict__ b_ci1,
    const float* __restrict__ g_ci,  const float* __restrict__ be_ci,
    const float* __restrict__ w_ci2, const float* __restrict__ b_ci2)
{
    const int b = blockIdx.x;
    __shared__ float t[C8];
    const float bni = rsqrtf(1.0f + 1e-5f);
    if (threadIdx.x < C8) {
        const int o = threadIdx.x;
        float s = b_ci1[o];
        for (int c = 0; c < CCH; c++)
            s = fmaf(w_ci1[o * CCH + c], g_pool[b * CCH + c], s);
        s = s * (g_ci[o] * bni) + be_ci[o];
        t[o] = gelu_erf(s);
    }
    __syncthreads();
    const int c = threadIdx.x;
    float s = b_ci2[c];
#pragma unroll
    for (int o = 0; o < C8; o++) s = fmaf(w_ci2[c * C8 + o], t[o], s);
    g_cgate[b * CCH + c] = 1.0f + sigmoidf_(s);
}

// ---------------------------------------------------------------------------
// kernel_launch
// ---------------------------------------------------------------------------
extern "C" void kernel_launch(void* const* d_in, const int* in_sizes, int n_in,
                              void* d_out, int out_size)
{
    const float* x      = (const float*)d_in[0];
    const float* w_qkv  = (const float*)d_in[1];
    const float* b_qkv  = (const float*)d_in[2];
    const float* w_dw1  = (const float*)d_in[3];
    const float* b_dw1  = (const float*)d_in[4];
    const float* gbn1   = (const float*)d_in[5];
    const float* bebn1  = (const float*)d_in[6];
    const float* w_si1  = (const float*)d_in[7];
    const float* b_si1  = (const float*)d_in[8];
    const float* g_si   = (const float*)d_in[9];
    const float* be_si  = (const float*)d_in[10];
    const float* w_si2  = (const float*)d_in[11];
    const float* b_si2  = (const float*)d_in[12];
    const float* w_ci1  = (const float*)d_in[13];
    const float* b_ci1  = (const float*)d_in[14];
    const float* g_ci   = (const float*)d_in[15];
    const float* be_ci  = (const float*)d_in[16];
    const float* w_ci2  = (const float*)d_in[17];
    const float* b_ci2  = (const float*)d_in[18];
    const float* w_dw2  = (const float*)d_in[19];
    const float* b_dw2  = (const float*)d_in[20];
    const float* gbn2   = (const float*)d_in[21];
    const float* bebn2  = (const float*)d_in[22];
    const float* w_proj = (const float*)d_in[23];
    const float* b_proj = (const float*)d_in[24];
    float* out = (float*)d_out;

    cudaFuncSetAttribute(attn_mma_kernel<8, 16, 0>,
                         cudaFuncAttributeMaxDynamicSharedMemorySize, ATT_SMEM);
    cudaFuncSetAttribute(attn_mma_kernel<16, 8, 96>,
                         cudaFuncAttributeMaxDynamicSharedMemorySize, ATT_SMEM);

    // 0) x -> xT
    xpose_kernel<<<dim3(MTOT / 32, CCH / 32), dim3(32, 8)>>>(x);

    // 1) qkv = x @ w_qkv + b_qkv
    mma_gemm_kernel<0, 3 * CCH><<<dim3((3 * CCH) / 96, MTOT / 128), 192>>>(
        w_qkv, b_qkv, nullptr);

    // 2) conv path first (sgate must precede attention)
    dwconv_bn_gelu_kernel<0><<<(MTOT * CCH) / 1024, 256>>>(x, w_dw1, b_dw1, gbn1, bebn1);
    mean_kernel<<<BSZ * CCH, 256>>>();
    spatial_kernel<<<MTOT / 128, 128>>>(w_si1, b_si1, g_si, be_si, w_si2, b_si2);
    channel_kernel<<<BSZ, CCH>>>(w_ci1, b_ci1, g_ci, be_ci, w_ci2, b_ci2);

    // 3) attention (gate + transpose fused) -> g_fuimg (NCHW)
    attn_mma_kernel<8, 16, 0 ><<<BSZ * (HDIM / 8) * (WDIM / 16) * 3, 256, ATT_SMEM>>>();
    attn_mma_kernel<16, 8, 96><<<BSZ * (HDIM / 16) * (WDIM / 8) * 3, 256, ATT_SMEM>>>();

    // 4) conv2 -> g_conv2
    dwconv_bn_gelu_kernel<1><<<(MTOT * CCH) / 1024, 256>>>(nullptr, w_dw2, b_dw2, gbn2, bebn2);

    // 5) out = (channel-gated conv2) @ w_proj + b_proj
    mma_gemm_kernel<1, CCH><<<dim3(CCH / 96, MTOT / 128), 192>>>(
        w_proj, b_proj, out);
}

// round 10
// speedup vs baseline: 1.9284x; 1.0220x over previous
#include <cuda_runtime.h>
#include <math.h>
#include <stdint.h>

// ---------------------------------------------------------------------------
// Problem constants
// ---------------------------------------------------------------------------
#define BSZ   8
#define HDIM  128
#define WDIM  128
#define CCH   192
#define LTOK  16384
#define C8    24
#define MTOT  (BSZ * LTOK)   // 131072

static __device__ __forceinline__ float gelu_erf(float x) {
    return 0.5f * x * (1.0f + erff(x * 0.70710678118654752f));
}
static __device__ __forceinline__ float sigmoidf_(float x) {
    return 1.0f / (1.0f + expf(-x));
}
static __device__ __forceinline__ uint32_t f2tf32(float x) {
    uint32_t r;
    asm("cvt.rna.tf32.f32 %0, %1;" : "=r"(r) : "f"(x));
    return r;
}

// m16n8k8 tf32 tensor-core MMA (proven layout)
static __device__ __forceinline__ void mma_tf32(
    float* c, const uint32_t* a, const uint32_t* b)
{
    asm volatile(
        "mma.sync.aligned.m16n8k8.row.col.f32.tf32.tf32.f32 "
        "{%0,%1,%2,%3}, {%4,%5,%6,%7}, {%8,%9}, {%0,%1,%2,%3};\n"
        : "+f"(c[0]), "+f"(c[1]), "+f"(c[2]), "+f"(c[3])
        : "r"(a[0]), "r"(a[1]), "r"(a[2]), "r"(a[3]),
          "r"(b[0]), "r"(b[1]));
}

// ---------------------------------------------------------------------------
// Device scratch
// ---------------------------------------------------------------------------
__device__ float g_qkv [MTOT * 3 * CCH];   // (B,L,3C)
__device__ float g_conv1[MTOT * CCH];      // (B,C,H,W)
__device__ float g_fuimg[MTOT * CCH];      // (B,C,H,W) gated attn out (NCHW)
__device__ float g_conv2[MTOT * CCH];      // (B,C,H,W)
__device__ float g_sgate[MTOT];
__device__ float g_pool [BSZ * CCH];       // SUM over H*W (scaled in channel_kernel)
__device__ float g_cgate[BSZ * CCH];

// ---------------------------------------------------------------------------
// GEMM via mma.sync tf32.
// MODE 0: A = x row-major (M,192), transposed in the loader; out = g_qkv
// MODE 1: A = g_conv2 (k-major NCHW) * g_cgate; out = Cout
// MMA core + fragment addressing byte-identical to the proven R4-R9 kernel.
// ---------------------------------------------------------------------------
#define APAD 136
#define BPAD 104

template<int MODE, int NFULL>
__global__ __launch_bounds__(192) void mma_gemm_kernel(
    const float* __restrict__ Ain,
    const float* __restrict__ Bw,
    const float* __restrict__ bias,
    float* __restrict__ Cout)
{
    __shared__ uint32_t As[16][APAD];
    __shared__ uint32_t Bs[16][BPAD];

    const int tid  = threadIdx.x;
    const int wid  = tid >> 5;
    const int lane = tid & 31;
    const int gid  = lane >> 2;
    const int tig  = lane & 3;
    const int warp_m = wid & 1;
    const int warp_n = wid >> 1;

    const int n0 = blockIdx.x * 96;
    const int m0 = blockIdx.y * 128;
    const int bb = m0 / LTOK;
    const int lb = m0 % LTOK;

    float* __restrict__ outp = (MODE == 0) ? g_qkv : Cout;

    float acc[4][4][4];
#pragma unroll
    for (int mt = 0; mt < 4; mt++)
#pragma unroll
        for (int nt = 0; nt < 4; nt++)
#pragma unroll
            for (int v = 0; v < 4; v++) acc[mt][nt][v] = 0.0f;

    for (int kt = 0; kt < CCH; kt += 16) {
        __syncthreads();
        // ---- A tile ----
        if (MODE == 0) {
            // x row-major: 512 float4 (128 rows x 4 k-quads), transposing store
#pragma unroll
            for (int it = 0; it < 3; it++) {
                const int lin = tid + it * 192;
                if (lin < 512) {
                    const int row = lin >> 2;
                    const int q   = (lin & 3) * 4;
                    const float4 v = *(const float4*)(Ain + (size_t)(m0 + row) * CCH + kt + q);
                    As[q + 0][row] = f2tf32(v.x);
                    As[q + 1][row] = f2tf32(v.y);
                    As[q + 2][row] = f2tf32(v.z);
                    As[q + 3][row] = f2tf32(v.w);
                }
            }
        } else {
            // g_conv2 k-major: 512 float4 (16 k x 32 m-quads), gated
#pragma unroll
            for (int it = 0; it < 3; it++) {
                const int lin = tid + it * 192;
                if (lin < 512) {
                    const int k  = lin >> 5;
                    const int mq = (lin & 31) << 2;
                    float4 v = *(const float4*)(g_conv2 + (size_t)bb * CCH * LTOK
                                                + (size_t)(kt + k) * LTOK + lb + mq);
                    const float g = g_cgate[bb * CCH + kt + k];
                    uint4 t;
                    t.x = f2tf32(v.x * g); t.y = f2tf32(v.y * g);
                    t.z = f2tf32(v.z * g); t.w = f2tf32(v.w * g);
                    *(uint4*)&As[k][mq] = t;
                }
            }
        }
        // ---- B tile ----
#pragma unroll
        for (int it = 0; it < 2; it++) {
            const int lin = tid + it * 192;
            const int k   = lin / 24;
            const int nq  = (lin % 24) << 2;
            float4 v = *(const float4*)(Bw + (size_t)(kt + k) * NFULL + n0 + nq);
            uint4 t;
            t.x = f2tf32(v.x); t.y = f2tf32(v.y);
            t.z = f2tf32(v.z); t.w = f2tf32(v.w);
            *(uint4*)&Bs[k][nq] = t;
        }
        __syncthreads();

#pragma unroll
        for (int ks = 0; ks < 2; ks++) {
            const int kr = ks * 8;
            uint32_t af[4][4];
#pragma unroll
            for (int mt = 0; mt < 4; mt++) {
                const int mr = warp_m * 64 + mt * 16;
                af[mt][0] = As[kr + tig    ][mr + gid];
                af[mt][1] = As[kr + tig    ][mr + gid + 8];
                af[mt][2] = As[kr + tig + 4][mr + gid];
                af[mt][3] = As[kr + tig + 4][mr + gid + 8];
            }
            uint32_t bf[4][2];
#pragma unroll
            for (int nt = 0; nt < 4; nt++) {
                const int nb = warp_n * 32 + nt * 8;
                bf[nt][0] = Bs[kr + tig    ][nb + gid];
                bf[nt][1] = Bs[kr + tig + 4][nb + gid];
            }
#pragma unroll
            for (int mt = 0; mt < 4; mt++)
#pragma unroll
                for (int nt = 0; nt < 4; nt++)
                    mma_tf32(acc[mt][nt], af[mt], bf[nt]);
        }
    }

#pragma unroll
    for (int mt = 0; mt < 4; mt++) {
        const int r0 = m0 + warp_m * 64 + mt * 16 + gid;
#pragma unroll
        for (int nt = 0; nt < 4; nt++) {
            const int col = n0 + warp_n * 32 + nt * 8 + tig * 2;
            const float bx = bias[col], by = bias[col + 1];
            float2 v0 = { acc[mt][nt][0] + bx, acc[mt][nt][1] + by };
            float2 v1 = { acc[mt][nt][2] + bx, acc[mt][nt][3] + by };
            *(float2*)(outp + (size_t)r0 * NFULL + col) = v0;
            *(float2*)(outp + (size_t)(r0 + 8) * NFULL + col) = v1;
        }
    }
}

// ---------------------------------------------------------------------------
// Windowed attention — R9-proven body (unchanged)
// ---------------------------------------------------------------------------
#define ATT_SMEM 102912

template<int HS, int WS, int COFF>
__global__ __launch_bounds__(256) void attn_mma_kernel()
{
    extern __shared__ char sm[];
    float*    Ssm  = (float*)sm;                    // [128][132]
    uint32_t* Su   = (uint32_t*)sm;
    float*    rsum = (float*)(sm + 67584);
    uint32_t* Qs   = (uint32_t*)(sm + 68096);       // [32][136]
    uint32_t* Ks   = Qs + 32 * 136;
    uint32_t* Vs   = (uint32_t*)(sm + 68096);       // [128][40]
    float*    Os   = (float*)(sm + 68096);          // [128][33]

    constexpr int WWn = WDIM / WS;
    constexpr int WH  = HDIM / HS;
    constexpr float SCALE3 = 3.0f * 0.17677669529663688f;   // 3/sqrt(32)

    int bid = blockIdx.x;
    const int head = bid % 3; bid /= 3;
    const int ww = bid % WWn; bid /= WWn;
    const int wh = bid % WH;  bid /= WH;
    const int b  = bid;
    const int co = COFF + head * 32;

    const int t    = threadIdx.x;
    const int wid  = t >> 5;        // 0..7
    const int lane = t & 31;
    const int gid  = lane >> 2;     // 0..7
    const int tig  = lane & 3;      // 0..3

    const int sL = t >> 2;          // 0..63
    const int d0 = (t & 3) * 8;

    // ---- Phase 0: Q,K -> smem [dim][token] tf32 ----
#pragma unroll
    for (int p = 0; p < 2; p++) {
        const int ts = p * 64 + sL;
        const int l  = (wh * HS + ts / WS) * WDIM + ww * WS + ts % WS;
        const float* qb = g_qkv + ((size_t)b * LTOK + l) * (3 * CCH) + co;
        const float* kb = qb + CCH;
        const float4 q0 = *(const float4*)(qb + d0);
        const float4 q1 = *(const float4*)(qb + d0 + 4);
        const float4 k0 = *(const float4*)(kb + d0);
        const float4 k1 = *(const float4*)(kb + d0 + 4);
        const float qa[8] = {q0.x,q0.y,q0.z,q0.w,q1.x,q1.y,q1.z,q1.w};
        const float ka[8] = {k0.x,k0.y,k0.z,k0.w,k1.x,k1.y,k1.z,k1.w};
#pragma unroll
        for (int j = 0; j < 8; j++) {
            Qs[(d0 + j) * 136 + ts] = f2tf32(qa[j]);
            Ks[(d0 + j) * 136 + ts] = f2tf32(ka[j]);
        }
    }
    __syncthreads();

    // ---- Phase 1: S rows wid*16..+15 ----
    {
        const int mrb = wid * 16;
#pragma unroll
        for (int nc = 0; nc < 4; nc++) {
            float acc[4][4] = {};
#pragma unroll
            for (int ks = 0; ks < 4; ks++) {
                const int kr = ks * 8;
                uint32_t af[4];
                af[0] = Qs[(kr + tig    ) * 136 + mrb + gid];
                af[1] = Qs[(kr + tig    ) * 136 + mrb + gid + 8];
                af[2] = Qs[(kr + tig + 4) * 136 + mrb + gid];
                af[3] = Qs[(kr + tig + 4) * 136 + mrb + gid + 8];
                uint32_t bf[4][2];
#pragma unroll
                for (int nt = 0; nt < 4; nt++) {
                    const int nb = nc * 32 + nt * 8;
                    bf[nt][0] = Ks[(kr + tig    ) * 136 + nb + gid];
                    bf[nt][1] = Ks[(kr + tig + 4) * 136 + nb + gid];
                }
#pragma unroll
                for (int nt = 0; nt < 4; nt++)
                    mma_tf32(acc[nt], af, bf[nt]);
            }
            const int r0 = mrb + gid;
#pragma unroll
            for (int nt = 0; nt < 4; nt++) {
                const int col = nc * 32 + nt * 8 + tig * 2;
                Ssm[r0 * 132 + col]           = acc[nt][0] * SCALE3;
                Ssm[r0 * 132 + col + 1]       = acc[nt][1] * SCALE3;
                Ssm[(r0 + 8) * 132 + col]     = acc[nt][2] * SCALE3;
                Ssm[(r0 + 8) * 132 + col + 1] = acc[nt][3] * SCALE3;
            }
        }
    }
    __syncthreads();   // S done; Qs/Ks dead

    // ---- Phase 2a: V -> X region ----
#pragma unroll
    for (int p = 0; p < 2; p++) {
        const int ts = p * 64 + sL;
        const int l  = (wh * HS + ts / WS) * WDIM + ww * WS + ts % WS;
        const float* vb = g_qkv + ((size_t)b * LTOK + l) * (3 * CCH) + 2 * CCH + co;
        const float4 v0 = *(const float4*)(vb + d0);
        const float4 v1 = *(const float4*)(vb + d0 + 4);
        uint4 t0, t1;
        t0.x = f2tf32(v0.x); t0.y = f2tf32(v0.y); t0.z = f2tf32(v0.z); t0.w = f2tf32(v0.w);
        t1.x = f2tf32(v1.x); t1.y = f2tf32(v1.y); t1.z = f2tf32(v1.z); t1.w = f2tf32(v1.w);
        *(uint4*)(Vs + ts * 40 + d0)     = t0;
        *(uint4*)(Vs + ts * 40 + d0 + 4) = t1;
    }

    // ---- Phase 2b: quad-per-row softmax on own 16 rows (gate folded) ----
#pragma unroll
    for (int i = 0; i < 2; i++) {
        const int r = wid * 16 + i * 8 + gid;
        float v[32];
#pragma unroll
        for (int jj = 0; jj < 32; jj++) v[jj] = Ssm[r * 132 + tig + 4 * jj];
        float mx = v[0];
#pragma unroll
        for (int jj = 1; jj < 32; jj++) mx = fmaxf(mx, v[jj]);
        mx = fmaxf(mx, __shfl_xor_sync(~0u, mx, 1));
        mx = fmaxf(mx, __shfl_xor_sync(~0u, mx, 2));
        float s = 0.0f;
#pragma unroll
        for (int jj = 0; jj < 32; jj++) {
            const float e = __expf(v[jj] - mx);
            s += e;
            Su[r * 132 + tig + 4 * jj] = f2tf32(e);
        }
        s += __shfl_xor_sync(~0u, s, 1);
        s += __shfl_xor_sync(~0u, s, 2);
        if (tig == 0) {
            const int lr = (wh * HS + r / WS) * WDIM + ww * WS + r % WS;
            rsum[r] = 3.0f * g_sgate[b * LTOK + lr] / s;
        }
    }
    __syncthreads();

    // ---- Phase 3: O^T = V^T P^T ; warp w -> N rows w*16..+15 ----
    {
        const int nbb = wid * 16;
        float acc[2][2][4] = {};
#pragma unroll
        for (int ks = 0; ks < 16; ks++) {
            const int kr = ks * 8;
            uint32_t af[2][4];
#pragma unroll
            for (int mt = 0; mt < 2; mt++) {
                const int mr = mt * 16;
                af[mt][0] = Vs[(kr + tig    ) * 40 + mr + gid];
                af[mt][1] = Vs[(kr + tig    ) * 40 + mr + gid + 8];
                af[mt][2] = Vs[(kr + tig + 4) * 40 + mr + gid];
                af[mt][3] = Vs[(kr + tig + 4) * 40 + mr + gid + 8];
            }
            uint32_t bf[2][2];
#pragma unroll
            for (int nt = 0; nt < 2; nt++) {
                const int nb = nbb + nt * 8;
                bf[nt][0] = Su[(nb + gid) * 132 + kr + tig];
                bf[nt][1] = Su[(nb + gid) * 132 + kr + tig + 4];
            }
#pragma unroll
            for (int mt = 0; mt < 2; mt++)
#pragma unroll
                for (int nt = 0; nt < 2; nt++)
                    mma_tf32(acc[mt][nt], af[mt], bf[nt]);
        }
        __syncthreads();   // Vs dead before Os overwrite

#pragma unroll
        for (int mt = 0; mt < 2; mt++) {
            const int dim0 = mt * 16 + gid;
#pragma unroll
            for (int nt = 0; nt < 2; nt++) {
                const int r = nbb + nt * 8 + tig * 2;
                const float s0 = rsum[r], s1 = rsum[r + 1];
                Os[r * 33 + dim0]           = acc[mt][nt][0] * s0;
                Os[(r + 1) * 33 + dim0]     = acc[mt][nt][1] * s1;
                Os[r * 33 + dim0 + 8]       = acc[mt][nt][2] * s0;
                Os[(r + 1) * 33 + dim0 + 8] = acc[mt][nt][3] * s1;
            }
        }
    }
    __syncthreads();

    // ---- Phase 4: transposed NCHW writeout (warp-per-channel-slice) ----
#pragma unroll
    for (int cc = 0; cc < 4; cc++) {
        const int c = wid * 4 + cc;
        float* cbase = g_fuimg + ((size_t)b * CCH + co + c) * LTOK;
#pragma unroll
        for (int rp = 0; rp < 4; rp++) {
            const int ts = rp * 32 + lane;
            const int l  = (wh * HS + ts / WS) * WDIM + ww * WS + ts % WS;
            cbase[l] = Os[ts * 33 + c];
        }
    }
}

// ---------------------------------------------------------------------------
// zero g_pool (sums accumulated by dwconv<0>)
// ---------------------------------------------------------------------------
__global__ void zero_pool_kernel()
{
    const int i = blockIdx.x * 256 + threadIdx.x;
    if (i < BSZ * CCH) g_pool[i] = 0.0f;
}

// ---------------------------------------------------------------------------
// Depthwise 3x3 + bias + BN + GELU, 4 pixels per thread.
// WHICH 0 additionally accumulates the per-(b,c) sum into g_pool (block lies
// entirely within one (b,c): 256 thr x 4 px = 1024 px, 16 blocks/channel).
// ---------------------------------------------------------------------------
template<int WHICH>
__global__ __launch_bounds__(256) void dwconv_bn_gelu_kernel(
    const float* __restrict__ xin,
    const float* __restrict__ wdw,
    const float* __restrict__ bdw,
    const float* __restrict__ gbn,
    const float* __restrict__ bebn)
{
    const int idx = blockIdx.x * 256 + threadIdx.x;
    const int w0 = (idx & 31) * 4;
    const int h  = (idx >> 5) & 127;
    const int bc = idx >> 12;
    const int c  = bc % CCH;

    const float* in  = (WHICH == 0) ? xin : g_fuimg;
    float*       out = (WHICH == 0) ? g_conv1 : g_conv2;

    const float* p = in + (size_t)bc * LTOK;
    float wk[9];
#pragma unroll
    for (int i = 0; i < 9; i++) wk[i] = wdw[c * 9 + i];

    float o0 = 0.f, o1 = 0.f, o2 = 0.f, o3 = 0.f;
#pragma unroll
    for (int r = 0; r < 3; r++) {
        const int hh = h - 1 + r;
        if (hh < 0 || hh >= HDIM) continue;
        const float* row = p + hh * WDIM;
        const float4 cc = *(const float4*)(row + w0);
        const float lf = (w0 > 0)   ? row[w0 - 1] : 0.0f;
        const float rt = (w0 < 124) ? row[w0 + 4] : 0.0f;
        const float k0 = wk[r*3+0], k1 = wk[r*3+1], k2 = wk[r*3+2];
        o0 = fmaf(k0, lf,   fmaf(k1, cc.x, fmaf(k2, cc.y, o0)));
        o1 = fmaf(k0, cc.x, fmaf(k1, cc.y, fmaf(k2, cc.z, o1)));
        o2 = fmaf(k0, cc.y, fmaf(k1, cc.z, fmaf(k2, cc.w, o2)));
        o3 = fmaf(k0, cc.z, fmaf(k1, cc.w, fmaf(k2, rt,   o3)));
    }
    const float bni = rsqrtf(1.0f + 1e-5f);
    const float sc = gbn[c] * bni, bb = bebn[c], bs = bdw[c];
    float4 o;
    o.x = gelu_erf((o0 + bs) * sc + bb);
    o.y = gelu_erf((o1 + bs) * sc + bb);
    o.z = gelu_erf((o2 + bs) * sc + bb);
    o.w = gelu_erf((o3 + bs) * sc + bb);
    *(float4*)(out + (size_t)idx * 4) = o;

    if (WHICH == 0) {
        // block-level sum of the 1024 outputs -> one atomicAdd per block
        float s = o.x + o.y + o.z + o.w;
#pragma unroll
        for (int off = 16; off > 0; off >>= 1)
            s += __shfl_xor_sync(0xffffffffu, s, off);
        __shared__ float red[8];
        if ((threadIdx.x & 31) == 0) red[threadIdx.x >> 5] = s;
        __syncthreads();
        if (threadIdx.x == 0) {
            float tot = 0.0f;
#pragma unroll
            for (int i = 0; i < 8; i++) tot += red[i];
            atomicAdd(&g_pool[bc], tot);
        }
    }
}

// ---------------------------------------------------------------------------
// Spatial interaction map -> g_sgate
// ---------------------------------------------------------------------------
__global__ __launch_bounds__(128) void spatial_kernel(
    const float* __restrict__ w_si1, const float* __restrict__ b_si1,
    const float* __restrict__ g_si,  const float* __restrict__ be_si,
    const float* __restrict__ w_si2, const float* __restrict__ b_si2)
{
    __shared__ float wsm[CCH * C8];   // [c][o]
    for (int i = threadIdx.x; i < CCH * C8; i += 128)
        wsm[i] = w_si1[(i % C8) * CCH + (i / C8)];
    __syncthreads();

    const int pid = blockIdx.x * 128 + threadIdx.x;
    const int b  = pid / LTOK;
    const int hw = pid % LTOK;

    float t[C8];
#pragma unroll
    for (int o = 0; o < C8; o++) t[o] = 0.0f;

    const float* base = g_conv1 + (size_t)b * CCH * LTOK + hw;
    for (int c = 0; c < CCH; c++) {
        const float v = base[(size_t)c * LTOK];
        const float* wr = &wsm[c * C8];
#pragma unroll
        for (int o = 0; o < C8; o++) t[o] = fmaf(wr[o], v, t[o]);
    }

    const float bni = rsqrtf(1.0f + 1e-5f);
    float s = b_si2[0];
#pragma unroll
    for (int o = 0; o < C8; o++) {
        float u = (t[o] + b_si1[o]) * (g_si[o] * bni) + be_si[o];
        s = fmaf(w_si2[o], gelu_erf(u), s);
    }
    g_sgate[pid] = 1.0f + sigmoidf_(s);
}

// ---------------------------------------------------------------------------
// Channel interaction -> g_cgate (g_pool now holds SUM; scale by 1/LTOK)
// ---------------------------------------------------------------------------
__global__ __launch_bounds__(192) void channel_kernel(
    const float* __restrict__ w_ci1, const float* __restrict__ b_ci1,
    const float* __restrict__ g_ci,  const float* __restrict__ be_ci,
    const float* __restrict__ w_ci2, const float* __restrict__ b_ci2)
{
    const int b = blockIdx.x;
    __shared__ float t[C8];
    const float bni = rsqrtf(1.0f + 1e-5f);
    const float inv = 1.0f / LTOK;
    if (threadIdx.x < C8) {
        const int o = threadIdx.x;
        float s = b_ci1[o];
        for (int c = 0; c < CCH; c++)
            s = fmaf(w_ci1[o * CCH + c], g_pool[b * CCH + c] * inv, s);
        s = s * (g_ci[o] * bni) + be_ci[o];
        t[o] = gelu_erf(s);
    }
    __syncthreads();
    const int c = threadIdx.x;
    float s = b_ci2[c];
#pragma unroll
    for (int o = 0; o < C8; o++) s = fmaf(w_ci2[c * C8 + o], t[o], s);
    g_cgate[b * CCH + c] = 1.0f + sigmoidf_(s);
}

// ---------------------------------------------------------------------------
// kernel_launch
// ---------------------------------------------------------------------------
extern "C" void kernel_launch(void* const* d_in, const int* in_sizes, int n_in,
                              void* d_out, int out_size)
{
    const float* x      = (const float*)d_in[0];
    const float* w_qkv  = (const float*)d_in[1];
    const float* b_qkv  = (const float*)d_in[2];
    const float* w_dw1  = (const float*)d_in[3];
    const float* b_dw1  = (const float*)d_in[4];
    const float* gbn1   = (const float*)d_in[5];
    const float* bebn1  = (const float*)d_in[6];
    const float* w_si1  = (const float*)d_in[7];
    const float* b_si1  = (const float*)d_in[8];
    const float* g_si   = (const float*)d_in[9];
    const float* be_si  = (const float*)d_in[10];
    const float* w_si2  = (const float*)d_in[11];
    const float* b_si2  = (const float*)d_in[12];
    const float* w_ci1  = (const float*)d_in[13];
    const float* b_ci1  = (const float*)d_in[14];
    const float* g_ci   = (const float*)d_in[15];
    const float* be_ci  = (const float*)d_in[16];
    const float* w_ci2  = (const float*)d_in[17];
    const float* b_ci2  = (const float*)d_in[18];
    const float* w_dw2  = (const float*)d_in[19];
    const float* b_dw2  = (const float*)d_in[20];
    const float* gbn2   = (const float*)d_in[21];
    const float* bebn2  = (const float*)d_in[22];
    const float* w_proj = (const float*)d_in[23];
    const float* b_proj = (const float*)d_in[24];
    float* out = (float*)d_out;

    cudaFuncSetAttribute(attn_mma_kernel<8, 16, 0>,
                         cudaFuncAttributeMaxDynamicSharedMemorySize, ATT_SMEM);
    cudaFuncSetAttribute(attn_mma_kernel<16, 8, 96>,
                         cudaFuncAttributeMaxDynamicSharedMemorySize, ATT_SMEM);

    // 0) qkv = x @ w_qkv + b_qkv (A transposed in the loader — no xpose kernel)
    mma_gemm_kernel<0, 3 * CCH><<<dim3((3 * CCH) / 96, MTOT / 128), 192>>>(
        x, w_qkv, b_qkv, nullptr);

    // 1) conv path (mean fused into dwconv<0> via atomics)
    zero_pool_kernel<<<(BSZ * CCH + 255) / 256, 256>>>();
    dwconv_bn_gelu_kernel<0><<<(MTOT * CCH) / 1024, 256>>>(x, w_dw1, b_dw1, gbn1, bebn1);
    spatial_kernel<<<MTOT / 128, 128>>>(w_si1, b_si1, g_si, be_si, w_si2, b_si2);
    channel_kernel<<<BSZ, CCH>>>(w_ci1, b_ci1, g_ci, be_ci, w_ci2, b_ci2);

    // 2) attention (gate + transpose fused) -> g_fuimg (NCHW)
    attn_mma_kernel<8, 16, 0 ><<<BSZ * (HDIM / 8) * (WDIM / 16) * 3, 256, ATT_SMEM>>>();
    attn_mma_kernel<16, 8, 96><<<BSZ * (HDIM / 16) * (WDIM / 8) * 3, 256, ATT_SMEM>>>();

    // 3) conv2 -> g_conv2
    dwconv_bn_gelu_kernel<1><<<(MTOT * CCH) / 1024, 256>>>(nullptr, w_dw2, b_dw2, gbn2, bebn2);

    // 4) out = (channel-gated conv2) @ w_proj + b_proj
    mma_gemm_kernel<1, CCH><<<dim3(CCH / 96, MTOT / 128), 192>>>(
        nullptr, w_proj, b_proj, out);
}

// round 11
// speedup vs baseline: 2.0486x; 1.0623x over previous
#include <cuda_runtime.h>
#include <math.h>
#include <stdint.h>

// ---------------------------------------------------------------------------
// Problem constants
// ---------------------------------------------------------------------------
#define BSZ   8
#define HDIM  128
#define WDIM  128
#define CCH   192
#define LTOK  16384
#define C8    24
#define MTOT  (BSZ * LTOK)   // 131072

static __device__ __forceinline__ float gelu_erf(float x) {
    return 0.5f * x * (1.0f + erff(x * 0.70710678118654752f));
}
static __device__ __forceinline__ float sigmoidf_(float x) {
    return 1.0f / (1.0f + expf(-x));
}
static __device__ __forceinline__ uint32_t f2tf32(float x) {
    uint32_t r;
    asm("cvt.rna.tf32.f32 %0, %1;" : "=r"(r) : "f"(x));
    return r;
}

// m16n8k8 tf32 tensor-core MMA (proven layout)
static __device__ __forceinline__ void mma_tf32(
    float* c, const uint32_t* a, const uint32_t* b)
{
    asm volatile(
        "mma.sync.aligned.m16n8k8.row.col.f32.tf32.tf32.f32 "
        "{%0,%1,%2,%3}, {%4,%5,%6,%7}, {%8,%9}, {%0,%1,%2,%3};\n"
        : "+f"(c[0]), "+f"(c[1]), "+f"(c[2]), "+f"(c[3])
        : "r"(a[0]), "r"(a[1]), "r"(a[2]), "r"(a[3]),
          "r"(b[0]), "r"(b[1]));
}

// ---------------------------------------------------------------------------
// Device scratch
// ---------------------------------------------------------------------------
__device__ float g_qkv [MTOT * 3 * CCH];   // (B,L,3C)
__device__ float g_conv1[MTOT * CCH];      // (B,C,H,W)
__device__ float g_fuimg[MTOT * CCH];      // (B,C,H,W) gated attn out (NCHW)
__device__ float g_conv2[MTOT * CCH];      // (B,C,H,W)
__device__ float g_sgate[MTOT];
__device__ float g_pool [BSZ * CCH];       // SUM over H*W (scaled in channel_kernel)
__device__ float g_cgate[BSZ * CCH];

// ---------------------------------------------------------------------------
// GEMM via mma.sync tf32 (proven, unchanged from R10)
// ---------------------------------------------------------------------------
#define APAD 136
#define BPAD 104

template<int MODE, int NFULL>
__global__ __launch_bounds__(192) void mma_gemm_kernel(
    const float* __restrict__ Ain,
    const float* __restrict__ Bw,
    const float* __restrict__ bias,
    float* __restrict__ Cout)
{
    __shared__ uint32_t As[16][APAD];
    __shared__ uint32_t Bs[16][BPAD];

    const int tid  = threadIdx.x;
    const int wid  = tid >> 5;
    const int lane = tid & 31;
    const int gid  = lane >> 2;
    const int tig  = lane & 3;
    const int warp_m = wid & 1;
    const int warp_n = wid >> 1;

    const int n0 = blockIdx.x * 96;
    const int m0 = blockIdx.y * 128;
    const int bb = m0 / LTOK;
    const int lb = m0 % LTOK;

    float* __restrict__ outp = (MODE == 0) ? g_qkv : Cout;

    float acc[4][4][4];
#pragma unroll
    for (int mt = 0; mt < 4; mt++)
#pragma unroll
        for (int nt = 0; nt < 4; nt++)
#pragma unroll
            for (int v = 0; v < 4; v++) acc[mt][nt][v] = 0.0f;

    for (int kt = 0; kt < CCH; kt += 16) {
        __syncthreads();
        // ---- A tile ----
        if (MODE == 0) {
#pragma unroll
            for (int it = 0; it < 3; it++) {
                const int lin = tid + it * 192;
                if (lin < 512) {
                    const int row = lin >> 2;
                    const int q   = (lin & 3) * 4;
                    const float4 v = *(const float4*)(Ain + (size_t)(m0 + row) * CCH + kt + q);
                    As[q + 0][row] = f2tf32(v.x);
                    As[q + 1][row] = f2tf32(v.y);
                    As[q + 2][row] = f2tf32(v.z);
                    As[q + 3][row] = f2tf32(v.w);
                }
            }
        } else {
#pragma unroll
            for (int it = 0; it < 3; it++) {
                const int lin = tid + it * 192;
                if (lin < 512) {
                    const int k  = lin >> 5;
                    const int mq = (lin & 31) << 2;
                    float4 v = *(const float4*)(g_conv2 + (size_t)bb * CCH * LTOK
                                                + (size_t)(kt + k) * LTOK + lb + mq);
                    const float g = g_cgate[bb * CCH + kt + k];
                    uint4 t;
                    t.x = f2tf32(v.x * g); t.y = f2tf32(v.y * g);
                    t.z = f2tf32(v.z * g); t.w = f2tf32(v.w * g);
                    *(uint4*)&As[k][mq] = t;
                }
            }
        }
        // ---- B tile ----
#pragma unroll
        for (int it = 0; it < 2; it++) {
            const int lin = tid + it * 192;
            const int k   = lin / 24;
            const int nq  = (lin % 24) << 2;
            float4 v = *(const float4*)(Bw + (size_t)(kt + k) * NFULL + n0 + nq);
            uint4 t;
            t.x = f2tf32(v.x); t.y = f2tf32(v.y);
            t.z = f2tf32(v.z); t.w = f2tf32(v.w);
            *(uint4*)&Bs[k][nq] = t;
        }
        __syncthreads();

#pragma unroll
        for (int ks = 0; ks < 2; ks++) {
            const int kr = ks * 8;
            uint32_t af[4][4];
#pragma unroll
            for (int mt = 0; mt < 4; mt++) {
                const int mr = warp_m * 64 + mt * 16;
                af[mt][0] = As[kr + tig    ][mr + gid];
                af[mt][1] = As[kr + tig    ][mr + gid + 8];
                af[mt][2] = As[kr + tig + 4][mr + gid];
                af[mt][3] = As[kr + tig + 4][mr + gid + 8];
            }
            uint32_t bf[4][2];
#pragma unroll
            for (int nt = 0; nt < 4; nt++) {
                const int nb = warp_n * 32 + nt * 8;
                bf[nt][0] = Bs[kr + tig    ][nb + gid];
                bf[nt][1] = Bs[kr + tig + 4][nb + gid];
            }
#pragma unroll
            for (int mt = 0; mt < 4; mt++)
#pragma unroll
                for (int nt = 0; nt < 4; nt++)
                    mma_tf32(acc[mt][nt], af[mt], bf[nt]);
        }
    }

#pragma unroll
    for (int mt = 0; mt < 4; mt++) {
        const int r0 = m0 + warp_m * 64 + mt * 16 + gid;
#pragma unroll
        for (int nt = 0; nt < 4; nt++) {
            const int col = n0 + warp_n * 32 + nt * 8 + tig * 2;
            const float bx = bias[col], by = bias[col + 1];
            float2 v0 = { acc[mt][nt][0] + bx, acc[mt][nt][1] + by };
            float2 v1 = { acc[mt][nt][2] + bx, acc[mt][nt][3] + by };
            *(float2*)(outp + (size_t)r0 * NFULL + col) = v0;
            *(float2*)(outp + (size_t)(r0 + 8) * NFULL + col) = v1;
        }
    }
}

// ---------------------------------------------------------------------------
// Windowed attention — R9/R10-proven body (unchanged)
// ---------------------------------------------------------------------------
#define ATT_SMEM 102912

template<int HS, int WS, int COFF>
__global__ __launch_bounds__(256) void attn_mma_kernel()
{
    extern __shared__ char sm[];
    float*    Ssm  = (float*)sm;                    // [128][132]
    uint32_t* Su   = (uint32_t*)sm;
    float*    rsum = (float*)(sm + 67584);
    uint32_t* Qs   = (uint32_t*)(sm + 68096);       // [32][136]
    uint32_t* Ks   = Qs + 32 * 136;
    uint32_t* Vs   = (uint32_t*)(sm + 68096);       // [128][40]
    float*    Os   = (float*)(sm + 68096);          // [128][33]

    constexpr int WWn = WDIM / WS;
    constexpr int WH  = HDIM / HS;
    constexpr float SCALE3 = 3.0f * 0.17677669529663688f;   // 3/sqrt(32)

    int bid = blockIdx.x;
    const int head = bid % 3; bid /= 3;
    const int ww = bid % WWn; bid /= WWn;
    const int wh = bid % WH;  bid /= WH;
    const int b  = bid;
    const int co = COFF + head * 32;

    const int t    = threadIdx.x;
    const int wid  = t >> 5;        // 0..7
    const int lane = t & 31;
    const int gid  = lane >> 2;     // 0..7
    const int tig  = lane & 3;      // 0..3

    const int sL = t >> 2;          // 0..63
    const int d0 = (t & 3) * 8;

    // ---- Phase 0: Q,K -> smem [dim][token] tf32 ----
#pragma unroll
    for (int p = 0; p < 2; p++) {
        const int ts = p * 64 + sL;
        const int l  = (wh * HS + ts / WS) * WDIM + ww * WS + ts % WS;
        const float* qb = g_qkv + ((size_t)b * LTOK + l) * (3 * CCH) + co;
        const float* kb = qb + CCH;
        const float4 q0 = *(const float4*)(qb + d0);
        const float4 q1 = *(const float4*)(qb + d0 + 4);
        const float4 k0 = *(const float4*)(kb + d0);
        const float4 k1 = *(const float4*)(kb + d0 + 4);
        const float qa[8] = {q0.x,q0.y,q0.z,q0.w,q1.x,q1.y,q1.z,q1.w};
        const float ka[8] = {k0.x,k0.y,k0.z,k0.w,k1.x,k1.y,k1.z,k1.w};
#pragma unroll
        for (int j = 0; j < 8; j++) {
            Qs[(d0 + j) * 136 + ts] = f2tf32(qa[j]);
            Ks[(d0 + j) * 136 + ts] = f2tf32(ka[j]);
        }
    }
    __syncthreads();

    // ---- Phase 1: S rows wid*16..+15 ----
    {
        const int mrb = wid * 16;
#pragma unroll
        for (int nc = 0; nc < 4; nc++) {
            float acc[4][4] = {};
#pragma unroll
            for (int ks = 0; ks < 4; ks++) {
                const int kr = ks * 8;
                uint32_t af[4];
                af[0] = Qs[(kr + tig    ) * 136 + mrb + gid];
                af[1] = Qs[(kr + tig    ) * 136 + mrb + gid + 8];
                af[2] = Qs[(kr + tig + 4) * 136 + mrb + gid];
                af[3] = Qs[(kr + tig + 4) * 136 + mrb + gid + 8];
                uint32_t bf[4][2];
#pragma unroll
                for (int nt = 0; nt < 4; nt++) {
                    const int nb = nc * 32 + nt * 8;
                    bf[nt][0] = Ks[(kr + tig    ) * 136 + nb + gid];
                    bf[nt][1] = Ks[(kr + tig + 4) * 136 + nb + gid];
                }
#pragma unroll
                for (int nt = 0; nt < 4; nt++)
                    mma_tf32(acc[nt], af, bf[nt]);
            }
            const int r0 = mrb + gid;
#pragma unroll
            for (int nt = 0; nt < 4; nt++) {
                const int col = nc * 32 + nt * 8 + tig * 2;
                Ssm[r0 * 132 + col]           = acc[nt][0] * SCALE3;
                Ssm[r0 * 132 + col + 1]       = acc[nt][1] * SCALE3;
                Ssm[(r0 + 8) * 132 + col]     = acc[nt][2] * SCALE3;
                Ssm[(r0 + 8) * 132 + col + 1] = acc[nt][3] * SCALE3;
            }
        }
    }
    __syncthreads();   // S done; Qs/Ks dead

    // ---- Phase 2a: V -> X region ----
#pragma unroll
    for (int p = 0; p < 2; p++) {
        const int ts = p * 64 + sL;
        const int l  = (wh * HS + ts / WS) * WDIM + ww * WS + ts % WS;
        const float* vb = g_qkv + ((size_t)b * LTOK + l) * (3 * CCH) + 2 * CCH + co;
        const float4 v0 = *(const float4*)(vb + d0);
        const float4 v1 = *(const float4*)(vb + d0 + 4);
        uint4 t0, t1;
        t0.x = f2tf32(v0.x); t0.y = f2tf32(v0.y); t0.z = f2tf32(v0.z); t0.w = f2tf32(v0.w);
        t1.x = f2tf32(v1.x); t1.y = f2tf32(v1.y); t1.z = f2tf32(v1.z); t1.w = f2tf32(v1.w);
        *(uint4*)(Vs + ts * 40 + d0)     = t0;
        *(uint4*)(Vs + ts * 40 + d0 + 4) = t1;
    }

    // ---- Phase 2b: quad-per-row softmax on own 16 rows (gate folded) ----
#pragma unroll
    for (int i = 0; i < 2; i++) {
        const int r = wid * 16 + i * 8 + gid;
        float v[32];
#pragma unroll
        for (int jj = 0; jj < 32; jj++) v[jj] = Ssm[r * 132 + tig + 4 * jj];
        float mx = v[0];
#pragma unroll
        for (int jj = 1; jj < 32; jj++) mx = fmaxf(mx, v[jj]);
        mx = fmaxf(mx, __shfl_xor_sync(~0u, mx, 1));
        mx = fmaxf(mx, __shfl_xor_sync(~0u, mx, 2));
        float s = 0.0f;
#pragma unroll
        for (int jj = 0; jj < 32; jj++) {
            const float e = __expf(v[jj] - mx);
            s += e;
            Su[r * 132 + tig + 4 * jj] = f2tf32(e);
        }
        s += __shfl_xor_sync(~0u, s, 1);
        s += __shfl_xor_sync(~0u, s, 2);
        if (tig == 0) {
            const int lr = (wh * HS + r / WS) * WDIM + ww * WS + r % WS;
            rsum[r] = 3.0f * g_sgate[b * LTOK + lr] / s;
        }
    }
    __syncthreads();

    // ---- Phase 3: O^T = V^T P^T ; warp w -> N rows w*16..+15 ----
    {
        const int nbb = wid * 16;
        float acc[2][2][4] = {};
#pragma unroll
        for (int ks = 0; ks < 16; ks++) {
            const int kr = ks * 8;
            uint32_t af[2][4];
#pragma unroll
            for (int mt = 0; mt < 2; mt++) {
                const int mr = mt * 16;
                af[mt][0] = Vs[(kr + tig    ) * 40 + mr + gid];
                af[mt][1] = Vs[(kr + tig    ) * 40 + mr + gid + 8];
                af[mt][2] = Vs[(kr + tig + 4) * 40 + mr + gid];
                af[mt][3] = Vs[(kr + tig + 4) * 40 + mr + gid + 8];
            }
            uint32_t bf[2][2];
#pragma unroll
            for (int nt = 0; nt < 2; nt++) {
                const int nb = nbb + nt * 8;
                bf[nt][0] = Su[(nb + gid) * 132 + kr + tig];
                bf[nt][1] = Su[(nb + gid) * 132 + kr + tig + 4];
            }
#pragma unroll
            for (int mt = 0; mt < 2; mt++)
#pragma unroll
                for (int nt = 0; nt < 2; nt++)
                    mma_tf32(acc[mt][nt], af[mt], bf[nt]);
        }
        __syncthreads();   // Vs dead before Os overwrite

#pragma unroll
        for (int mt = 0; mt < 2; mt++) {
            const int dim0 = mt * 16 + gid;
#pragma unroll
            for (int nt = 0; nt < 2; nt++) {
                const int r = nbb + nt * 8 + tig * 2;
                const float s0 = rsum[r], s1 = rsum[r + 1];
                Os[r * 33 + dim0]           = acc[mt][nt][0] * s0;
                Os[(r + 1) * 33 + dim0]     = acc[mt][nt][1] * s1;
                Os[r * 33 + dim0 + 8]       = acc[mt][nt][2] * s0;
                Os[(r + 1) * 33 + dim0 + 8] = acc[mt][nt][3] * s1;
            }
        }
    }
    __syncthreads();

    // ---- Phase 4: transposed NCHW writeout (warp-per-channel-slice) ----
#pragma unroll
    for (int cc = 0; cc < 4; cc++) {
        const int c = wid * 4 + cc;
        float* cbase = g_fuimg + ((size_t)b * CCH + co + c) * LTOK;
#pragma unroll
        for (int rp = 0; rp < 4; rp++) {
            const int ts = rp * 32 + lane;
            const int l  = (wh * HS + ts / WS) * WDIM + ww * WS + ts % WS;
            cbase[l] = Os[ts * 33 + c];
        }
    }
}

// ---------------------------------------------------------------------------
// zero g_pool
// ---------------------------------------------------------------------------
__global__ void zero_pool_kernel()
{
    const int i = blockIdx.x * 256 + threadIdx.x;
    if (i < BSZ * CCH) g_pool[i] = 0.0f;
}

// ---------------------------------------------------------------------------
// Depthwise 3x3 + bias + BN + GELU, 4 pixels per thread (R10-proven).
// WHICH 0 accumulates per-(b,c) sum into g_pool.
// ---------------------------------------------------------------------------
template<int WHICH>
__global__ __launch_bounds__(256) void dwconv_bn_gelu_kernel(
    const float* __restrict__ xin,
    const float* __restrict__ wdw,
    const float* __restrict__ bdw,
    const float* __restrict__ gbn,
    const float* __restrict__ bebn)
{
    const int idx = blockIdx.x * 256 + threadIdx.x;
    const int w0 = (idx & 31) * 4;
    const int h  = (idx >> 5) & 127;
    const int bc = idx >> 12;
    const int c  = bc % CCH;

    const float* in  = (WHICH == 0) ? xin : g_fuimg;
    float*       out = (WHICH == 0) ? g_conv1 : g_conv2;

    const float* p = in + (size_t)bc * LTOK;
    float wk[9];
#pragma unroll
    for (int i = 0; i < 9; i++) wk[i] = wdw[c * 9 + i];

    float o0 = 0.f, o1 = 0.f, o2 = 0.f, o3 = 0.f;
#pragma unroll
    for (int r = 0; r < 3; r++) {
        const int hh = h - 1 + r;
        if (hh < 0 || hh >= HDIM) continue;
        const float* row = p + hh * WDIM;
        const float4 cc = *(const float4*)(row + w0);
        const float lf = (w0 > 0)   ? row[w0 - 1] : 0.0f;
        const float rt = (w0 < 124) ? row[w0 + 4] : 0.0f;
        const float k0 = wk[r*3+0], k1 = wk[r*3+1], k2 = wk[r*3+2];
        o0 = fmaf(k0, lf,   fmaf(k1, cc.x, fmaf(k2, cc.y, o0)));
        o1 = fmaf(k0, cc.x, fmaf(k1, cc.y, fmaf(k2, cc.z, o1)));
        o2 = fmaf(k0, cc.y, fmaf(k1, cc.z, fmaf(k2, cc.w, o2)));
        o3 = fmaf(k0, cc.z, fmaf(k1, cc.w, fmaf(k2, rt,   o3)));
    }
    const float bni = rsqrtf(1.0f + 1e-5f);
    const float sc = gbn[c] * bni, bb = bebn[c], bs = bdw[c];
    float4 o;
    o.x = gelu_erf((o0 + bs) * sc + bb);
    o.y = gelu_erf((o1 + bs) * sc + bb);
    o.z = gelu_erf((o2 + bs) * sc + bb);
    o.w = gelu_erf((o3 + bs) * sc + bb);
    *(float4*)(out + (size_t)idx * 4) = o;

    if (WHICH == 0) {
        float s = o.x + o.y + o.z + o.w;
#pragma unroll
        for (int off = 16; off > 0; off >>= 1)
            s += __shfl_xor_sync(0xffffffffu, s, off);
        __shared__ float red[8];
        if ((threadIdx.x & 31) == 0) red[threadIdx.x >> 5] = s;
        __syncthreads();
        if (threadIdx.x == 0) {
            float tot = 0.0f;
#pragma unroll
            for (int i = 0; i < 8; i++) tot += red[i];
            atomicAdd(&g_pool[bc], tot);
        }
    }
}

// ---------------------------------------------------------------------------
// Spatial interaction -> g_sgate.  REWRITTEN for FMA-issue efficiency:
// 2 pixels/thread (float2 LDG per c), float4 LDS on weights.
// ---------------------------------------------------------------------------
__global__ __launch_bounds__(256) void spatial_kernel(
    const float* __restrict__ w_si1, const float* __restrict__ b_si1,
    const float* __restrict__ g_si,  const float* __restrict__ be_si,
    const float* __restrict__ w_si2, const float* __restrict__ b_si2)
{
    __shared__ float wsm[CCH * C8];   // [c][o], 96 B per c-row (16B aligned)
    for (int i = threadIdx.x; i < CCH * C8; i += 256)
        wsm[i] = w_si1[(i % C8) * CCH + (i / C8)];
    __syncthreads();

    const int pid = (blockIdx.x * 256 + threadIdx.x) * 2;   // even
    const int b  = pid / LTOK;
    const int hw = pid % LTOK;

    float t0[C8], t1[C8];
#pragma unroll
    for (int o = 0; o < C8; o++) { t0[o] = 0.0f; t1[o] = 0.0f; }

    const float* base = g_conv1 + (size_t)b * CCH * LTOK + hw;
#pragma unroll 4
    for (int c = 0; c < CCH; c++) {
        const float2 v = *(const float2*)(base + (size_t)c * LTOK);
        const float4* wr = (const float4*)&wsm[c * C8];
#pragma unroll
        for (int o4 = 0; o4 < 6; o4++) {
            const float4 w = wr[o4];
            t0[o4*4+0] = fmaf(w.x, v.x, t0[o4*4+0]);
            t0[o4*4+1] = fmaf(w.y, v.x, t0[o4*4+1]);
            t0[o4*4+2] = fmaf(w.z, v.x, t0[o4*4+2]);
            t0[o4*4+3] = fmaf(w.w, v.x, t0[o4*4+3]);
            t1[o4*4+0] = fmaf(w.x, v.y, t1[o4*4+0]);
            t1[o4*4+1] = fmaf(w.y, v.y, t1[o4*4+1]);
            t1[o4*4+2] = fmaf(w.z, v.y, t1[o4*4+2]);
            t1[o4*4+3] = fmaf(w.w, v.y, t1[o4*4+3]);
        }
    }

    const float bni = rsqrtf(1.0f + 1e-5f);
    float s0 = b_si2[0], s1 = s0;
#pragma unroll
    for (int o = 0; o < C8; o++) {
        const float gb = g_si[o] * bni, be = be_si[o], bi = b_si1[o], w2 = w_si2[o];
        s0 = fmaf(w2, gelu_erf((t0[o] + bi) * gb + be), s0);
        s1 = fmaf(w2, gelu_erf((t1[o] + bi) * gb + be), s1);
    }
    g_sgate[pid]     = 1.0f + sigmoidf_(s0);
    g_sgate[pid + 1] = 1.0f + sigmoidf_(s1);
}

// ---------------------------------------------------------------------------
// Channel interaction -> g_cgate (g_pool holds SUM; scale by 1/LTOK)
// ---------------------------------------------------------------------------
__global__ __launch_bounds__(192) void channel_kernel(
    const float* __restrict__ w_ci1, const float* __restrict__ b_ci1,
    const float* __restrict__ g_ci,  const float* __restrict__ be_ci,
    const float* __restrict__ w_ci2, const float* __restrict__ b_ci2)
{
    const int b = blockIdx.x;
    __shared__ float t[C8];
    const float bni = rsqrtf(1.0f + 1e-5f);
    const float inv = 1.0f / LTOK;
    if (threadIdx.x < C8) {
        const int o = threadIdx.x;
        float s = b_ci1[o];
        for (int c = 0; c < CCH; c++)
            s = fmaf(w_ci1[o * CCH + c], g_pool[b * CCH + c] * inv, s);
        s = s * (g_ci[o] * bni) + be_ci[o];
        t[o] = gelu_erf(s);
    }
    __syncthreads();
    const int c = threadIdx.x;
    float s = b_ci2[c];
#pragma unroll
    for (int o = 0; o < C8; o++) s = fmaf(w_ci2[c * C8 + o], t[o], s);
    g_cgate[b * CCH + c] = 1.0f + sigmoidf_(s);
}

// ---------------------------------------------------------------------------
// kernel_launch
// ---------------------------------------------------------------------------
extern "C" void kernel_launch(void* const* d_in, const int* in_sizes, int n_in,
                              void* d_out, int out_size)
{
    const float* x      = (const float*)d_in[0];
    const float* w_qkv  = (const float*)d_in[1];
    const float* b_qkv  = (const float*)d_in[2];
    const float* w_dw1  = (const float*)d_in[3];
    const float* b_dw1  = (const float*)d_in[4];
    const float* gbn1   = (const float*)d_in[5];
    const float* bebn1  = (const float*)d_in[6];
    const float* w_si1  = (const float*)d_in[7];
    const float* b_si1  = (const float*)d_in[8];
    const float* g_si   = (const float*)d_in[9];
    const float* be_si  = (const float*)d_in[10];
    const float* w_si2  = (const float*)d_in[11];
    const float* b_si2  = (const float*)d_in[12];
    const float* w_ci1  = (const float*)d_in[13];
    const float* b_ci1  = (const float*)d_in[14];
    const float* g_ci   = (const float*)d_in[15];
    const float* be_ci  = (const float*)d_in[16];
    const float* w_ci2  = (const float*)d_in[17];
    const float* b_ci2  = (const float*)d_in[18];
    const float* w_dw2  = (const float*)d_in[19];
    const float* b_dw2  = (const float*)d_in[20];
    const float* gbn2   = (const float*)d_in[21];
    const float* bebn2  = (const float*)d_in[22];
    const float* w_proj = (const float*)d_in[23];
    const float* b_proj = (const float*)d_in[24];
    float* out = (float*)d_out;

    cudaFuncSetAttribute(attn_mma_kernel<8, 16, 0>,
                         cudaFuncAttributeMaxDynamicSharedMemorySize, ATT_SMEM);
    cudaFuncSetAttribute(attn_mma_kernel<16, 8, 96>,
                         cudaFuncAttributeMaxDynamicSharedMemorySize, ATT_SMEM);

    // 0) qkv = x @ w_qkv + b_qkv
    mma_gemm_kernel<0, 3 * CCH><<<dim3((3 * CCH) / 96, MTOT / 128), 192>>>(
        x, w_qkv, b_qkv, nullptr);

    // 1) conv path (mean fused into dwconv<0>)
    zero_pool_kernel<<<(BSZ * CCH + 255) / 256, 256>>>();
    dwconv_bn_gelu_kernel<0><<<(MTOT * CCH) / 1024, 256>>>(x, w_dw1, b_dw1, gbn1, bebn1);
    spatial_kernel<<<MTOT / 512, 256>>>(w_si1, b_si1, g_si, be_si, w_si2, b_si2);
    channel_kernel<<<BSZ, CCH>>>(w_ci1, b_ci1, g_ci, be_ci, w_ci2, b_ci2);

    // 2) attention (gate + transpose fused) -> g_fuimg (NCHW)
    attn_mma_kernel<8, 16, 0 ><<<BSZ * (HDIM / 8) * (WDIM / 16) * 3, 256, ATT_SMEM>>>();
    attn_mma_kernel<16, 8, 96><<<BSZ * (HDIM / 16) * (WDIM / 8) * 3, 256, ATT_SMEM>>>();

    // 3) conv2 -> g_conv2
    dwconv_bn_gelu_kernel<1><<<(MTOT * CCH) / 1024, 256>>>(nullptr, w_dw2, b_dw2, gbn2, bebn2);

    // 4) out = (channel-gated conv2) @ w_proj + b_proj
    mma_gemm_kernel<1, CCH><<<dim3(CCH / 96, MTOT / 128), 192>>>(
        nullptr, w_proj, b_proj, out);
}

// round 12
// speedup vs baseline: 2.2548x; 1.1006x over previous
#include <cuda_runtime.h>
#include <math.h>
#include <stdint.h>

// ---------------------------------------------------------------------------
// Problem constants
// ---------------------------------------------------------------------------
#define BSZ   8
#define HDIM  128
#define WDIM  128
#define CCH   192
#define LTOK  16384
#define C8    24
#define MTOT  (BSZ * LTOK)   // 131072

static __device__ __forceinline__ float gelu_erf(float x) {
    return 0.5f * x * (1.0f + erff(x * 0.70710678118654752f));
}
static __device__ __forceinline__ float sigmoidf_(float x) {
    return 1.0f / (1.0f + expf(-x));
}
static __device__ __forceinline__ uint32_t f2tf32(float x) {
    uint32_t r;
    asm("cvt.rna.tf32.f32 %0, %1;" : "=r"(r) : "f"(x));
    return r;
}

// m16n8k8 tf32 tensor-core MMA (proven layout)
static __device__ __forceinline__ void mma_tf32(
    float* c, const uint32_t* a, const uint32_t* b)
{
    asm volatile(
        "mma.sync.aligned.m16n8k8.row.col.f32.tf32.tf32.f32 "
        "{%0,%1,%2,%3}, {%4,%5,%6,%7}, {%8,%9}, {%0,%1,%2,%3};\n"
        : "+f"(c[0]), "+f"(c[1]), "+f"(c[2]), "+f"(c[3])
        : "r"(a[0]), "r"(a[1]), "r"(a[2]), "r"(a[3]),
          "r"(b[0]), "r"(b[1]));
}

// ---------------------------------------------------------------------------
// Device scratch
// ---------------------------------------------------------------------------
__device__ float g_qkv [MTOT * 3 * CCH];   // (B,L,3C)
__device__ float g_conv1[MTOT * CCH];      // (B,C,H,W)
__device__ float g_fuimg[MTOT * CCH];      // (B,C,H,W) gated attn out (NCHW)
__device__ float g_conv2[MTOT * CCH];      // (B,C,H,W)
__device__ float g_sgate[MTOT];
__device__ float g_pool [BSZ * CCH];       // SUM over H*W (scaled in channel_kernel)
__device__ float g_cgate[BSZ * CCH];

// ---------------------------------------------------------------------------
// GEMM via mma.sync tf32 — double-buffered software pipeline.
// MODE 0: A = x row-major (transposed in loader); out = g_qkv
// MODE 1: A = g_conv2 k-major * g_cgate; out = Cout
// Fragment addressing / MMA order identical to the proven R4-R11 kernel.
// ---------------------------------------------------------------------------
#define APAD 136
#define BPAD 104

template<int MODE, int NFULL>
__global__ __launch_bounds__(192) void mma_gemm_kernel(
    const float* __restrict__ Ain,
    const float* __restrict__ Bw,
    const float* __restrict__ bias,
    float* __restrict__ Cout)
{
    __shared__ uint32_t As[2][16][APAD];
    __shared__ uint32_t Bs[2][16][BPAD];

    const int tid  = threadIdx.x;
    const int wid  = tid >> 5;
    const int lane = tid & 31;
    const int gid  = lane >> 2;
    const int tig  = lane & 3;
    const int warp_m = wid & 1;
    const int warp_n = wid >> 1;

    const int n0 = blockIdx.x * 96;
    const int m0 = blockIdx.y * 128;
    const int bb = m0 / LTOK;
    const int lb = m0 % LTOK;

    float* __restrict__ outp = (MODE == 0) ? g_qkv : Cout;

    float acc[4][4][4];
#pragma unroll
    for (int mt = 0; mt < 4; mt++)
#pragma unroll
        for (int nt = 0; nt < 4; nt++)
#pragma unroll
            for (int v = 0; v < 4; v++) acc[mt][nt][v] = 0.0f;

    float4 aReg[3];
    float  gReg[3];
    float4 bReg[2];

    auto ldg_tiles = [&](int kt) {
        if (MODE == 0) {
#pragma unroll
            for (int it = 0; it < 3; it++) {
                const int lin = tid + it * 192;
                if (lin < 512) {
                    const int row = lin >> 2;
                    const int q   = (lin & 3) * 4;
                    aReg[it] = *(const float4*)(Ain + (size_t)(m0 + row) * CCH + kt + q);
                }
            }
        } else {
#pragma unroll
            for (int it = 0; it < 3; it++) {
                const int lin = tid + it * 192;
                if (lin < 512) {
                    const int k  = lin >> 5;
                    const int mq = (lin & 31) << 2;
                    aReg[it] = *(const float4*)(g_conv2 + (size_t)bb * CCH * LTOK
                                                + (size_t)(kt + k) * LTOK + lb + mq);
                    gReg[it] = g_cgate[bb * CCH + kt + k];
                }
            }
        }
#pragma unroll
        for (int it = 0; it < 2; it++) {
            const int lin = tid + it * 192;
            const int k   = lin / 24;
            const int nq  = (lin % 24) << 2;
            bReg[it] = *(const float4*)(Bw + (size_t)(kt + k) * NFULL + n0 + nq);
        }
    };

    auto sts_tiles = [&](int buf) {
        if (MODE == 0) {
#pragma unroll
            for (int it = 0; it < 3; it++) {
                const int lin = tid + it * 192;
                if (lin < 512) {
                    const int row = lin >> 2;
                    const int q   = (lin & 3) * 4;
                    As[buf][q + 0][row] = f2tf32(aReg[it].x);
                    As[buf][q + 1][row] = f2tf32(aReg[it].y);
                    As[buf][q + 2][row] = f2tf32(aReg[it].z);
                    As[buf][q + 3][row] = f2tf32(aReg[it].w);
                }
            }
        } else {
#pragma unroll
            for (int it = 0; it < 3; it++) {
                const int lin = tid + it * 192;
                if (lin < 512) {
                    const int k  = lin >> 5;
                    const int mq = (lin & 31) << 2;
                    uint4 t;
                    t.x = f2tf32(aReg[it].x * gReg[it]);
                    t.y = f2tf32(aReg[it].y * gReg[it]);
                    t.z = f2tf32(aReg[it].z * gReg[it]);
                    t.w = f2tf32(aReg[it].w * gReg[it]);
                    *(uint4*)&As[buf][k][mq] = t;
                }
            }
        }
#pragma unroll
        for (int it = 0; it < 2; it++) {
            const int lin = tid + it * 192;
            const int k   = lin / 24;
            const int nq  = (lin % 24) << 2;
            uint4 t;
            t.x = f2tf32(bReg[it].x); t.y = f2tf32(bReg[it].y);
            t.z = f2tf32(bReg[it].z); t.w = f2tf32(bReg[it].w);
            *(uint4*)&Bs[buf][k][nq] = t;
        }
    };

    auto compute = [&](int buf) {
#pragma unroll
        for (int ks = 0; ks < 2; ks++) {
            const int kr = ks * 8;
            uint32_t af[4][4];
#pragma unroll
            for (int mt = 0; mt < 4; mt++) {
                const int mr = warp_m * 64 + mt * 16;
                af[mt][0] = As[buf][kr + tig    ][mr + gid];
                af[mt][1] = As[buf][kr + tig    ][mr + gid + 8];
                af[mt][2] = As[buf][kr + tig + 4][mr + gid];
                af[mt][3] = As[buf][kr + tig + 4][mr + gid + 8];
            }
            uint32_t bf[4][2];
#pragma unroll
            for (int nt = 0; nt < 4; nt++) {
                const int nb = warp_n * 32 + nt * 8;
                bf[nt][0] = Bs[buf][kr + tig    ][nb + gid];
                bf[nt][1] = Bs[buf][kr + tig + 4][nb + gid];
            }
#pragma unroll
            for (int mt = 0; mt < 4; mt++)
#pragma unroll
                for (int nt = 0; nt < 4; nt++)
                    mma_tf32(acc[mt][nt], af[mt], bf[nt]);
        }
    };

    // prologue
    ldg_tiles(0);
    sts_tiles(0);
    __syncthreads();

    for (int t = 0; t < 12; t++) {
        const int cur = t & 1;
        if (t < 11) ldg_tiles((t + 1) * 16);   // LDGs in flight during compute
        compute(cur);
        if (t < 11) sts_tiles(cur ^ 1);        // absorbs LDG scoreboard wait
        __syncthreads();
    }

#pragma unroll
    for (int mt = 0; mt < 4; mt++) {
        const int r0 = m0 + warp_m * 64 + mt * 16 + gid;
#pragma unroll
        for (int nt = 0; nt < 4; nt++) {
            const int col = n0 + warp_n * 32 + nt * 8 + tig * 2;
            const float bx = bias[col], by = bias[col + 1];
            float2 v0 = { acc[mt][nt][0] + bx, acc[mt][nt][1] + by };
            float2 v1 = { acc[mt][nt][2] + bx, acc[mt][nt][3] + by };
            *(float2*)(outp + (size_t)r0 * NFULL + col) = v0;
            *(float2*)(outp + (size_t)(r0 + 8) * NFULL + col) = v1;
        }
    }
}

// ---------------------------------------------------------------------------
// Windowed attention — R9/R10/R11-proven body (unchanged)
// ---------------------------------------------------------------------------
#define ATT_SMEM 102912

template<int HS, int WS, int COFF>
__global__ __launch_bounds__(256) void attn_mma_kernel()
{
    extern __shared__ char sm[];
    float*    Ssm  = (float*)sm;                    // [128][132]
    uint32_t* Su   = (uint32_t*)sm;
    float*    rsum = (float*)(sm + 67584);
    uint32_t* Qs   = (uint32_t*)(sm + 68096);       // [32][136]
    uint32_t* Ks   = Qs + 32 * 136;
    uint32_t* Vs   = (uint32_t*)(sm + 68096);       // [128][40]
    float*    Os   = (float*)(sm + 68096);          // [128][33]

    constexpr int WWn = WDIM / WS;
    constexpr int WH  = HDIM / HS;
    constexpr float SCALE3 = 3.0f * 0.17677669529663688f;   // 3/sqrt(32)

    int bid = blockIdx.x;
    const int head = bid % 3; bid /= 3;
    const int ww = bid % WWn; bid /= WWn;
    const int wh = bid % WH;  bid /= WH;
    const int b  = bid;
    const int co = COFF + head * 32;

    const int t    = threadIdx.x;
    const int wid  = t >> 5;        // 0..7
    const int lane = t & 31;
    const int gid  = lane >> 2;     // 0..7
    const int tig  = lane & 3;      // 0..3

    const int sL = t >> 2;          // 0..63
    const int d0 = (t & 3) * 8;

    // ---- Phase 0: Q,K -> smem [dim][token] tf32 ----
#pragma unroll
    for (int p = 0; p < 2; p++) {
        const int ts = p * 64 + sL;
        const int l  = (wh * HS + ts / WS) * WDIM + ww * WS + ts % WS;
        const float* qb = g_qkv + ((size_t)b * LTOK + l) * (3 * CCH) + co;
        const float* kb = qb + CCH;
        const float4 q0 = *(const float4*)(qb + d0);
        const float4 q1 = *(const float4*)(qb + d0 + 4);
        const float4 k0 = *(const float4*)(kb + d0);
        const float4 k1 = *(const float4*)(kb + d0 + 4);
        const float qa[8] = {q0.x,q0.y,q0.z,q0.w,q1.x,q1.y,q1.z,q1.w};
        const float ka[8] = {k0.x,k0.y,k0.z,k0.w,k1.x,k1.y,k1.z,k1.w};
#pragma unroll
        for (int j = 0; j < 8; j++) {
            Qs[(d0 + j) * 136 + ts] = f2tf32(qa[j]);
            Ks[(d0 + j) * 136 + ts] = f2tf32(ka[j]);
        }
    }
    __syncthreads();

    // ---- Phase 1: S rows wid*16..+15 ----
    {
        const int mrb = wid * 16;
#pragma unroll
        for (int nc = 0; nc < 4; nc++) {
            float acc[4][4] = {};
#pragma unroll
            for (int ks = 0; ks < 4; ks++) {
                const int kr = ks * 8;
                uint32_t af[4];
                af[0] = Qs[(kr + tig    ) * 136 + mrb + gid];
                af[1] = Qs[(kr + tig    ) * 136 + mrb + gid + 8];
                af[2] = Qs[(kr + tig + 4) * 136 + mrb + gid];
                af[3] = Qs[(kr + tig + 4) * 136 + mrb + gid + 8];
                uint32_t bf[4][2];
#pragma unroll
                for (int nt = 0; nt < 4; nt++) {
                    const int nb = nc * 32 + nt * 8;
                    bf[nt][0] = Ks[(kr + tig    ) * 136 + nb + gid];
                    bf[nt][1] = Ks[(kr + tig + 4) * 136 + nb + gid];
                }
#pragma unroll
                for (int nt = 0; nt < 4; nt++)
                    mma_tf32(acc[nt], af, bf[nt]);
            }
            const int r0 = mrb + gid;
#pragma unroll
            for (int nt = 0; nt < 4; nt++) {
                const int col = nc * 32 + nt * 8 + tig * 2;
                Ssm[r0 * 132 + col]           = acc[nt][0] * SCALE3;
                Ssm[r0 * 132 + col + 1]       = acc[nt][1] * SCALE3;
                Ssm[(r0 + 8) * 132 + col]     = acc[nt][2] * SCALE3;
                Ssm[(r0 + 8) * 132 + col + 1] = acc[nt][3] * SCALE3;
            }
        }
    }
    __syncthreads();   // S done; Qs/Ks dead

    // ---- Phase 2a: V -> X region ----
#pragma unroll
    for (int p = 0; p < 2; p++) {
        const int ts = p * 64 + sL;
        const int l  = (wh * HS + ts / WS) * WDIM + ww * WS + ts % WS;
        const float* vb = g_qkv + ((size_t)b * LTOK + l) * (3 * CCH) + 2 * CCH + co;
        const float4 v0 = *(const float4*)(vb + d0);
        const float4 v1 = *(const float4*)(vb + d0 + 4);
        uint4 t0, t1;
        t0.x = f2tf32(v0.x); t0.y = f2tf32(v0.y); t0.z = f2tf32(v0.z); t0.w = f2tf32(v0.w);
        t1.x = f2tf32(v1.x); t1.y = f2tf32(v1.y); t1.z = f2tf32(v1.z); t1.w = f2tf32(v1.w);
        *(uint4*)(Vs + ts * 40 + d0)     = t0;
        *(uint4*)(Vs + ts * 40 + d0 + 4) = t1;
    }

    // ---- Phase 2b: quad-per-row softmax on own 16 rows (gate folded) ----
#pragma unroll
    for (int i = 0; i < 2; i++) {
        const int r = wid * 16 + i * 8 + gid;
        float v[32];
#pragma unroll
        for (int jj = 0; jj < 32; jj++) v[jj] = Ssm[r * 132 + tig + 4 * jj];
        float mx = v[0];
#pragma unroll
        for (int jj = 1; jj < 32; jj++) mx = fmaxf(mx, v[jj]);
        mx = fmaxf(mx, __shfl_xor_sync(~0u, mx, 1));
        mx = fmaxf(mx, __shfl_xor_sync(~0u, mx, 2));
        float s = 0.0f;
#pragma unroll
        for (int jj = 0; jj < 32; jj++) {
            const float e = __expf(v[jj] - mx);
            s += e;
            Su[r * 132 + tig + 4 * jj] = f2tf32(e);
        }
        s += __shfl_xor_sync(~0u, s, 1);
        s += __shfl_xor_sync(~0u, s, 2);
        if (tig == 0) {
            const int lr = (wh * HS + r / WS) * WDIM + ww * WS + r % WS;
            rsum[r] = 3.0f * g_sgate[b * LTOK + lr] / s;
        }
    }
    __syncthreads();

    // ---- Phase 3: O^T = V^T P^T ; warp w -> N rows w*16..+15 ----
    {
        const int nbb = wid * 16;
        float acc[2][2][4] = {};
#pragma unroll
        for (int ks = 0; ks < 16; ks++) {
            const int kr = ks * 8;
            uint32_t af[2][4];
#pragma unroll
            for (int mt = 0; mt < 2; mt++) {
                const int mr = mt * 16;
                af[mt][0] = Vs[(kr + tig    ) * 40 + mr + gid];
                af[mt][1] = Vs[(kr + tig    ) * 40 + mr + gid + 8];
                af[mt][2] = Vs[(kr + tig + 4) * 40 + mr + gid];
                af[mt][3] = Vs[(kr + tig + 4) * 40 + mr + gid + 8];
            }
            uint32_t bf[2][2];
#pragma unroll
            for (int nt = 0; nt < 2; nt++) {
                const int nb = nbb + nt * 8;
                bf[nt][0] = Su[(nb + gid) * 132 + kr + tig];
                bf[nt][1] = Su[(nb + gid) * 132 + kr + tig + 4];
            }
#pragma unroll
            for (int mt = 0; mt < 2; mt++)
#pragma unroll
                for (int nt = 0; nt < 2; nt++)
                    mma_tf32(acc[mt][nt], af[mt], bf[nt]);
        }
        __syncthreads();   // Vs dead before Os overwrite

#pragma unroll
        for (int mt = 0; mt < 2; mt++) {
            const int dim0 = mt * 16 + gid;
#pragma unroll
            for (int nt = 0; nt < 2; nt++) {
                const int r = nbb + nt * 8 + tig * 2;
                const float s0 = rsum[r], s1 = rsum[r + 1];
                Os[r * 33 + dim0]           = acc[mt][nt][0] * s0;
                Os[(r + 1) * 33 + dim0]     = acc[mt][nt][1] * s1;
                Os[r * 33 + dim0 + 8]       = acc[mt][nt][2] * s0;
                Os[(r + 1) * 33 + dim0 + 8] = acc[mt][nt][3] * s1;
            }
        }
    }
    __syncthreads();

    // ---- Phase 4: transposed NCHW writeout (warp-per-channel-slice) ----
#pragma unroll
    for (int cc = 0; cc < 4; cc++) {
        const int c = wid * 4 + cc;
        float* cbase = g_fuimg + ((size_t)b * CCH + co + c) * LTOK;
#pragma unroll
        for (int rp = 0; rp < 4; rp++) {
            const int ts = rp * 32 + lane;
            const int l  = (wh * HS + ts / WS) * WDIM + ww * WS + ts % WS;
            cbase[l] = Os[ts * 33 + c];
        }
    }
}

// ---------------------------------------------------------------------------
// zero g_pool
// ---------------------------------------------------------------------------
__global__ void zero_pool_kernel()
{
    const int i = blockIdx.x * 256 + threadIdx.x;
    if (i < BSZ * CCH) g_pool[i] = 0.0f;
}

// ---------------------------------------------------------------------------
// Depthwise 3x3 + bias + BN + GELU, 4 pixels per thread (proven).
// WHICH 0 accumulates per-(b,c) sum into g_pool.
// ---------------------------------------------------------------------------
template<int WHICH>
__global__ __launch_bounds__(256) void dwconv_bn_gelu_kernel(
    const float* __restrict__ xin,
    const float* __restrict__ wdw,
    const float* __restrict__ bdw,
    const float* __restrict__ gbn,
    const float* __restrict__ bebn)
{
    const int idx = blockIdx.x * 256 + threadIdx.x;
    const int w0 = (idx & 31) * 4;
    const int h  = (idx >> 5) & 127;
    const int bc = idx >> 12;
    const int c  = bc % CCH;

    const float* in  = (WHICH == 0) ? xin : g_fuimg;
    float*       out = (WHICH == 0) ? g_conv1 : g_conv2;

    const float* p = in + (size_t)bc * LTOK;
    float wk[9];
#pragma unroll
    for (int i = 0; i < 9; i++) wk[i] = wdw[c * 9 + i];

    float o0 = 0.f, o1 = 0.f, o2 = 0.f, o3 = 0.f;
#pragma unroll
    for (int r = 0; r < 3; r++) {
        const int hh = h - 1 + r;
        if (hh < 0 || hh >= HDIM) continue;
        const float* row = p + hh * WDIM;
        const float4 cc = *(const float4*)(row + w0);
        const float lf = (w0 > 0)   ? row[w0 - 1] : 0.0f;
        const float rt = (w0 < 124) ? row[w0 + 4] : 0.0f;
        const float k0 = wk[r*3+0], k1 = wk[r*3+1], k2 = wk[r*3+2];
        o0 = fmaf(k0, lf,   fmaf(k1, cc.x, fmaf(k2, cc.y, o0)));
        o1 = fmaf(k0, cc.x, fmaf(k1, cc.y, fmaf(k2, cc.z, o1)));
        o2 = fmaf(k0, cc.y, fmaf(k1, cc.z, fmaf(k2, cc.w, o2)));
        o3 = fmaf(k0, cc.z, fmaf(k1, cc.w, fmaf(k2, rt,   o3)));
    }
    const float bni = rsqrtf(1.0f + 1e-5f);
    const float sc = gbn[c] * bni, bb = bebn[c], bs = bdw[c];
    float4 o;
    o.x = gelu_erf((o0 + bs) * sc + bb);
    o.y = gelu_erf((o1 + bs) * sc + bb);
    o.z = gelu_erf((o2 + bs) * sc + bb);
    o.w = gelu_erf((o3 + bs) * sc + bb);
    *(float4*)(out + (size_t)idx * 4) = o;

    if (WHICH == 0) {
        float s = o.x + o.y + o.z + o.w;
#pragma unroll
        for (int off = 16; off > 0; off >>= 1)
            s += __shfl_xor_sync(0xffffffffu, s, off);
        __shared__ float red[8];
        if ((threadIdx.x & 31) == 0) red[threadIdx.x >> 5] = s;
        __syncthreads();
        if (threadIdx.x == 0) {
            float tot = 0.0f;
#pragma unroll
            for (int i = 0; i < 8; i++) tot += red[i];
            atomicAdd(&g_pool[bc], tot);
        }
    }
}

// ---------------------------------------------------------------------------
// Spatial interaction -> g_sgate (R11-proven, unchanged)
// ---------------------------------------------------------------------------
__global__ __launch_bounds__(256) void spatial_kernel(
    const float* __restrict__ w_si1, const float* __restrict__ b_si1,
    const float* __restrict__ g_si,  const float* __restrict__ be_si,
    const float* __restrict__ w_si2, const float* __restrict__ b_si2)
{
    __shared__ float wsm[CCH * C8];   // [c][o]
    for (int i = threadIdx.x; i < CCH * C8; i += 256)
        wsm[i] = w_si1[(i % C8) * CCH + (i / C8)];
    __syncthreads();

    const int pid = (blockIdx.x * 256 + threadIdx.x) * 2;   // even
    const int b  = pid / LTOK;
    const int hw = pid % LTOK;

    float t0[C8], t1[C8];
#pragma unroll
    for (int o = 0; o < C8; o++) { t0[o] = 0.0f; t1[o] = 0.0f; }

    const float* base = g_conv1 + (size_t)b * CCH * LTOK + hw;
#pragma unroll 4
    for (int c = 0; c < CCH; c++) {
        const float2 v = *(const float2*)(base + (size_t)c * LTOK);
        const float4* wr = (const float4*)&wsm[c * C8];
#pragma unroll
        for (int o4 = 0; o4 < 6; o4++) {
            const float4 w = wr[o4];
            t0[o4*4+0] = fmaf(w.x, v.x, t0[o4*4+0]);
            t0[o4*4+1] = fmaf(w.y, v.x, t0[o4*4+1]);
            t0[o4*4+2] = fmaf(w.z, v.x, t0[o4*4+2]);
            t0[o4*4+3] = fmaf(w.w, v.x, t0[o4*4+3]);
            t1[o4*4+0] = fmaf(w.x, v.y, t1[o4*4+0]);
            t1[o4*4+1] = fmaf(w.y, v.y, t1[o4*4+1]);
            t1[o4*4+2] = fmaf(w.z, v.y, t1[o4*4+2]);
            t1[o4*4+3] = fmaf(w.w, v.y, t1[o4*4+3]);
        }
    }

    const float bni = rsqrtf(1.0f + 1e-5f);
    float s0 = b_si2[0], s1 = s0;
#pragma unroll
    for (int o = 0; o < C8; o++) {
        const float gb = g_si[o] * bni, be = be_si[o], bi = b_si1[o], w2 = w_si2[o];
        s0 = fmaf(w2, gelu_erf((t0[o] + bi) * gb + be), s0);
        s1 = fmaf(w2, gelu_erf((t1[o] + bi) * gb + be), s1);
    }
    g_sgate[pid]     = 1.0f + sigmoidf_(s0);
    g_sgate[pid + 1] = 1.0f + sigmoidf_(s1);
}

// ---------------------------------------------------------------------------
// Channel interaction -> g_cgate (g_pool holds SUM; scale by 1/LTOK)
// ---------------------------------------------------------------------------
__global__ __launch_bounds__(192) void channel_kernel(
    const float* __restrict__ w_ci1, const float* __restrict__ b_ci1,
    const float* __restrict__ g_ci,  const float* __restrict__ be_ci,
    const float* __restrict__ w_ci2, const float* __restrict__ b_ci2)
{
    const int b = blockIdx.x;
    __shared__ float t[C8];
    const float bni = rsqrtf(1.0f + 1e-5f);
    const float inv = 1.0f / LTOK;
    if (threadIdx.x < C8) {
        const int o = threadIdx.x;
        float s = b_ci1[o];
        for (int c = 0; c < CCH; c++)
            s = fmaf(w_ci1[o * CCH + c], g_pool[b * CCH + c] * inv, s);
        s = s * (g_ci[o] * bni) + be_ci[o];
        t[o] = gelu_erf(s);
    }
    __syncthreads();
    const int c = threadIdx.x;
    float s = b_ci2[c];
#pragma unroll
    for (int o = 0; o < C8; o++) s = fmaf(w_ci2[c * C8 + o], t[o], s);
    g_cgate[b * CCH + c] = 1.0f + sigmoidf_(s);
}

// ---------------------------------------------------------------------------
// kernel_launch
// ---------------------------------------------------------------------------
extern "C" void kernel_launch(void* const* d_in, const int* in_sizes, int n_in,
                              void* d_out, int out_size)
{
    const float* x      = (const float*)d_in[0];
    const float* w_qkv  = (const float*)d_in[1];
    const float* b_qkv  = (const float*)d_in[2];
    const float* w_dw1  = (const float*)d_in[3];
    const float* b_dw1  = (const float*)d_in[4];
    const float* gbn1   = (const float*)d_in[5];
    const float* bebn1  = (const float*)d_in[6];
    const float* w_si1  = (const float*)d_in[7];
    const float* b_si1  = (const float*)d_in[8];
    const float* g_si   = (const float*)d_in[9];
    const float* be_si  = (const float*)d_in[10];
    const float* w_si2  = (const float*)d_in[11];
    const float* b_si2  = (const float*)d_in[12];
    const float* w_ci1  = (const float*)d_in[13];
    const float* b_ci1  = (const float*)d_in[14];
    const float* g_ci   = (const float*)d_in[15];
    const float* be_ci  = (const float*)d_in[16];
    const float* w_ci2  = (const float*)d_in[17];
    const float* b_ci2  = (const float*)d_in[18];
    const float* w_dw2  = (const float*)d_in[19];
    const float* b_dw2  = (const float*)d_in[20];
    const float* gbn2   = (const float*)d_in[21];
    const float* bebn2  = (const float*)d_in[22];
    const float* w_proj = (const float*)d_in[23];
    const float* b_proj = (const float*)d_in[24];
    float* out = (float*)d_out;

    cudaFuncSetAttribute(attn_mma_kernel<8, 16, 0>,
                         cudaFuncAttributeMaxDynamicSharedMemorySize, ATT_SMEM);
    cudaFuncSetAttribute(attn_mma_kernel<16, 8, 96>,
                         cudaFuncAttributeMaxDynamicSharedMemorySize, ATT_SMEM);

    // 0) qkv = x @ w_qkv + b_qkv  (double-buffered)
    mma_gemm_kernel<0, 3 * CCH><<<dim3((3 * CCH) / 96, MTOT / 128), 192>>>(
        x, w_qkv, b_qkv, nullptr);

    // 1) conv path (mean fused into dwconv<0>)
    zero_pool_kernel<<<(BSZ * CCH + 255) / 256, 256>>>();
    dwconv_bn_gelu_kernel<0><<<(MTOT * CCH) / 1024, 256>>>(x, w_dw1, b_dw1, gbn1, bebn1);
    spatial_kernel<<<MTOT / 512, 256>>>(w_si1, b_si1, g_si, be_si, w_si2, b_si2);
    channel_kernel<<<BSZ, CCH>>>(w_ci1, b_ci1, g_ci, be_ci, w_ci2, b_ci2);

    // 2) attention (gate + transpose fused) -> g_fuimg (NCHW)
    attn_mma_kernel<8, 16, 0 ><<<BSZ * (HDIM / 8) * (WDIM / 16) * 3, 256, ATT_SMEM>>>();
    attn_mma_kernel<16, 8, 96><<<BSZ * (HDIM / 16) * (WDIM / 8) * 3, 256, ATT_SMEM>>>();

    // 3) conv2 -> g_conv2
    dwconv_bn_gelu_kernel<1><<<(MTOT * CCH) / 1024, 256>>>(nullptr, w_dw2, b_dw2, gbn2, bebn2);

    // 4) out = (channel-gated conv2) @ w_proj + b_proj  (double-buffered)
    mma_gemm_kernel<1, CCH><<<dim3(CCH / 96, MTOT / 128), 192>>>(
        nullptr, w_proj, b_proj, out);
}